// round 12
// baseline (speedup 1.0000x reference)
#include <cuda_runtime.h>
#include <cuda_bf16.h>
#include <cuda_fp16.h>
#include <cstdint>
#include <math.h>

#define NB 25
#define BATCH 4096
#define DN 1024
#define RS (NB * DN)
#define NMAT (2 * NB)
#define MM ((size_t)DN * DN)
#define NSQ_HL 4                 // hi/lo bf16 squarings (small-gap regime)
#define NSQ_F16 6                // single-term fp16 tail (risk == bf16 tail at step+3)
#define NSQ (NSQ_HL + NSQ_F16)
#define BK 64
#define NKS (DN / BK)            // 16 k-stages
#define RSEB 144                 // smem row stride bytes (128B data + 16B pad)
#define MATB (128 * RSEB)        // 18432 B per matrix tile
#define STG4 (4 * MATB)          // 73728 B per stage (4 mats)
#define SMEM_BYTES (3 * STG4)    // 221184, 3-stage pipeline
#define STG2 (2 * MATB)          // 36864 B per stage (2 mats)
#define SMEM1 (2 * STG2)         // 73728 (1-term kernel, 2 stages)

typedef __nv_bfloat16 bf16;
typedef __half fp16;

// ----------------------------- scratch -------------------------------------
__device__ bf16  g_xhi[(size_t)BATCH * RS];
__device__ bf16  g_xlo[(size_t)BATCH * RS];
__device__ bf16  g_wth[NMAT * MM];
__device__ bf16  g_wtl[NMAT * MM];
__device__ float g_G  [NMAT * MM];
__device__ bf16  g_P0h[NMAT * MM];
__device__ bf16  g_P0l[NMAT * MM];
__device__ bf16  g_P1h[NMAT * MM];
__device__ bf16  g_P1l[NMAT * MM];
__device__ bf16  g_hhi[(size_t)BATCH * RS];
__device__ bf16  g_hlo[(size_t)BATCH * RS];
__device__ float g_tr [(NSQ + 1) * NMAT];
__device__ float g_v  [NMAT * DN];
__device__ float g_gv [NMAT * DN];
__device__ float g_is [NMAT];

// ----------------------------- PTX helpers ---------------------------------
__device__ __forceinline__ uint32_t smem_u32(const void* p) {
    uint32_t a;
    asm("{ .reg .u64 t; cvta.to.shared.u64 t, %1; cvt.u32.u64 %0, t; }" : "=r"(a) : "l"(p));
    return a;
}
__device__ __forceinline__ void cp16(uint32_t s, const void* g) {
    asm volatile("cp.async.cg.shared.global [%0], [%1], 16;" :: "r"(s), "l"(g));
}
#define CP_COMMIT() asm volatile("cp.async.commit_group;" ::: "memory")
#define CP_WAIT(N)  asm volatile("cp.async.wait_group %0;" :: "n"(N) : "memory")

#define LDSM4(r0, r1, r2, r3, addr) \
    asm volatile("ldmatrix.sync.aligned.m8n8.x4.shared.b16 {%0,%1,%2,%3}, [%4];" \
        : "=r"(r0), "=r"(r1), "=r"(r2), "=r"(r3) : "r"(addr))

#define MMA16816(c, a, b) \
    asm volatile("mma.sync.aligned.m16n8k16.row.col.f32.bf16.bf16.f32 " \
        "{%0,%1,%2,%3}, {%4,%5,%6,%7}, {%8,%9}, {%0,%1,%2,%3};" \
        : "+f"((c)[0]), "+f"((c)[1]), "+f"((c)[2]), "+f"((c)[3]) \
        : "r"((a)[0]), "r"((a)[1]), "r"((a)[2]), "r"((a)[3]), "r"((b)[0]), "r"((b)[1]))

#define MMAH16816(c, a, b) \
    asm volatile("mma.sync.aligned.m16n8k16.row.col.f32.f16.f16.f32 " \
        "{%0,%1,%2,%3}, {%4,%5,%6,%7}, {%8,%9}, {%0,%1,%2,%3};" \
        : "+f"((c)[0]), "+f"((c)[1]), "+f"((c)[2]), "+f"((c)[3]) \
        : "r"((a)[0]), "r"((a)[1]), "r"((a)[2]), "r"((a)[3]), "r"((b)[0]), "r"((b)[1]))

// ----------------------------- conversions ---------------------------------
__global__ void __launch_bounds__(256) conv_split(const float* __restrict__ in,
                                                  bf16* __restrict__ hi, bf16* __restrict__ lo)
{
    size_t i = ((size_t)blockIdx.x * 256 + threadIdx.x) * 4;
    float4 v = *(const float4*)(in + i);
    bf16 h0 = __float2bfloat16(v.x), h1 = __float2bfloat16(v.y);
    bf16 h2 = __float2bfloat16(v.z), h3 = __float2bfloat16(v.w);
    hi[i+0] = h0; hi[i+1] = h1; hi[i+2] = h2; hi[i+3] = h3;
    lo[i+0] = __float2bfloat16(v.x - __bfloat162float(h0));
    lo[i+1] = __float2bfloat16(v.y - __bfloat162float(h1));
    lo[i+2] = __float2bfloat16(v.z - __bfloat162float(h2));
    lo[i+3] = __float2bfloat16(v.w - __bfloat162float(h3));
}

__global__ void __launch_bounds__(256) conv_wT(const float* __restrict__ w,
                                               bf16* __restrict__ hi, bf16* __restrict__ lo)
{
    const int m = blockIdx.z;
    const float* W = w + (size_t)m * MM;
    bf16* Hi = hi + (size_t)m * MM;
    bf16* Lo = lo + (size_t)m * MM;
    __shared__ float t[32][33];
    const int r0 = blockIdx.y * 32, c0 = blockIdx.x * 32;
    const int tr = threadIdx.x >> 5, tc = threadIdx.x & 31;
#pragma unroll
    for (int i = 0; i < 4; i++)
        t[tr + 8 * i][tc] = W[(size_t)(r0 + tr + 8 * i) * DN + c0 + tc];
    __syncthreads();
#pragma unroll
    for (int i = 0; i < 4; i++) {
        int rr = tr + 8 * i;
        float v = t[tc][rr];
        bf16 h = __float2bfloat16(v);
        size_t o = (size_t)(c0 + rr) * DN + r0 + tc;
        Hi[o] = h;
        Lo[o] = __float2bfloat16(v - __bfloat162float(h));
    }
}

// -------- 3-term hi/lo GEMM, 512 threads / 16 warps, 3-stage pipeline -------
// MODE 0: Gram   -> Cf (fp32) + Chi/Clo    [triangular grid + mirror]
// MODE 1: square -> Chi/Clo, scl=(1/tr)^2  [triangular grid + mirror]
// MODE 2: MLP1   -> Chi/Clo = gelu(C*is + b1)
// MODE 3: MLP2   -> Cf = C*is + b2
// MODE 4: square -> fp16 single output     [triangular grid + mirror]
template <int MODE>
__global__ void __launch_bounds__(512, 1) gemm_k(
    const bf16* __restrict__ Ahi, const bf16* __restrict__ Alo, long lda, long aoffz,
    const bf16* __restrict__ Bhi, const bf16* __restrict__ Blo,
    float* __restrict__ Cf, bf16* __restrict__ Chi, bf16* __restrict__ Clo,
    long ldc, long coffz,
    const float* __restrict__ bias, const float* __restrict__ sc,
    const float* __restrict__ trin)
{
    constexpr bool TRI   = (MODE == 0 || MODE == 1 || MODE == 4);
    constexpr bool TRSCL = (MODE == 1 || MODE == 4);
    constexpr bool MLPM  = (MODE == 2 || MODE == 3);
    constexpr bool OUTF  = (MODE == 0 || MODE == 3);
    constexpr bool OUTHL = (MODE == 0 || MODE == 1 || MODE == 2);
    constexpr bool OUT16 = (MODE == 4);

    extern __shared__ char smem[];
    const uint32_t sb = smem_u32(smem);

    const int tid = threadIdx.x;
    const int wid = tid >> 5, lane = tid & 31;
    const int wr = wid >> 2, wc = wid & 3;       // 4x4 warps, 32x32 warp tiles
    const int z = blockIdx.z;

    int row0, col0;
    if (TRI) {
        int t = blockIdx.x, ti = 0;
        while (t >= 8 - ti) { t -= 8 - ti; ti++; }
        row0 = ti * 128; col0 = (ti + t) * 128;
    } else {
        row0 = blockIdx.y * 128; col0 = blockIdx.x * 128;
    }

    const bf16* Ah = Ahi + (size_t)z * aoffz + (size_t)row0 * lda;
    const bf16* Al = Alo + (size_t)z * aoffz + (size_t)row0 * lda;
    const bf16* Bh = Bhi + (size_t)z * MM + (size_t)col0 * DN;
    const bf16* Bl = Blo + (size_t)z * MM + (size_t)col0 * DN;

    const bf16* gbase[4] = {Ah, Al, Bh, Bl};
    const long  gstr [4] = {lda, lda, DN, DN};

    auto load_stage = [&](int st, int k0) {
        const uint32_t base = sb + (uint32_t)st * STG4;
        const int ch = tid & 7;
        const int rlo = tid >> 3;                 // 0..63
#pragma unroll
        for (int t = 0; t < 8; t++) {
            const int mat = t >> 1;
            const int r = ((t & 1) << 6) + rlo;   // 0..127
            cp16(base + (uint32_t)mat * MATB + (uint32_t)(r * RSEB + ch * 16),
                 gbase[mat] + (long)r * gstr[mat] + k0 + ch * 8);
        }
        CP_COMMIT();
    };

    float acc[2][4][4];
#pragma unroll
    for (int mi = 0; mi < 2; mi++)
#pragma unroll
        for (int ni = 0; ni < 4; ni++)
#pragma unroll
            for (int q = 0; q < 4; q++) acc[mi][ni][q] = 0.0f;

    load_stage(0, 0);
    load_stage(1, BK);

    const int arow = (lane & 7) + ((lane >> 3) & 1) * 8;
    const int acol = (lane >> 4) * 16;
    const int brow = (lane & 7) + ((lane >> 4) & 1) * 8;
    const int bcol = ((lane >> 3) & 1) * 16;

    for (int s = 0; s < NKS; s++) {
        if (s < NKS - 1) { CP_WAIT(1); } else { CP_WAIT(0); }
        __syncthreads();
        if (s + 2 < NKS) load_stage((s + 2) % 3, (s + 2) * BK);

        const uint32_t stb = sb + (uint32_t)(s % 3) * STG4;
        const uint32_t aBh = stb + (uint32_t)((wr * 32 + arow) * RSEB) + acol;
        const uint32_t aBl = aBh + MATB;
        const uint32_t bBh = stb + 2u * MATB + (uint32_t)((wc * 32 + brow) * RSEB) + bcol;
        const uint32_t bBl = bBh + MATB;

#pragma unroll
        for (int kk = 0; kk < 4; kk++) {
            const uint32_t ko = (uint32_t)(kk * 32);
            uint32_t ah[2][4], al[2][4], bh[4][2], bl[4][2];
#pragma unroll
            for (int mi = 0; mi < 2; mi++) {
                LDSM4(ah[mi][0], ah[mi][1], ah[mi][2], ah[mi][3], aBh + ko + (uint32_t)(mi * 16 * RSEB));
                LDSM4(al[mi][0], al[mi][1], al[mi][2], al[mi][3], aBl + ko + (uint32_t)(mi * 16 * RSEB));
            }
#pragma unroll
            for (int p = 0; p < 2; p++) {
                LDSM4(bh[2*p][0], bh[2*p][1], bh[2*p+1][0], bh[2*p+1][1], bBh + ko + (uint32_t)(p * 16 * RSEB));
                LDSM4(bl[2*p][0], bl[2*p][1], bl[2*p+1][0], bl[2*p+1][1], bBl + ko + (uint32_t)(p * 16 * RSEB));
            }
#pragma unroll
            for (int mi = 0; mi < 2; mi++)
#pragma unroll
                for (int ni = 0; ni < 4; ni++) MMA16816(acc[mi][ni], ah[mi], bh[ni]);
#pragma unroll
            for (int mi = 0; mi < 2; mi++)
#pragma unroll
                for (int ni = 0; ni < 4; ni++) MMA16816(acc[mi][ni], ah[mi], bl[ni]);
#pragma unroll
            for (int mi = 0; mi < 2; mi++)
#pragma unroll
                for (int ni = 0; ni < 4; ni++) MMA16816(acc[mi][ni], al[mi], bh[ni]);
        }
        __syncthreads();
    }

    // ------------------------------ epilogue -------------------------------
    float scl = 1.0f;
    if (TRSCL) { float it = 1.0f / trin[z]; scl = it * it; }
    if (MLPM) scl = sc[z];
    const int gID = lane >> 2, tg = lane & 3;
    const bool mirror = TRI && (row0 != col0);
    float* ts = (float*)smem;
    fp16* C16 = reinterpret_cast<fp16*>(Chi);

#pragma unroll
    for (int mi = 0; mi < 2; mi++)
#pragma unroll
        for (int ni = 0; ni < 4; ni++)
#pragma unroll
            for (int hf = 0; hf < 2; hf++) {
                const int rl = wr * 32 + mi * 16 + gID + hf * 8;
                const int cl = wc * 32 + ni * 8 + tg * 2;
                float v0 = acc[mi][ni][hf * 2 + 0] * scl;
                float v1 = acc[mi][ni][hf * 2 + 1] * scl;
                if (MLPM) {
                    v0 += bias[z * DN + col0 + cl];
                    v1 += bias[z * DN + col0 + cl + 1];
                }
                if (MODE == 2) {
                    v0 = 0.5f * v0 * (1.0f + erff(v0 * 0.70710678118654752f));
                    v1 = 0.5f * v1 * (1.0f + erff(v1 * 0.70710678118654752f));
                }
                const size_t off = (size_t)z * coffz + (size_t)(row0 + rl) * ldc + col0 + cl;
                if (OUTF) {
                    float2 f2; f2.x = v0; f2.y = v1;
                    *(float2*)(Cf + off) = f2;
                }
                if (OUTHL) {
                    bf16 h0 = __float2bfloat16(v0);
                    bf16 h1 = __float2bfloat16(v1);
                    __nv_bfloat162 hh; hh.x = h0; hh.y = h1;
                    __nv_bfloat162 ll;
                    ll.x = __float2bfloat16(v0 - __bfloat162float(h0));
                    ll.y = __float2bfloat16(v1 - __bfloat162float(h1));
                    *(__nv_bfloat162*)(Chi + off) = hh;
                    *(__nv_bfloat162*)(Clo + off) = ll;
                }
                if (OUT16) {
                    __half2 hh = __floats2half2_rn(v0, v1);
                    *(__half2*)(C16 + off) = hh;
                }
                if (mirror) {
                    ts[rl * 129 + cl] = v0;
                    ts[rl * 129 + cl + 1] = v1;
                }
            }

    if (mirror) {
        __syncthreads();
#pragma unroll 4
        for (int i = 0; i < 16; i++) {
            int lin = i * 1024 + tid * 2;
            int mr = lin >> 7, mc = lin & 127;
            float v0 = ts[mc * 129 + mr];
            float v1 = ts[(mc + 1) * 129 + mr];
            const size_t off = (size_t)z * coffz + (size_t)(col0 + mr) * ldc + row0 + mc;
            if (MODE == 0) {
                float2 f2; f2.x = v0; f2.y = v1;
                *(float2*)(Cf + off) = f2;
            }
            if (OUTHL) {
                bf16 h0 = __float2bfloat16(v0);
                bf16 h1 = __float2bfloat16(v1);
                __nv_bfloat162 hh; hh.x = h0; hh.y = h1;
                __nv_bfloat162 ll;
                ll.x = __float2bfloat16(v0 - __bfloat162float(h0));
                ll.y = __float2bfloat16(v1 - __bfloat162float(h1));
                *(__nv_bfloat162*)(Chi + off) = hh;
                *(__nv_bfloat162*)(Clo + off) = ll;
            }
            if (OUT16) {
                __half2 hh = __floats2half2_rn(v0, v1);
                *(__half2*)(C16 + off) = hh;
            }
        }
    }
}

// ------------- 1-term fp16 squaring GEMM, 2-stage, 2 CTAs/SM ----------------
// For tail squarings (gap grown enough that fp16 noise is harmless).
__global__ void __launch_bounds__(256, 2) gemm1h_k(
    const fp16* __restrict__ Ph, fp16* __restrict__ Po,
    const float* __restrict__ trin)
{
    extern __shared__ char smem[];
    const uint32_t sb = smem_u32(smem);

    const int tid = threadIdx.x;
    const int wid = tid >> 5, lane = tid & 31;
    const int wr = wid >> 1, wc = wid & 1;
    const int z = blockIdx.z;

    int t = blockIdx.x, ti = 0;
    while (t >= 8 - ti) { t -= 8 - ti; ti++; }
    const int row0 = ti * 128, col0 = (ti + t) * 128;

    const fp16* Ah = Ph + (size_t)z * MM + (size_t)row0 * DN;
    const fp16* Bh = Ph + (size_t)z * MM + (size_t)col0 * DN;

    auto load_stage = [&](int st, int k0) {
        const uint32_t base = sb + (uint32_t)st * STG2;
        const int ch = tid & 7;
        const int rlo = tid >> 3;
#pragma unroll
        for (int t2 = 0; t2 < 8; t2++) {
            const int mat = t2 >> 2;
            const int r = ((t2 & 3) << 5) + rlo;
            const fp16* src = mat ? Bh : Ah;
            cp16(base + (uint32_t)mat * MATB + (uint32_t)(r * RSEB + ch * 16),
                 src + (long)r * DN + k0 + ch * 8);
        }
        CP_COMMIT();
    };

    float acc[2][8][4];
#pragma unroll
    for (int mi = 0; mi < 2; mi++)
#pragma unroll
        for (int ni = 0; ni < 8; ni++)
#pragma unroll
            for (int q = 0; q < 4; q++) acc[mi][ni][q] = 0.0f;

    load_stage(0, 0);

    const int arow = (lane & 7) + ((lane >> 3) & 1) * 8;
    const int acol = (lane >> 4) * 16;
    const int brow = (lane & 7) + ((lane >> 4) & 1) * 8;
    const int bcol = ((lane >> 3) & 1) * 16;

    for (int s = 0; s < NKS; s++) {
        CP_WAIT(0);
        __syncthreads();
        if (s + 1 < NKS) load_stage((s + 1) & 1, (s + 1) * BK);

        const uint32_t stb = sb + (uint32_t)(s & 1) * STG2;
        const uint32_t aB = stb + (uint32_t)((wr * 32 + arow) * RSEB) + acol;
        const uint32_t bB = stb + MATB + (uint32_t)((wc * 64 + brow) * RSEB) + bcol;

#pragma unroll
        for (int kk = 0; kk < 4; kk++) {
            const uint32_t ko = (uint32_t)(kk * 32);
            uint32_t ah[2][4], bh[8][2];
#pragma unroll
            for (int mi = 0; mi < 2; mi++)
                LDSM4(ah[mi][0], ah[mi][1], ah[mi][2], ah[mi][3], aB + ko + (uint32_t)(mi * 16 * RSEB));
#pragma unroll
            for (int p = 0; p < 4; p++)
                LDSM4(bh[2*p][0], bh[2*p][1], bh[2*p+1][0], bh[2*p+1][1], bB + ko + (uint32_t)(p * 16 * RSEB));
#pragma unroll
            for (int mi = 0; mi < 2; mi++)
#pragma unroll
                for (int ni = 0; ni < 8; ni++) MMAH16816(acc[mi][ni], ah[mi], bh[ni]);
        }
        __syncthreads();
    }

    const float it = 1.0f / trin[z];
    const float scl = it * it;
    const int gID = lane >> 2, tg = lane & 3;
    const bool mirror = (row0 != col0);
    float* ts = (float*)smem;

#pragma unroll
    for (int mi = 0; mi < 2; mi++)
#pragma unroll
        for (int ni = 0; ni < 8; ni++)
#pragma unroll
            for (int hf = 0; hf < 2; hf++) {
                const int rl = wr * 32 + mi * 16 + gID + hf * 8;
                const int cl = wc * 64 + ni * 8 + tg * 2;
                float v0 = acc[mi][ni][hf * 2 + 0] * scl;
                float v1 = acc[mi][ni][hf * 2 + 1] * scl;
                const size_t off = (size_t)z * MM + (size_t)(row0 + rl) * DN + col0 + cl;
                *(__half2*)(Po + off) = __floats2half2_rn(v0, v1);
                if (mirror) {
                    ts[rl * 129 + cl] = v0;
                    ts[rl * 129 + cl + 1] = v1;
                }
            }

    if (mirror) {
        __syncthreads();
#pragma unroll 4
        for (int i = 0; i < 32; i++) {
            int lin = i * 512 + tid * 2;
            int mr = lin >> 7, mc = lin & 127;
            float v0 = ts[mc * 129 + mr];
            float v1 = ts[(mc + 1) * 129 + mr];
            const size_t off = (size_t)z * MM + (size_t)(col0 + mr) * DN + row0 + mc;
            *(__half2*)(Po + off) = __floats2half2_rn(v0, v1);
        }
    }
}

// --------------------------- small kernels ----------------------------------
__global__ void __launch_bounds__(256) k_trace_f(const float* __restrict__ G,
                                                 float* __restrict__ out)
{
    const int m = blockIdx.x;
    float sum = 0.0f;
    for (int d = threadIdx.x; d < DN; d += 256)
        sum += G[(size_t)m * MM + (size_t)d * DN + d];
    __shared__ float red[256];
    red[threadIdx.x] = sum; __syncthreads();
    for (int off = 128; off > 0; off >>= 1) {
        if (threadIdx.x < off) red[threadIdx.x] += red[threadIdx.x + off];
        __syncthreads();
    }
    if (threadIdx.x == 0) out[m] = red[0];
}

__global__ void __launch_bounds__(256) k_trace_hl(const bf16* __restrict__ Ph,
                                                  const bf16* __restrict__ Pl,
                                                  float* __restrict__ out)
{
    const int m = blockIdx.x;
    float sum = 0.0f;
    for (int d = threadIdx.x; d < DN; d += 256) {
        size_t o = (size_t)m * MM + (size_t)d * DN + d;
        sum += __bfloat162float(Ph[o]) + __bfloat162float(Pl[o]);
    }
    __shared__ float red[256];
    red[threadIdx.x] = sum; __syncthreads();
    for (int off = 128; off > 0; off >>= 1) {
        if (threadIdx.x < off) red[threadIdx.x] += red[threadIdx.x + off];
        __syncthreads();
    }
    if (threadIdx.x == 0) out[m] = red[0];
}

__global__ void __launch_bounds__(256) k_trace_h16(const fp16* __restrict__ P,
                                                   float* __restrict__ out)
{
    const int m = blockIdx.x;
    float sum = 0.0f;
    for (int d = threadIdx.x; d < DN; d += 256)
        sum += __half2float(P[(size_t)m * MM + (size_t)d * DN + d]);
    __shared__ float red[256];
    red[threadIdx.x] = sum; __syncthreads();
    for (int off = 128; off > 0; off >>= 1) {
        if (threadIdx.x < off) red[threadIdx.x] += red[threadIdx.x + off];
        __syncthreads();
    }
    if (threadIdx.x == 0) out[m] = red[0];
}

// Robust extractor: j = argmax_d |P[d][d]| (diag ~ lambda*v_d^2), then v = P[:,j].
__global__ void __launch_bounds__(256) k_pickcol16(const fp16* __restrict__ P,
                                                   float* __restrict__ v)
{
    const int m = blockIdx.x;
    const size_t base = (size_t)m * MM;
    __shared__ float bv[256];
    __shared__ int bi[256];
    float best = -1.0f; int bidx = 0;
    for (int d = threadIdx.x; d < DN; d += 256) {
        float val = fabsf(__half2float(P[base + (size_t)d * DN + d]));
        if (val > best) { best = val; bidx = d; }
    }
    bv[threadIdx.x] = best; bi[threadIdx.x] = bidx;
    __syncthreads();
    for (int off = 128; off > 0; off >>= 1) {
        if (threadIdx.x < off && bv[threadIdx.x + off] > bv[threadIdx.x]) {
            bv[threadIdx.x] = bv[threadIdx.x + off];
            bi[threadIdx.x] = bi[threadIdx.x + off];
        }
        __syncthreads();
    }
    const int j = bi[0];
    for (int i = threadIdx.x; i < DN; i += 256)
        v[m * DN + i] = __half2float(P[base + (size_t)j * DN + i]);
}

__global__ void __launch_bounds__(256) k_matvec(const float* __restrict__ G,
                                                const float* __restrict__ v,
                                                float* __restrict__ gv)
{
    const int m = blockIdx.y, r = blockIdx.x;
    const float* row = G + (size_t)m * MM + (size_t)r * DN;
    const float* vm = v + m * DN;
    float4 a = *(const float4*)&row[threadIdx.x * 4];
    float4 b = *(const float4*)&vm[threadIdx.x * 4];
    float sum = a.x * b.x + a.y * b.y + a.z * b.z + a.w * b.w;
    __shared__ float red[256];
    red[threadIdx.x] = sum; __syncthreads();
    for (int off = 128; off > 0; off >>= 1) {
        if (threadIdx.x < off) red[threadIdx.x] += red[threadIdx.x + off];
        __syncthreads();
    }
    if (threadIdx.x == 0) gv[m * DN + r] = red[0];
}

__global__ void __launch_bounds__(256) k_sigma(const float* __restrict__ v,
                                               const float* __restrict__ gv,
                                               float* __restrict__ is_)
{
    const int m = blockIdx.x;
    float num = 0.0f, den = 0.0f;
    for (int d = threadIdx.x; d < DN; d += 256) {
        float vv = v[m * DN + d];
        num += vv * gv[m * DN + d];
        den += vv * vv;
    }
    __shared__ float rn[256], rd[256];
    rn[threadIdx.x] = num; rd[threadIdx.x] = den; __syncthreads();
    for (int off = 128; off > 0; off >>= 1) {
        if (threadIdx.x < off) { rn[threadIdx.x] += rn[threadIdx.x + off]; rd[threadIdx.x] += rd[threadIdx.x + off]; }
        __syncthreads();
    }
    if (threadIdx.x == 0) is_[m] = sqrtf(rd[0] / rn[0]);
}

// ---------------------------------------------------------------------------
extern "C" void kernel_launch(void* const* d_in, const int* in_sizes, int n_in,
                              void* d_out, int out_size)
{
    const float* x  = (const float*)d_in[0];
    const float* w1 = (const float*)d_in[1];
    const float* b1 = (const float*)d_in[2];
    const float* w2 = (const float*)d_in[3];
    const float* b2 = (const float*)d_in[4];
    float* out = (float*)d_out;

    bf16 *xhi, *xlo, *wth, *wtl, *P0h, *P0l, *P1h, *P1l, *hhi, *hlo;
    float *G, *tr, *v, *gv, *is_;
    cudaGetSymbolAddress((void**)&xhi, g_xhi); cudaGetSymbolAddress((void**)&xlo, g_xlo);
    cudaGetSymbolAddress((void**)&wth, g_wth); cudaGetSymbolAddress((void**)&wtl, g_wtl);
    cudaGetSymbolAddress((void**)&G, g_G);
    cudaGetSymbolAddress((void**)&P0h, g_P0h); cudaGetSymbolAddress((void**)&P0l, g_P0l);
    cudaGetSymbolAddress((void**)&P1h, g_P1h); cudaGetSymbolAddress((void**)&P1l, g_P1l);
    cudaGetSymbolAddress((void**)&hhi, g_hhi); cudaGetSymbolAddress((void**)&hlo, g_hlo);
    cudaGetSymbolAddress((void**)&tr, g_tr);   cudaGetSymbolAddress((void**)&v, g_v);
    cudaGetSymbolAddress((void**)&gv, g_gv);   cudaGetSymbolAddress((void**)&is_, g_is);

    cudaFuncSetAttribute(gemm_k<0>, cudaFuncAttributeMaxDynamicSharedMemorySize, SMEM_BYTES);
    cudaFuncSetAttribute(gemm_k<1>, cudaFuncAttributeMaxDynamicSharedMemorySize, SMEM_BYTES);
    cudaFuncSetAttribute(gemm_k<2>, cudaFuncAttributeMaxDynamicSharedMemorySize, SMEM_BYTES);
    cudaFuncSetAttribute(gemm_k<3>, cudaFuncAttributeMaxDynamicSharedMemorySize, SMEM_BYTES);
    cudaFuncSetAttribute(gemm_k<4>, cudaFuncAttributeMaxDynamicSharedMemorySize, SMEM_BYTES);
    cudaFuncSetAttribute(gemm1h_k,  cudaFuncAttributeMaxDynamicSharedMemorySize, SMEM1);

    conv_split<<<(unsigned)((size_t)BATCH * RS / 4 / 256), 256>>>(x, xhi, xlo);
    conv_wT<<<dim3(32, 32, NB), 256>>>(w1, wth, wtl);
    conv_wT<<<dim3(32, 32, NB), 256>>>(w2, wth + (size_t)NB * MM, wtl + (size_t)NB * MM);

    // Gram: G (fp32) + P0 hi/lo, triangular grid; trace from fp32 G
    gemm_k<0><<<dim3(36, 1, NMAT), 512, SMEM_BYTES>>>(
        wth, wtl, DN, (long)MM, wth, wtl, G, P0h, P0l, DN, (long)MM,
        nullptr, nullptr, nullptr);
    k_trace_f<<<NMAT, 256>>>(G, tr);

    // Steps 1..3: hi/lo bf16 squarings (small-gap regime)
    bf16 *pih = P0h, *pil = P0l, *poh = P1h, *pol = P1l;
    int step = 0;
    for (int s = 0; s < NSQ_HL - 1; s++, step++) {
        gemm_k<1><<<dim3(36, 1, NMAT), 512, SMEM_BYTES>>>(
            pih, pil, DN, (long)MM, pih, pil, nullptr, poh, pol, DN, (long)MM,
            nullptr, nullptr, tr + step * NMAT);
        k_trace_hl<<<NMAT, 256>>>(poh, pol, tr + (step + 1) * NMAT);
        bf16* t1 = pih; pih = poh; poh = t1;
        bf16* t2 = pil; pil = pol; pol = t2;
    }
    // Step 4: hi/lo -> fp16 single output (transition; risk == R11's proven bf16@7->8)
    fp16* q0 = reinterpret_cast<fp16*>(poh == P0h ? P0h : P1h);
    {
        gemm_k<4><<<dim3(36, 1, NMAT), 512, SMEM_BYTES>>>(
            pih, pil, DN, (long)MM, pih, pil, nullptr, (bf16*)q0, nullptr, DN, (long)MM,
            nullptr, nullptr, tr + step * NMAT);
        step++;
        k_trace_h16<<<NMAT, 256>>>(q0, tr + step * NMAT);
    }
    // Steps 5..10: single-term fp16 squarings
    fp16* pi16 = q0;
    fp16* po16 = reinterpret_cast<fp16*>((void*)q0 == (void*)P0h ? P1h : P0h);
    for (int s = 0; s < NSQ_F16; s++, step++) {
        gemm1h_k<<<dim3(36, 1, NMAT), 256, SMEM1>>>(pi16, po16, tr + step * NMAT);
        k_trace_h16<<<NMAT, 256>>>(po16, tr + (step + 1) * NMAT);
        fp16* t1 = pi16; pi16 = po16; po16 = t1;
    }

    // Rayleigh quotient on fp32 G with v = argmax-diag column of P_final
    k_pickcol16<<<NMAT, 256>>>(pi16, v);
    k_matvec<<<dim3(DN, NMAT), 256>>>(G, v, gv);
    k_sigma<<<NMAT, 256>>>(v, gv, is_);

    // MLP
    gemm_k<2><<<dim3(8, 32, NB), 512, SMEM_BYTES>>>(
        xhi, xlo, RS, (long)DN, wth, wtl, nullptr, hhi, hlo, RS, (long)DN,
        b1, is_, nullptr);
    gemm_k<3><<<dim3(8, 32, NB), 512, SMEM_BYTES>>>(
        hhi, hlo, RS, (long)DN, wth + (size_t)NB * MM, wtl + (size_t)NB * MM,
        out, nullptr, nullptr, RS, (long)DN, b2, is_ + NB, nullptr);
}

// round 13
// speedup vs baseline: 1.5418x; 1.5418x over previous
#include <cuda_runtime.h>
#include <cuda_bf16.h>
#include <cuda_fp16.h>
#include <cstdint>
#include <math.h>

#define NB 25
#define BATCH 4096
#define DN 1024
#define RS (NB * DN)
#define NMAT (2 * NB)
#define MM ((size_t)DN * DN)
#define NSQ_HL 4                 // hi/lo bf16 squarings incl. fp16-out transition
#define NSQ_F16 6                // single-term fp16 tail
#define NSQ (NSQ_HL + NSQ_F16)
#define BK 64
#define NKS (DN / BK)            // 16 k-stages
#define RSEB 144                 // smem row stride bytes (128B data + 16B pad)
#define MATB (128 * RSEB)        // 18432 B per matrix tile
#define STG4 (4 * MATB)          // 73728 B per stage (4 mats)
#define SMEM_BYTES (3 * STG4)    // 221184, 3-stage pipeline
#define STG2 (2 * MATB)          // 36864 B per stage (2 mats)
#define SMEM1 (2 * STG2)         // 73728 (1-term kernel, 2 stages)
#define TRTGT 256.0f             // fp16-chain trace target (entries ~0.25, no subnormals)

typedef __nv_bfloat16 bf16;
typedef __half fp16;

// ----------------------------- scratch -------------------------------------
__device__ bf16  g_xhi[(size_t)BATCH * RS];
__device__ bf16  g_xlo[(size_t)BATCH * RS];
__device__ bf16  g_wth[NMAT * MM];
__device__ bf16  g_wtl[NMAT * MM];
__device__ float g_G  [NMAT * MM];
__device__ bf16  g_P0h[NMAT * MM];
__device__ bf16  g_P0l[NMAT * MM];
__device__ bf16  g_P1h[NMAT * MM];
__device__ bf16  g_P1l[NMAT * MM];
__device__ bf16  g_hhi[(size_t)BATCH * RS];
__device__ bf16  g_hlo[(size_t)BATCH * RS];
__device__ float g_tr [(NSQ + 1) * NMAT];
__device__ float g_v  [NMAT * DN];
__device__ float g_gv [NMAT * DN];
__device__ float g_is [NMAT];

// ----------------------------- PTX helpers ---------------------------------
__device__ __forceinline__ uint32_t smem_u32(const void* p) {
    uint32_t a;
    asm("{ .reg .u64 t; cvta.to.shared.u64 t, %1; cvt.u32.u64 %0, t; }" : "=r"(a) : "l"(p));
    return a;
}
__device__ __forceinline__ void cp16(uint32_t s, const void* g) {
    asm volatile("cp.async.cg.shared.global [%0], [%1], 16;" :: "r"(s), "l"(g));
}
#define CP_COMMIT() asm volatile("cp.async.commit_group;" ::: "memory")
#define CP_WAIT(N)  asm volatile("cp.async.wait_group %0;" :: "n"(N) : "memory")

#define LDSM4(r0, r1, r2, r3, addr) \
    asm volatile("ldmatrix.sync.aligned.m8n8.x4.shared.b16 {%0,%1,%2,%3}, [%4];" \
        : "=r"(r0), "=r"(r1), "=r"(r2), "=r"(r3) : "r"(addr))

#define MMA16816(c, a, b) \
    asm volatile("mma.sync.aligned.m16n8k16.row.col.f32.bf16.bf16.f32 " \
        "{%0,%1,%2,%3}, {%4,%5,%6,%7}, {%8,%9}, {%0,%1,%2,%3};" \
        : "+f"((c)[0]), "+f"((c)[1]), "+f"((c)[2]), "+f"((c)[3]) \
        : "r"((a)[0]), "r"((a)[1]), "r"((a)[2]), "r"((a)[3]), "r"((b)[0]), "r"((b)[1]))

#define MMAH16816(c, a, b) \
    asm volatile("mma.sync.aligned.m16n8k16.row.col.f32.f16.f16.f32 " \
        "{%0,%1,%2,%3}, {%4,%5,%6,%7}, {%8,%9}, {%0,%1,%2,%3};" \
        : "+f"((c)[0]), "+f"((c)[1]), "+f"((c)[2]), "+f"((c)[3]) \
        : "r"((a)[0]), "r"((a)[1]), "r"((a)[2]), "r"((a)[3]), "r"((b)[0]), "r"((b)[1]))

// ----------------------------- conversions ---------------------------------
__global__ void __launch_bounds__(256) conv_split(const float* __restrict__ in,
                                                  bf16* __restrict__ hi, bf16* __restrict__ lo)
{
    size_t i = ((size_t)blockIdx.x * 256 + threadIdx.x) * 4;
    float4 v = *(const float4*)(in + i);
    bf16 h0 = __float2bfloat16(v.x), h1 = __float2bfloat16(v.y);
    bf16 h2 = __float2bfloat16(v.z), h3 = __float2bfloat16(v.w);
    hi[i+0] = h0; hi[i+1] = h1; hi[i+2] = h2; hi[i+3] = h3;
    lo[i+0] = __float2bfloat16(v.x - __bfloat162float(h0));
    lo[i+1] = __float2bfloat16(v.y - __bfloat162float(h1));
    lo[i+2] = __float2bfloat16(v.z - __bfloat162float(h2));
    lo[i+3] = __float2bfloat16(v.w - __bfloat162float(h3));
}

__global__ void __launch_bounds__(256) conv_wT(const float* __restrict__ w,
                                               bf16* __restrict__ hi, bf16* __restrict__ lo)
{
    const int m = blockIdx.z;
    const float* W = w + (size_t)m * MM;
    bf16* Hi = hi + (size_t)m * MM;
    bf16* Lo = lo + (size_t)m * MM;
    __shared__ float t[32][33];
    const int r0 = blockIdx.y * 32, c0 = blockIdx.x * 32;
    const int tr = threadIdx.x >> 5, tc = threadIdx.x & 31;
#pragma unroll
    for (int i = 0; i < 4; i++)
        t[tr + 8 * i][tc] = W[(size_t)(r0 + tr + 8 * i) * DN + c0 + tc];
    __syncthreads();
#pragma unroll
    for (int i = 0; i < 4; i++) {
        int rr = tr + 8 * i;
        float v = t[tc][rr];
        bf16 h = __float2bfloat16(v);
        size_t o = (size_t)(c0 + rr) * DN + r0 + tc;
        Hi[o] = h;
        Lo[o] = __float2bfloat16(v - __bfloat162float(h));
    }
}

// -------- 3-term hi/lo GEMM, 512 threads / 16 warps, 3-stage pipeline -------
// MODE 0: Gram   -> Cf (fp32) + Chi/Clo    [triangular grid + mirror]
// MODE 1: square -> Chi/Clo, scl=(1/tr)^2  [triangular grid + mirror]
// MODE 2: MLP1   -> Chi/Clo = gelu(C*is + b1)
// MODE 3: MLP2   -> Cf = C*is + b2
// MODE 4: square -> fp16 out, scl=TRTGT/tr^2 [triangular grid + mirror]
template <int MODE>
__global__ void __launch_bounds__(512, 1) gemm_k(
    const bf16* __restrict__ Ahi, const bf16* __restrict__ Alo, long lda, long aoffz,
    const bf16* __restrict__ Bhi, const bf16* __restrict__ Blo,
    float* __restrict__ Cf, bf16* __restrict__ Chi, bf16* __restrict__ Clo,
    long ldc, long coffz,
    const float* __restrict__ bias, const float* __restrict__ sc,
    const float* __restrict__ trin)
{
    constexpr bool TRI   = (MODE == 0 || MODE == 1 || MODE == 4);
    constexpr bool MLPM  = (MODE == 2 || MODE == 3);
    constexpr bool OUTF  = (MODE == 0 || MODE == 3);
    constexpr bool OUTHL = (MODE == 0 || MODE == 1 || MODE == 2);
    constexpr bool OUT16 = (MODE == 4);

    extern __shared__ char smem[];
    const uint32_t sb = smem_u32(smem);

    const int tid = threadIdx.x;
    const int wid = tid >> 5, lane = tid & 31;
    const int wr = wid >> 2, wc = wid & 3;       // 4x4 warps, 32x32 warp tiles
    const int z = blockIdx.z;

    int row0, col0;
    if (TRI) {
        int t = blockIdx.x, ti = 0;
        while (t >= 8 - ti) { t -= 8 - ti; ti++; }
        row0 = ti * 128; col0 = (ti + t) * 128;
    } else {
        row0 = blockIdx.y * 128; col0 = blockIdx.x * 128;
    }

    const bf16* Ah = Ahi + (size_t)z * aoffz + (size_t)row0 * lda;
    const bf16* Al = Alo + (size_t)z * aoffz + (size_t)row0 * lda;
    const bf16* Bh = Bhi + (size_t)z * MM + (size_t)col0 * DN;
    const bf16* Bl = Blo + (size_t)z * MM + (size_t)col0 * DN;

    const bf16* gbase[4] = {Ah, Al, Bh, Bl};
    const long  gstr [4] = {lda, lda, DN, DN};

    auto load_stage = [&](int st, int k0) {
        const uint32_t base = sb + (uint32_t)st * STG4;
        const int ch = tid & 7;
        const int rlo = tid >> 3;                 // 0..63
#pragma unroll
        for (int t = 0; t < 8; t++) {
            const int mat = t >> 1;
            const int r = ((t & 1) << 6) + rlo;   // 0..127
            cp16(base + (uint32_t)mat * MATB + (uint32_t)(r * RSEB + ch * 16),
                 gbase[mat] + (long)r * gstr[mat] + k0 + ch * 8);
        }
        CP_COMMIT();
    };

    float acc[2][4][4];
#pragma unroll
    for (int mi = 0; mi < 2; mi++)
#pragma unroll
        for (int ni = 0; ni < 4; ni++)
#pragma unroll
            for (int q = 0; q < 4; q++) acc[mi][ni][q] = 0.0f;

    load_stage(0, 0);
    load_stage(1, BK);

    const int arow = (lane & 7) + ((lane >> 3) & 1) * 8;
    const int acol = (lane >> 4) * 16;
    const int brow = (lane & 7) + ((lane >> 4) & 1) * 8;
    const int bcol = ((lane >> 3) & 1) * 16;

    for (int s = 0; s < NKS; s++) {
        if (s < NKS - 1) { CP_WAIT(1); } else { CP_WAIT(0); }
        __syncthreads();
        if (s + 2 < NKS) load_stage((s + 2) % 3, (s + 2) * BK);

        const uint32_t stb = sb + (uint32_t)(s % 3) * STG4;
        const uint32_t aBh = stb + (uint32_t)((wr * 32 + arow) * RSEB) + acol;
        const uint32_t aBl = aBh + MATB;
        const uint32_t bBh = stb + 2u * MATB + (uint32_t)((wc * 32 + brow) * RSEB) + bcol;
        const uint32_t bBl = bBh + MATB;

#pragma unroll
        for (int kk = 0; kk < 4; kk++) {
            const uint32_t ko = (uint32_t)(kk * 32);
            uint32_t ah[2][4], al[2][4], bh[4][2], bl[4][2];
#pragma unroll
            for (int mi = 0; mi < 2; mi++) {
                LDSM4(ah[mi][0], ah[mi][1], ah[mi][2], ah[mi][3], aBh + ko + (uint32_t)(mi * 16 * RSEB));
                LDSM4(al[mi][0], al[mi][1], al[mi][2], al[mi][3], aBl + ko + (uint32_t)(mi * 16 * RSEB));
            }
#pragma unroll
            for (int p = 0; p < 2; p++) {
                LDSM4(bh[2*p][0], bh[2*p][1], bh[2*p+1][0], bh[2*p+1][1], bBh + ko + (uint32_t)(p * 16 * RSEB));
                LDSM4(bl[2*p][0], bl[2*p][1], bl[2*p+1][0], bl[2*p+1][1], bBl + ko + (uint32_t)(p * 16 * RSEB));
            }
#pragma unroll
            for (int mi = 0; mi < 2; mi++)
#pragma unroll
                for (int ni = 0; ni < 4; ni++) MMA16816(acc[mi][ni], ah[mi], bh[ni]);
#pragma unroll
            for (int mi = 0; mi < 2; mi++)
#pragma unroll
                for (int ni = 0; ni < 4; ni++) MMA16816(acc[mi][ni], ah[mi], bl[ni]);
#pragma unroll
            for (int mi = 0; mi < 2; mi++)
#pragma unroll
                for (int ni = 0; ni < 4; ni++) MMA16816(acc[mi][ni], al[mi], bh[ni]);
        }
        __syncthreads();
    }

    // ------------------------------ epilogue -------------------------------
    float scl = 1.0f;
    if (MODE == 1) { float it = 1.0f / trin[z]; scl = it * it; }
    if (MODE == 4) { float tv = trin[z]; scl = TRTGT / (tv * tv); }
    if (MLPM) scl = sc[z];
    const int gID = lane >> 2, tg = lane & 3;
    const bool mirror = TRI && (row0 != col0);
    float* ts = (float*)smem;
    fp16* C16 = reinterpret_cast<fp16*>(Chi);

#pragma unroll
    for (int mi = 0; mi < 2; mi++)
#pragma unroll
        for (int ni = 0; ni < 4; ni++)
#pragma unroll
            for (int hf = 0; hf < 2; hf++) {
                const int rl = wr * 32 + mi * 16 + gID + hf * 8;
                const int cl = wc * 32 + ni * 8 + tg * 2;
                float v0 = acc[mi][ni][hf * 2 + 0] * scl;
                float v1 = acc[mi][ni][hf * 2 + 1] * scl;
                if (MLPM) {
                    v0 += bias[z * DN + col0 + cl];
                    v1 += bias[z * DN + col0 + cl + 1];
                }
                if (MODE == 2) {
                    v0 = 0.5f * v0 * (1.0f + erff(v0 * 0.70710678118654752f));
                    v1 = 0.5f * v1 * (1.0f + erff(v1 * 0.70710678118654752f));
                }
                const size_t off = (size_t)z * coffz + (size_t)(row0 + rl) * ldc + col0 + cl;
                if (OUTF) {
                    float2 f2; f2.x = v0; f2.y = v1;
                    *(float2*)(Cf + off) = f2;
                }
                if (OUTHL) {
                    bf16 h0 = __float2bfloat16(v0);
                    bf16 h1 = __float2bfloat16(v1);
                    __nv_bfloat162 hh; hh.x = h0; hh.y = h1;
                    __nv_bfloat162 ll;
                    ll.x = __float2bfloat16(v0 - __bfloat162float(h0));
                    ll.y = __float2bfloat16(v1 - __bfloat162float(h1));
                    *(__nv_bfloat162*)(Chi + off) = hh;
                    *(__nv_bfloat162*)(Clo + off) = ll;
                }
                if (OUT16) {
                    __half2 hh = __floats2half2_rn(v0, v1);
                    *(__half2*)(C16 + off) = hh;
                }
                if (mirror) {
                    ts[rl * 129 + cl] = v0;
                    ts[rl * 129 + cl + 1] = v1;
                }
            }

    if (mirror) {
        __syncthreads();
#pragma unroll 4
        for (int i = 0; i < 16; i++) {
            int lin = i * 1024 + tid * 2;
            int mr = lin >> 7, mc = lin & 127;
            float v0 = ts[mc * 129 + mr];
            float v1 = ts[(mc + 1) * 129 + mr];
            const size_t off = (size_t)z * coffz + (size_t)(col0 + mr) * ldc + row0 + mc;
            if (MODE == 0) {
                float2 f2; f2.x = v0; f2.y = v1;
                *(float2*)(Cf + off) = f2;
            }
            if (OUTHL) {
                bf16 h0 = __float2bfloat16(v0);
                bf16 h1 = __float2bfloat16(v1);
                __nv_bfloat162 hh; hh.x = h0; hh.y = h1;
                __nv_bfloat162 ll;
                ll.x = __float2bfloat16(v0 - __bfloat162float(h0));
                ll.y = __float2bfloat16(v1 - __bfloat162float(h1));
                *(__nv_bfloat162*)(Chi + off) = hh;
                *(__nv_bfloat162*)(Clo + off) = ll;
            }
            if (OUT16) {
                __half2 hh = __floats2half2_rn(v0, v1);
                *(__half2*)(C16 + off) = hh;
            }
        }
    }
}

// ------------- 1-term fp16 squaring GEMM, 2-stage, 2 CTAs/SM ----------------
// Tail squarings; chain kept at trace ~= TRTGT so entries stay ~0.25 (no subnormals).
__global__ void __launch_bounds__(256, 2) gemm1h_k(
    const fp16* __restrict__ Ph, fp16* __restrict__ Po,
    const float* __restrict__ trin)
{
    extern __shared__ char smem[];
    const uint32_t sb = smem_u32(smem);

    const int tid = threadIdx.x;
    const int wid = tid >> 5, lane = tid & 31;
    const int wr = wid >> 1, wc = wid & 1;
    const int z = blockIdx.z;

    int t = blockIdx.x, ti = 0;
    while (t >= 8 - ti) { t -= 8 - ti; ti++; }
    const int row0 = ti * 128, col0 = (ti + t) * 128;

    const fp16* Ah = Ph + (size_t)z * MM + (size_t)row0 * DN;
    const fp16* Bh = Ph + (size_t)z * MM + (size_t)col0 * DN;

    auto load_stage = [&](int st, int k0) {
        const uint32_t base = sb + (uint32_t)st * STG2;
        const int ch = tid & 7;
        const int rlo = tid >> 3;
#pragma unroll
        for (int t2 = 0; t2 < 8; t2++) {
            const int mat = t2 >> 2;
            const int r = ((t2 & 3) << 5) + rlo;
            const fp16* src = mat ? Bh : Ah;
            cp16(base + (uint32_t)mat * MATB + (uint32_t)(r * RSEB + ch * 16),
                 src + (long)r * DN + k0 + ch * 8);
        }
        CP_COMMIT();
    };

    float acc[2][8][4];
#pragma unroll
    for (int mi = 0; mi < 2; mi++)
#pragma unroll
        for (int ni = 0; ni < 8; ni++)
#pragma unroll
            for (int q = 0; q < 4; q++) acc[mi][ni][q] = 0.0f;

    load_stage(0, 0);

    const int arow = (lane & 7) + ((lane >> 3) & 1) * 8;
    const int acol = (lane >> 4) * 16;
    const int brow = (lane & 7) + ((lane >> 4) & 1) * 8;
    const int bcol = ((lane >> 3) & 1) * 16;

    for (int s = 0; s < NKS; s++) {
        CP_WAIT(0);
        __syncthreads();
        if (s + 1 < NKS) load_stage((s + 1) & 1, (s + 1) * BK);

        const uint32_t stb = sb + (uint32_t)(s & 1) * STG2;
        const uint32_t aB = stb + (uint32_t)((wr * 32 + arow) * RSEB) + acol;
        const uint32_t bB = stb + MATB + (uint32_t)((wc * 64 + brow) * RSEB) + bcol;

#pragma unroll
        for (int kk = 0; kk < 4; kk++) {
            const uint32_t ko = (uint32_t)(kk * 32);
            uint32_t ah[2][4], bh[8][2];
#pragma unroll
            for (int mi = 0; mi < 2; mi++)
                LDSM4(ah[mi][0], ah[mi][1], ah[mi][2], ah[mi][3], aB + ko + (uint32_t)(mi * 16 * RSEB));
#pragma unroll
            for (int p = 0; p < 4; p++)
                LDSM4(bh[2*p][0], bh[2*p][1], bh[2*p+1][0], bh[2*p+1][1], bB + ko + (uint32_t)(p * 16 * RSEB));
#pragma unroll
            for (int mi = 0; mi < 2; mi++)
#pragma unroll
                for (int ni = 0; ni < 8; ni++) MMAH16816(acc[mi][ni], ah[mi], bh[ni]);
        }
        __syncthreads();
    }

    const float tv = trin[z];
    const float scl = TRTGT / (tv * tv);   // fixed point: X=TRTGT*vv^T -> out=TRTGT*vv^T
    const int gID = lane >> 2, tg = lane & 3;
    const bool mirror = (row0 != col0);
    float* ts = (float*)smem;

#pragma unroll
    for (int mi = 0; mi < 2; mi++)
#pragma unroll
        for (int ni = 0; ni < 8; ni++)
#pragma unroll
            for (int hf = 0; hf < 2; hf++) {
                const int rl = wr * 32 + mi * 16 + gID + hf * 8;
                const int cl = wc * 64 + ni * 8 + tg * 2;
                float v0 = acc[mi][ni][hf * 2 + 0] * scl;
                float v1 = acc[mi][ni][hf * 2 + 1] * scl;
                const size_t off = (size_t)z * MM + (size_t)(row0 + rl) * DN + col0 + cl;
                *(__half2*)(Po + off) = __floats2half2_rn(v0, v1);
                if (mirror) {
                    ts[rl * 129 + cl] = v0;
                    ts[rl * 129 + cl + 1] = v1;
                }
            }

    if (mirror) {
        __syncthreads();
#pragma unroll 4
        for (int i = 0; i < 32; i++) {
            int lin = i * 512 + tid * 2;
            int mr = lin >> 7, mc = lin & 127;
            float v0 = ts[mc * 129 + mr];
            float v1 = ts[(mc + 1) * 129 + mr];
            const size_t off = (size_t)z * MM + (size_t)(col0 + mr) * DN + row0 + mc;
            *(__half2*)(Po + off) = __floats2half2_rn(v0, v1);
        }
    }
}

// --------------------------- small kernels ----------------------------------
__global__ void __launch_bounds__(256) k_trace_f(const float* __restrict__ G,
                                                 float* __restrict__ out)
{
    const int m = blockIdx.x;
    float sum = 0.0f;
    for (int d = threadIdx.x; d < DN; d += 256)
        sum += G[(size_t)m * MM + (size_t)d * DN + d];
    __shared__ float red[256];
    red[threadIdx.x] = sum; __syncthreads();
    for (int off = 128; off > 0; off >>= 1) {
        if (threadIdx.x < off) red[threadIdx.x] += red[threadIdx.x + off];
        __syncthreads();
    }
    if (threadIdx.x == 0) out[m] = red[0];
}

__global__ void __launch_bounds__(256) k_trace_hl(const bf16* __restrict__ Ph,
                                                  const bf16* __restrict__ Pl,
                                                  float* __restrict__ out)
{
    const int m = blockIdx.x;
    float sum = 0.0f;
    for (int d = threadIdx.x; d < DN; d += 256) {
        size_t o = (size_t)m * MM + (size_t)d * DN + d;
        sum += __bfloat162float(Ph[o]) + __bfloat162float(Pl[o]);
    }
    __shared__ float red[256];
    red[threadIdx.x] = sum; __syncthreads();
    for (int off = 128; off > 0; off >>= 1) {
        if (threadIdx.x < off) red[threadIdx.x] += red[threadIdx.x + off];
        __syncthreads();
    }
    if (threadIdx.x == 0) out[m] = red[0];
}

__global__ void __launch_bounds__(256) k_trace_h16(const fp16* __restrict__ P,
                                                   float* __restrict__ out)
{
    const int m = blockIdx.x;
    float sum = 0.0f;
    for (int d = threadIdx.x; d < DN; d += 256)
        sum += __half2float(P[(size_t)m * MM + (size_t)d * DN + d]);
    __shared__ float red[256];
    red[threadIdx.x] = sum; __syncthreads();
    for (int off = 128; off > 0; off >>= 1) {
        if (threadIdx.x < off) red[threadIdx.x] += red[threadIdx.x + off];
        __syncthreads();
    }
    if (threadIdx.x == 0) out[m] = red[0];
}

// Robust extractor: j = argmax_d |P[d][d]| (diag ~ lambda*v_d^2), then v = P[:,j].
__global__ void __launch_bounds__(256) k_pickcol16(const fp16* __restrict__ P,
                                                   float* __restrict__ v)
{
    const int m = blockIdx.x;
    const size_t base = (size_t)m * MM;
    __shared__ float bv[256];
    __shared__ int bi[256];
    float best = -1.0f; int bidx = 0;
    for (int d = threadIdx.x; d < DN; d += 256) {
        float val = fabsf(__half2float(P[base + (size_t)d * DN + d]));
        if (val > best) { best = val; bidx = d; }
    }
    bv[threadIdx.x] = best; bi[threadIdx.x] = bidx;
    __syncthreads();
    for (int off = 128; off > 0; off >>= 1) {
        if (threadIdx.x < off && bv[threadIdx.x + off] > bv[threadIdx.x]) {
            bv[threadIdx.x] = bv[threadIdx.x + off];
            bi[threadIdx.x] = bi[threadIdx.x + off];
        }
        __syncthreads();
    }
    const int j = bi[0];
    for (int i = threadIdx.x; i < DN; i += 256)
        v[m * DN + i] = __half2float(P[base + (size_t)j * DN + i]);
}

__global__ void __launch_bounds__(256) k_matvec(const float* __restrict__ G,
                                                const float* __restrict__ v,
                                                float* __restrict__ gv)
{
    const int m = blockIdx.y, r = blockIdx.x;
    const float* row = G + (size_t)m * MM + (size_t)r * DN;
    const float* vm = v + m * DN;
    float4 a = *(const float4*)&row[threadIdx.x * 4];
    float4 b = *(const float4*)&vm[threadIdx.x * 4];
    float sum = a.x * b.x + a.y * b.y + a.z * b.z + a.w * b.w;
    __shared__ float red[256];
    red[threadIdx.x] = sum; __syncthreads();
    for (int off = 128; off > 0; off >>= 1) {
        if (threadIdx.x < off) red[threadIdx.x] += red[threadIdx.x + off];
        __syncthreads();
    }
    if (threadIdx.x == 0) gv[m * DN + r] = red[0];
}

__global__ void __launch_bounds__(256) k_sigma(const float* __restrict__ v,
                                               const float* __restrict__ gv,
                                               float* __restrict__ is_)
{
    const int m = blockIdx.x;
    float num = 0.0f, den = 0.0f;
    for (int d = threadIdx.x; d < DN; d += 256) {
        float vv = v[m * DN + d];
        num += vv * gv[m * DN + d];
        den += vv * vv;
    }
    __shared__ float rn[256], rd[256];
    rn[threadIdx.x] = num; rd[threadIdx.x] = den; __syncthreads();
    for (int off = 128; off > 0; off >>= 1) {
        if (threadIdx.x < off) { rn[threadIdx.x] += rn[threadIdx.x + off]; rd[threadIdx.x] += rd[threadIdx.x + off]; }
        __syncthreads();
    }
    if (threadIdx.x == 0) is_[m] = sqrtf(rd[0] / rn[0]);
}

// ---------------------------------------------------------------------------
extern "C" void kernel_launch(void* const* d_in, const int* in_sizes, int n_in,
                              void* d_out, int out_size)
{
    const float* x  = (const float*)d_in[0];
    const float* w1 = (const float*)d_in[1];
    const float* b1 = (const float*)d_in[2];
    const float* w2 = (const float*)d_in[3];
    const float* b2 = (const float*)d_in[4];
    float* out = (float*)d_out;

    bf16 *xhi, *xlo, *wth, *wtl, *P0h, *P0l, *P1h, *P1l, *hhi, *hlo;
    float *G, *tr, *v, *gv, *is_;
    cudaGetSymbolAddress((void**)&xhi, g_xhi); cudaGetSymbolAddress((void**)&xlo, g_xlo);
    cudaGetSymbolAddress((void**)&wth, g_wth); cudaGetSymbolAddress((void**)&wtl, g_wtl);
    cudaGetSymbolAddress((void**)&G, g_G);
    cudaGetSymbolAddress((void**)&P0h, g_P0h); cudaGetSymbolAddress((void**)&P0l, g_P0l);
    cudaGetSymbolAddress((void**)&P1h, g_P1h); cudaGetSymbolAddress((void**)&P1l, g_P1l);
    cudaGetSymbolAddress((void**)&hhi, g_hhi); cudaGetSymbolAddress((void**)&hlo, g_hlo);
    cudaGetSymbolAddress((void**)&tr, g_tr);   cudaGetSymbolAddress((void**)&v, g_v);
    cudaGetSymbolAddress((void**)&gv, g_gv);   cudaGetSymbolAddress((void**)&is_, g_is);

    cudaFuncSetAttribute(gemm_k<0>, cudaFuncAttributeMaxDynamicSharedMemorySize, SMEM_BYTES);
    cudaFuncSetAttribute(gemm_k<1>, cudaFuncAttributeMaxDynamicSharedMemorySize, SMEM_BYTES);
    cudaFuncSetAttribute(gemm_k<2>, cudaFuncAttributeMaxDynamicSharedMemorySize, SMEM_BYTES);
    cudaFuncSetAttribute(gemm_k<3>, cudaFuncAttributeMaxDynamicSharedMemorySize, SMEM_BYTES);
    cudaFuncSetAttribute(gemm_k<4>, cudaFuncAttributeMaxDynamicSharedMemorySize, SMEM_BYTES);
    cudaFuncSetAttribute(gemm1h_k,  cudaFuncAttributeMaxDynamicSharedMemorySize, SMEM1);

    conv_split<<<(unsigned)((size_t)BATCH * RS / 4 / 256), 256>>>(x, xhi, xlo);
    conv_wT<<<dim3(32, 32, NB), 256>>>(w1, wth, wtl);
    conv_wT<<<dim3(32, 32, NB), 256>>>(w2, wth + (size_t)NB * MM, wtl + (size_t)NB * MM);

    // Gram: G (fp32) + P0 hi/lo, triangular grid; trace from fp32 G
    gemm_k<0><<<dim3(36, 1, NMAT), 512, SMEM_BYTES>>>(
        wth, wtl, DN, (long)MM, wth, wtl, G, P0h, P0l, DN, (long)MM,
        nullptr, nullptr, nullptr);
    k_trace_f<<<NMAT, 256>>>(G, tr);

    // Steps 1..3: hi/lo bf16 squarings (small-gap regime)
    bf16 *pih = P0h, *pil = P0l, *poh = P1h, *pol = P1l;
    int step = 0;
    for (int s = 0; s < NSQ_HL - 1; s++, step++) {
        gemm_k<1><<<dim3(36, 1, NMAT), 512, SMEM_BYTES>>>(
            pih, pil, DN, (long)MM, pih, pil, nullptr, poh, pol, DN, (long)MM,
            nullptr, nullptr, tr + step * NMAT);
        k_trace_hl<<<NMAT, 256>>>(poh, pol, tr + (step + 1) * NMAT);
        bf16* t1 = pih; pih = poh; poh = t1;
        bf16* t2 = pil; pil = pol; pol = t2;
    }
    // Step 4: hi/lo -> fp16 single output scaled to trace TRTGT
    fp16* q0 = reinterpret_cast<fp16*>(poh == P0h ? P0h : P1h);
    {
        gemm_k<4><<<dim3(36, 1, NMAT), 512, SMEM_BYTES>>>(
            pih, pil, DN, (long)MM, pih, pil, nullptr, (bf16*)q0, nullptr, DN, (long)MM,
            nullptr, nullptr, tr + step * NMAT);
        step++;
        k_trace_h16<<<NMAT, 256>>>(q0, tr + step * NMAT);
    }
    // Steps 5..10: single-term fp16 squarings at trace TRTGT
    fp16* pi16 = q0;
    fp16* po16 = reinterpret_cast<fp16*>((void*)q0 == (void*)P0h ? P1h : P0h);
    for (int s = 0; s < NSQ_F16; s++, step++) {
        gemm1h_k<<<dim3(36, 1, NMAT), 256, SMEM1>>>(pi16, po16, tr + step * NMAT);
        k_trace_h16<<<NMAT, 256>>>(po16, tr + (step + 1) * NMAT);
        fp16* t1 = pi16; pi16 = po16; po16 = t1;
    }

    // Rayleigh quotient on fp32 G with v = argmax-diag column of P_final
    k_pickcol16<<<NMAT, 256>>>(pi16, v);
    k_matvec<<<dim3(DN, NMAT), 256>>>(G, v, gv);
    k_sigma<<<NMAT, 256>>>(v, gv, is_);

    // MLP
    gemm_k<2><<<dim3(8, 32, NB), 512, SMEM_BYTES>>>(
        xhi, xlo, RS, (long)DN, wth, wtl, nullptr, hhi, hlo, RS, (long)DN,
        b1, is_, nullptr);
    gemm_k<3><<<dim3(8, 32, NB), 512, SMEM_BYTES>>>(
        hhi, hlo, RS, (long)DN, wth + (size_t)NB * MM, wtl + (size_t)NB * MM,
        out, nullptr, nullptr, RS, (long)DN, b2, is_ + NB, nullptr);
}

// round 14
// speedup vs baseline: 1.7647x; 1.1446x over previous
#include <cuda_runtime.h>
#include <cuda_bf16.h>
#include <cuda_fp16.h>
#include <cstdint>
#include <math.h>

#define NB 25
#define BATCH 4096
#define DN 1024
#define RS (NB * DN)
#define NMAT (2 * NB)
#define MM ((size_t)DN * DN)
#define NSQ_HL 4                 // hi/lo bf16 squarings incl. fp16-out transition
#define NSQ_F16 6                // single-term fp16 tail
#define NSQ (NSQ_HL + NSQ_F16)
#define BK 64
#define NKS (DN / BK)            // 16 k-stages
#define RSEB 144                 // smem row stride bytes (128B data + 16B pad)
#define MATB (128 * RSEB)        // 18432 B per matrix tile
#define STG4 (4 * MATB)          // 73728 B per stage (4 mats)
#define SMEM_BYTES (3 * STG4)    // 221184, 3-stage pipeline
#define STG2 (2 * MATB)          // 36864 B per stage (2 mats)
#define SMEM1 (2 * STG2)         // 73728 (1-term kernel, 2 stages)
#define STG3 (3 * MATB)          // 55296 B per stage (3 mats)
#define SMEM2H (3 * STG3)        // 165888 (2-term fp16 MLP kernel, 3 stages)
#define TRTGT 256.0f             // fp16-chain trace target

typedef __nv_bfloat16 bf16;
typedef __half fp16;

// ----------------------------- scratch -------------------------------------
__device__ fp16  g_x16[(size_t)BATCH * RS];     // x as single fp16 (MLP1 A)
__device__ bf16  g_wth[NMAT * MM];              // W^T bf16 hi (Gram)
__device__ bf16  g_wtl[NMAT * MM];              // W^T bf16 lo (Gram)
__device__ fp16  g_w16h[NMAT * MM];             // W^T fp16 hi (MLP)
__device__ fp16  g_w16l[NMAT * MM];             // W^T fp16 lo (MLP)
__device__ float g_G  [NMAT * MM];
__device__ bf16  g_P0h[NMAT * MM];
__device__ bf16  g_P0l[NMAT * MM];
__device__ bf16  g_P1h[NMAT * MM];
__device__ bf16  g_P1l[NMAT * MM];
__device__ fp16  g_h16[(size_t)BATCH * RS];     // hidden as single fp16 (MLP2 A)
__device__ float g_tr [(NSQ + 1) * NMAT];
__device__ float g_v  [NMAT * DN];
__device__ float g_gv [NMAT * DN];
__device__ float g_is [NMAT];

// ----------------------------- PTX helpers ---------------------------------
__device__ __forceinline__ uint32_t smem_u32(const void* p) {
    uint32_t a;
    asm("{ .reg .u64 t; cvta.to.shared.u64 t, %1; cvt.u32.u64 %0, t; }" : "=r"(a) : "l"(p));
    return a;
}
__device__ __forceinline__ void cp16(uint32_t s, const void* g) {
    asm volatile("cp.async.cg.shared.global [%0], [%1], 16;" :: "r"(s), "l"(g));
}
#define CP_COMMIT() asm volatile("cp.async.commit_group;" ::: "memory")
#define CP_WAIT(N)  asm volatile("cp.async.wait_group %0;" :: "n"(N) : "memory")

#define LDSM4(r0, r1, r2, r3, addr) \
    asm volatile("ldmatrix.sync.aligned.m8n8.x4.shared.b16 {%0,%1,%2,%3}, [%4];" \
        : "=r"(r0), "=r"(r1), "=r"(r2), "=r"(r3) : "r"(addr))

#define MMA16816(c, a, b) \
    asm volatile("mma.sync.aligned.m16n8k16.row.col.f32.bf16.bf16.f32 " \
        "{%0,%1,%2,%3}, {%4,%5,%6,%7}, {%8,%9}, {%0,%1,%2,%3};" \
        : "+f"((c)[0]), "+f"((c)[1]), "+f"((c)[2]), "+f"((c)[3]) \
        : "r"((a)[0]), "r"((a)[1]), "r"((a)[2]), "r"((a)[3]), "r"((b)[0]), "r"((b)[1]))

#define MMAH16816(c, a, b) \
    asm volatile("mma.sync.aligned.m16n8k16.row.col.f32.f16.f16.f32 " \
        "{%0,%1,%2,%3}, {%4,%5,%6,%7}, {%8,%9}, {%0,%1,%2,%3};" \
        : "+f"((c)[0]), "+f"((c)[1]), "+f"((c)[2]), "+f"((c)[3]) \
        : "r"((a)[0]), "r"((a)[1]), "r"((a)[2]), "r"((a)[3]), "r"((b)[0]), "r"((b)[1]))

// ----------------------------- conversions ---------------------------------
__global__ void __launch_bounds__(256) conv_x16(const float* __restrict__ in,
                                                fp16* __restrict__ out)
{
    size_t i = ((size_t)blockIdx.x * 256 + threadIdx.x) * 4;
    float4 v = *(const float4*)(in + i);
    *(__half2*)(out + i)     = __floats2half2_rn(v.x, v.y);
    *(__half2*)(out + i + 2) = __floats2half2_rn(v.z, v.w);
}

// W transpose + quad split: bf16 hi/lo (Gram) and fp16 hi/lo (MLP), one pass.
__global__ void __launch_bounds__(256) conv_wT(const float* __restrict__ w,
                                               bf16* __restrict__ bhi, bf16* __restrict__ blo,
                                               fp16* __restrict__ hhi, fp16* __restrict__ hlo)
{
    const int m = blockIdx.z;
    const float* W = w + (size_t)m * MM;
    bf16* Bh = bhi + (size_t)m * MM;
    bf16* Bl = blo + (size_t)m * MM;
    fp16* Hh = hhi + (size_t)m * MM;
    fp16* Hl = hlo + (size_t)m * MM;
    __shared__ float t[32][33];
    const int r0 = blockIdx.y * 32, c0 = blockIdx.x * 32;
    const int tr = threadIdx.x >> 5, tc = threadIdx.x & 31;
#pragma unroll
    for (int i = 0; i < 4; i++)
        t[tr + 8 * i][tc] = W[(size_t)(r0 + tr + 8 * i) * DN + c0 + tc];
    __syncthreads();
#pragma unroll
    for (int i = 0; i < 4; i++) {
        int rr = tr + 8 * i;
        float v = t[tc][rr];
        size_t o = (size_t)(c0 + rr) * DN + r0 + tc;
        bf16 h = __float2bfloat16(v);
        Bh[o] = h;
        Bl[o] = __float2bfloat16(v - __bfloat162float(h));
        fp16 h6 = __float2half_rn(v);
        Hh[o] = h6;
        Hl[o] = __float2half_rn(v - __half2float(h6));
    }
}

// -------- 3-term hi/lo bf16 GEMM (Gram/squarings), 512 thr, 3-stage --------
// MODE 0: Gram   -> Cf (fp32) + Chi/Clo    [triangular grid + mirror]
// MODE 1: square -> Chi/Clo, scl=(1/tr)^2  [triangular grid + mirror]
// MODE 4: square -> fp16 out, scl=TRTGT/tr^2 [triangular grid + mirror]
template <int MODE>
__global__ void __launch_bounds__(512, 1) gemm_k(
    const bf16* __restrict__ Ahi, const bf16* __restrict__ Alo,
    const bf16* __restrict__ Bhi, const bf16* __restrict__ Blo,
    float* __restrict__ Cf, bf16* __restrict__ Chi, bf16* __restrict__ Clo,
    const float* __restrict__ trin)
{
    constexpr bool OUT16 = (MODE == 4);
    extern __shared__ char smem[];
    const uint32_t sb = smem_u32(smem);

    const int tid = threadIdx.x;
    const int wid = tid >> 5, lane = tid & 31;
    const int wr = wid >> 2, wc = wid & 3;
    const int z = blockIdx.z;

    int t = blockIdx.x, ti = 0;
    while (t >= 8 - ti) { t -= 8 - ti; ti++; }
    const int row0 = ti * 128, col0 = (ti + t) * 128;

    const bf16* Ah = Ahi + (size_t)z * MM + (size_t)row0 * DN;
    const bf16* Al = Alo + (size_t)z * MM + (size_t)row0 * DN;
    const bf16* Bh = Bhi + (size_t)z * MM + (size_t)col0 * DN;
    const bf16* Bl = Blo + (size_t)z * MM + (size_t)col0 * DN;
    const bf16* gbase[4] = {Ah, Al, Bh, Bl};

    auto load_stage = [&](int st, int k0) {
        const uint32_t base = sb + (uint32_t)st * STG4;
        const int ch = tid & 7;
        const int rlo = tid >> 3;
#pragma unroll
        for (int t2 = 0; t2 < 8; t2++) {
            const int mat = t2 >> 1;
            const int r = ((t2 & 1) << 6) + rlo;
            cp16(base + (uint32_t)mat * MATB + (uint32_t)(r * RSEB + ch * 16),
                 gbase[mat] + (long)r * DN + k0 + ch * 8);
        }
        CP_COMMIT();
    };

    float acc[2][4][4];
#pragma unroll
    for (int mi = 0; mi < 2; mi++)
#pragma unroll
        for (int ni = 0; ni < 4; ni++)
#pragma unroll
            for (int q = 0; q < 4; q++) acc[mi][ni][q] = 0.0f;

    load_stage(0, 0);
    load_stage(1, BK);

    const int arow = (lane & 7) + ((lane >> 3) & 1) * 8;
    const int acol = (lane >> 4) * 16;
    const int brow = (lane & 7) + ((lane >> 4) & 1) * 8;
    const int bcol = ((lane >> 3) & 1) * 16;

    for (int s = 0; s < NKS; s++) {
        if (s < NKS - 1) { CP_WAIT(1); } else { CP_WAIT(0); }
        __syncthreads();
        if (s + 2 < NKS) load_stage((s + 2) % 3, (s + 2) * BK);

        const uint32_t stb = sb + (uint32_t)(s % 3) * STG4;
        const uint32_t aBh = stb + (uint32_t)((wr * 32 + arow) * RSEB) + acol;
        const uint32_t aBl = aBh + MATB;
        const uint32_t bBh = stb + 2u * MATB + (uint32_t)((wc * 32 + brow) * RSEB) + bcol;
        const uint32_t bBl = bBh + MATB;

#pragma unroll
        for (int kk = 0; kk < 4; kk++) {
            const uint32_t ko = (uint32_t)(kk * 32);
            uint32_t ah[2][4], al[2][4], bh[4][2], bl[4][2];
#pragma unroll
            for (int mi = 0; mi < 2; mi++) {
                LDSM4(ah[mi][0], ah[mi][1], ah[mi][2], ah[mi][3], aBh + ko + (uint32_t)(mi * 16 * RSEB));
                LDSM4(al[mi][0], al[mi][1], al[mi][2], al[mi][3], aBl + ko + (uint32_t)(mi * 16 * RSEB));
            }
#pragma unroll
            for (int p = 0; p < 2; p++) {
                LDSM4(bh[2*p][0], bh[2*p][1], bh[2*p+1][0], bh[2*p+1][1], bBh + ko + (uint32_t)(p * 16 * RSEB));
                LDSM4(bl[2*p][0], bl[2*p][1], bl[2*p+1][0], bl[2*p+1][1], bBl + ko + (uint32_t)(p * 16 * RSEB));
            }
#pragma unroll
            for (int mi = 0; mi < 2; mi++)
#pragma unroll
                for (int ni = 0; ni < 4; ni++) MMA16816(acc[mi][ni], ah[mi], bh[ni]);
#pragma unroll
            for (int mi = 0; mi < 2; mi++)
#pragma unroll
                for (int ni = 0; ni < 4; ni++) MMA16816(acc[mi][ni], ah[mi], bl[ni]);
#pragma unroll
            for (int mi = 0; mi < 2; mi++)
#pragma unroll
                for (int ni = 0; ni < 4; ni++) MMA16816(acc[mi][ni], al[mi], bh[ni]);
        }
        __syncthreads();
    }

    float scl = 1.0f;
    if (MODE == 1) { float it = 1.0f / trin[z]; scl = it * it; }
    if (MODE == 4) { float tv = trin[z]; scl = TRTGT / (tv * tv); }
    const int gID = lane >> 2, tg = lane & 3;
    const bool mirror = (row0 != col0);
    float* ts = (float*)smem;
    fp16* C16 = reinterpret_cast<fp16*>(Chi);

#pragma unroll
    for (int mi = 0; mi < 2; mi++)
#pragma unroll
        for (int ni = 0; ni < 4; ni++)
#pragma unroll
            for (int hf = 0; hf < 2; hf++) {
                const int rl = wr * 32 + mi * 16 + gID + hf * 8;
                const int cl = wc * 32 + ni * 8 + tg * 2;
                float v0 = acc[mi][ni][hf * 2 + 0] * scl;
                float v1 = acc[mi][ni][hf * 2 + 1] * scl;
                const size_t off = (size_t)z * MM + (size_t)(row0 + rl) * DN + col0 + cl;
                if (MODE == 0) {
                    float2 f2; f2.x = v0; f2.y = v1;
                    *(float2*)(Cf + off) = f2;
                }
                if (!OUT16) {
                    bf16 h0 = __float2bfloat16(v0);
                    bf16 h1 = __float2bfloat16(v1);
                    __nv_bfloat162 hh; hh.x = h0; hh.y = h1;
                    __nv_bfloat162 ll;
                    ll.x = __float2bfloat16(v0 - __bfloat162float(h0));
                    ll.y = __float2bfloat16(v1 - __bfloat162float(h1));
                    *(__nv_bfloat162*)(Chi + off) = hh;
                    *(__nv_bfloat162*)(Clo + off) = ll;
                } else {
                    *(__half2*)(C16 + off) = __floats2half2_rn(v0, v1);
                }
                if (mirror) {
                    ts[rl * 129 + cl] = v0;
                    ts[rl * 129 + cl + 1] = v1;
                }
            }

    if (mirror) {
        __syncthreads();
#pragma unroll 4
        for (int i = 0; i < 16; i++) {
            int lin = i * 1024 + tid * 2;
            int mr = lin >> 7, mc = lin & 127;
            float v0 = ts[mc * 129 + mr];
            float v1 = ts[(mc + 1) * 129 + mr];
            const size_t off = (size_t)z * MM + (size_t)(col0 + mr) * DN + row0 + mc;
            if (MODE == 0) {
                float2 f2; f2.x = v0; f2.y = v1;
                *(float2*)(Cf + off) = f2;
            }
            if (!OUT16) {
                bf16 h0 = __float2bfloat16(v0);
                bf16 h1 = __float2bfloat16(v1);
                __nv_bfloat162 hh; hh.x = h0; hh.y = h1;
                __nv_bfloat162 ll;
                ll.x = __float2bfloat16(v0 - __bfloat162float(h0));
                ll.y = __float2bfloat16(v1 - __bfloat162float(h1));
                *(__nv_bfloat162*)(Chi + off) = hh;
                *(__nv_bfloat162*)(Clo + off) = ll;
            } else {
                *(__half2*)(C16 + off) = __floats2half2_rn(v0, v1);
            }
        }
    }
}

// -------- 2-term fp16 MLP GEMM: A single fp16, B fp16 hi/lo, 3-stage -------
// MODE 0: h = gelu((X W1)*is + b1) -> fp16
// MODE 1: out = (h W2)*is + b2     -> fp32
template <int MODE>
__global__ void __launch_bounds__(512, 1) gemm2h_k(
    const fp16* __restrict__ A, long lda,
    const fp16* __restrict__ Bhi, const fp16* __restrict__ Blo,
    float* __restrict__ Cf, fp16* __restrict__ C16,
    const float* __restrict__ bias, const float* __restrict__ sc)
{
    extern __shared__ char smem[];
    const uint32_t sb = smem_u32(smem);

    const int tid = threadIdx.x;
    const int wid = tid >> 5, lane = tid & 31;
    const int wr = wid >> 2, wc = wid & 3;       // 4x4 warps, 32x32 warp tiles
    const int z = blockIdx.z;
    const int row0 = blockIdx.y * 128, col0 = blockIdx.x * 128;

    const fp16* Aa = A + (size_t)z * DN + (size_t)row0 * lda;
    const fp16* Bh = Bhi + (size_t)z * MM + (size_t)col0 * DN;
    const fp16* Bl = Blo + (size_t)z * MM + (size_t)col0 * DN;
    const fp16* gbase[3] = {Aa, Bh, Bl};
    const long  gstr [3] = {lda, DN, DN};

    auto load_stage = [&](int st, int k0) {
        const uint32_t base = sb + (uint32_t)st * STG3;
        const int ch = tid & 7;
        const int rlo = tid >> 3;                 // 0..63
#pragma unroll
        for (int t = 0; t < 6; t++) {
            const int mat = t >> 1;
            const int r = ((t & 1) << 6) + rlo;   // 0..127
            cp16(base + (uint32_t)mat * MATB + (uint32_t)(r * RSEB + ch * 16),
                 gbase[mat] + (long)r * gstr[mat] + k0 + ch * 8);
        }
        CP_COMMIT();
    };

    float acc[2][4][4];
#pragma unroll
    for (int mi = 0; mi < 2; mi++)
#pragma unroll
        for (int ni = 0; ni < 4; ni++)
#pragma unroll
            for (int q = 0; q < 4; q++) acc[mi][ni][q] = 0.0f;

    load_stage(0, 0);
    load_stage(1, BK);

    const int arow = (lane & 7) + ((lane >> 3) & 1) * 8;
    const int acol = (lane >> 4) * 16;
    const int brow = (lane & 7) + ((lane >> 4) & 1) * 8;
    const int bcol = ((lane >> 3) & 1) * 16;

    for (int s = 0; s < NKS; s++) {
        if (s < NKS - 1) { CP_WAIT(1); } else { CP_WAIT(0); }
        __syncthreads();
        if (s + 2 < NKS) load_stage((s + 2) % 3, (s + 2) * BK);

        const uint32_t stb = sb + (uint32_t)(s % 3) * STG3;
        const uint32_t aB  = stb + (uint32_t)((wr * 32 + arow) * RSEB) + acol;
        const uint32_t bBh = stb + MATB + (uint32_t)((wc * 32 + brow) * RSEB) + bcol;
        const uint32_t bBl = bBh + MATB;

#pragma unroll
        for (int kk = 0; kk < 4; kk++) {
            const uint32_t ko = (uint32_t)(kk * 32);
            uint32_t ah[2][4], bh[4][2], bl[4][2];
#pragma unroll
            for (int mi = 0; mi < 2; mi++)
                LDSM4(ah[mi][0], ah[mi][1], ah[mi][2], ah[mi][3], aB + ko + (uint32_t)(mi * 16 * RSEB));
#pragma unroll
            for (int p = 0; p < 2; p++) {
                LDSM4(bh[2*p][0], bh[2*p][1], bh[2*p+1][0], bh[2*p+1][1], bBh + ko + (uint32_t)(p * 16 * RSEB));
                LDSM4(bl[2*p][0], bl[2*p][1], bl[2*p+1][0], bl[2*p+1][1], bBl + ko + (uint32_t)(p * 16 * RSEB));
            }
#pragma unroll
            for (int mi = 0; mi < 2; mi++)
#pragma unroll
                for (int ni = 0; ni < 4; ni++) MMAH16816(acc[mi][ni], ah[mi], bh[ni]);
#pragma unroll
            for (int mi = 0; mi < 2; mi++)
#pragma unroll
                for (int ni = 0; ni < 4; ni++) MMAH16816(acc[mi][ni], ah[mi], bl[ni]);
        }
        __syncthreads();
    }

    const float scl = sc[z];
    const int gID = lane >> 2, tg = lane & 3;

#pragma unroll
    for (int mi = 0; mi < 2; mi++)
#pragma unroll
        for (int ni = 0; ni < 4; ni++)
#pragma unroll
            for (int hf = 0; hf < 2; hf++) {
                const int rl = wr * 32 + mi * 16 + gID + hf * 8;
                const int cl = wc * 32 + ni * 8 + tg * 2;
                float v0 = acc[mi][ni][hf * 2 + 0] * scl + bias[z * DN + col0 + cl];
                float v1 = acc[mi][ni][hf * 2 + 1] * scl + bias[z * DN + col0 + cl + 1];
                if (MODE == 0) {
                    v0 = 0.5f * v0 * (1.0f + erff(v0 * 0.70710678118654752f));
                    v1 = 0.5f * v1 * (1.0f + erff(v1 * 0.70710678118654752f));
                }
                const size_t off = (size_t)z * DN + (size_t)(row0 + rl) * RS + col0 + cl;
                if (MODE == 0) {
                    *(__half2*)(C16 + off) = __floats2half2_rn(v0, v1);
                } else {
                    float2 f2; f2.x = v0; f2.y = v1;
                    *(float2*)(Cf + off) = f2;
                }
            }
}

// ------------- 1-term fp16 squaring GEMM, 2-stage, 2 CTAs/SM ----------------
__global__ void __launch_bounds__(256, 2) gemm1h_k(
    const fp16* __restrict__ Ph, fp16* __restrict__ Po,
    const float* __restrict__ trin)
{
    extern __shared__ char smem[];
    const uint32_t sb = smem_u32(smem);

    const int tid = threadIdx.x;
    const int wid = tid >> 5, lane = tid & 31;
    const int wr = wid >> 1, wc = wid & 1;
    const int z = blockIdx.z;

    int t = blockIdx.x, ti = 0;
    while (t >= 8 - ti) { t -= 8 - ti; ti++; }
    const int row0 = ti * 128, col0 = (ti + t) * 128;

    const fp16* Ah = Ph + (size_t)z * MM + (size_t)row0 * DN;
    const fp16* Bh = Ph + (size_t)z * MM + (size_t)col0 * DN;

    auto load_stage = [&](int st, int k0) {
        const uint32_t base = sb + (uint32_t)st * STG2;
        const int ch = tid & 7;
        const int rlo = tid >> 3;
#pragma unroll
        for (int t2 = 0; t2 < 8; t2++) {
            const int mat = t2 >> 2;
            const int r = ((t2 & 3) << 5) + rlo;
            const fp16* src = mat ? Bh : Ah;
            cp16(base + (uint32_t)mat * MATB + (uint32_t)(r * RSEB + ch * 16),
                 src + (long)r * DN + k0 + ch * 8);
        }
        CP_COMMIT();
    };

    float acc[2][8][4];
#pragma unroll
    for (int mi = 0; mi < 2; mi++)
#pragma unroll
        for (int ni = 0; ni < 8; ni++)
#pragma unroll
            for (int q = 0; q < 4; q++) acc[mi][ni][q] = 0.0f;

    load_stage(0, 0);

    const int arow = (lane & 7) + ((lane >> 3) & 1) * 8;
    const int acol = (lane >> 4) * 16;
    const int brow = (lane & 7) + ((lane >> 4) & 1) * 8;
    const int bcol = ((lane >> 3) & 1) * 16;

    for (int s = 0; s < NKS; s++) {
        CP_WAIT(0);
        __syncthreads();
        if (s + 1 < NKS) load_stage((s + 1) & 1, (s + 1) * BK);

        const uint32_t stb = sb + (uint32_t)(s & 1) * STG2;
        const uint32_t aB = stb + (uint32_t)((wr * 32 + arow) * RSEB) + acol;
        const uint32_t bB = stb + MATB + (uint32_t)((wc * 64 + brow) * RSEB) + bcol;

#pragma unroll
        for (int kk = 0; kk < 4; kk++) {
            const uint32_t ko = (uint32_t)(kk * 32);
            uint32_t ah[2][4], bh[8][2];
#pragma unroll
            for (int mi = 0; mi < 2; mi++)
                LDSM4(ah[mi][0], ah[mi][1], ah[mi][2], ah[mi][3], aB + ko + (uint32_t)(mi * 16 * RSEB));
#pragma unroll
            for (int p = 0; p < 4; p++)
                LDSM4(bh[2*p][0], bh[2*p][1], bh[2*p+1][0], bh[2*p+1][1], bB + ko + (uint32_t)(p * 16 * RSEB));
#pragma unroll
            for (int mi = 0; mi < 2; mi++)
#pragma unroll
                for (int ni = 0; ni < 8; ni++) MMAH16816(acc[mi][ni], ah[mi], bh[ni]);
        }
        __syncthreads();
    }

    const float tv = trin[z];
    const float scl = TRTGT / (tv * tv);
    const int gID = lane >> 2, tg = lane & 3;
    const bool mirror = (row0 != col0);
    float* ts = (float*)smem;

#pragma unroll
    for (int mi = 0; mi < 2; mi++)
#pragma unroll
        for (int ni = 0; ni < 8; ni++)
#pragma unroll
            for (int hf = 0; hf < 2; hf++) {
                const int rl = wr * 32 + mi * 16 + gID + hf * 8;
                const int cl = wc * 64 + ni * 8 + tg * 2;
                float v0 = acc[mi][ni][hf * 2 + 0] * scl;
                float v1 = acc[mi][ni][hf * 2 + 1] * scl;
                const size_t off = (size_t)z * MM + (size_t)(row0 + rl) * DN + col0 + cl;
                *(__half2*)(Po + off) = __floats2half2_rn(v0, v1);
                if (mirror) {
                    ts[rl * 129 + cl] = v0;
                    ts[rl * 129 + cl + 1] = v1;
                }
            }

    if (mirror) {
        __syncthreads();
#pragma unroll 4
        for (int i = 0; i < 32; i++) {
            int lin = i * 512 + tid * 2;
            int mr = lin >> 7, mc = lin & 127;
            float v0 = ts[mc * 129 + mr];
            float v1 = ts[(mc + 1) * 129 + mr];
            const size_t off = (size_t)z * MM + (size_t)(col0 + mr) * DN + row0 + mc;
            *(__half2*)(Po + off) = __floats2half2_rn(v0, v1);
        }
    }
}

// --------------------------- small kernels ----------------------------------
__global__ void __launch_bounds__(256) k_trace_f(const float* __restrict__ G,
                                                 float* __restrict__ out)
{
    const int m = blockIdx.x;
    float sum = 0.0f;
    for (int d = threadIdx.x; d < DN; d += 256)
        sum += G[(size_t)m * MM + (size_t)d * DN + d];
    __shared__ float red[256];
    red[threadIdx.x] = sum; __syncthreads();
    for (int off = 128; off > 0; off >>= 1) {
        if (threadIdx.x < off) red[threadIdx.x] += red[threadIdx.x + off];
        __syncthreads();
    }
    if (threadIdx.x == 0) out[m] = red[0];
}

__global__ void __launch_bounds__(256) k_trace_hl(const bf16* __restrict__ Ph,
                                                  const bf16* __restrict__ Pl,
                                                  float* __restrict__ out)
{
    const int m = blockIdx.x;
    float sum = 0.0f;
    for (int d = threadIdx.x; d < DN; d += 256) {
        size_t o = (size_t)m * MM + (size_t)d * DN + d;
        sum += __bfloat162float(Ph[o]) + __bfloat162float(Pl[o]);
    }
    __shared__ float red[256];
    red[threadIdx.x] = sum; __syncthreads();
    for (int off = 128; off > 0; off >>= 1) {
        if (threadIdx.x < off) red[threadIdx.x] += red[threadIdx.x + off];
        __syncthreads();
    }
    if (threadIdx.x == 0) out[m] = red[0];
}

__global__ void __launch_bounds__(256) k_trace_h16(const fp16* __restrict__ P,
                                                   float* __restrict__ out)
{
    const int m = blockIdx.x;
    float sum = 0.0f;
    for (int d = threadIdx.x; d < DN; d += 256)
        sum += __half2float(P[(size_t)m * MM + (size_t)d * DN + d]);
    __shared__ float red[256];
    red[threadIdx.x] = sum; __syncthreads();
    for (int off = 128; off > 0; off >>= 1) {
        if (threadIdx.x < off) red[threadIdx.x] += red[threadIdx.x + off];
        __syncthreads();
    }
    if (threadIdx.x == 0) out[m] = red[0];
}

__global__ void __launch_bounds__(256) k_pickcol16(const fp16* __restrict__ P,
                                                   float* __restrict__ v)
{
    const int m = blockIdx.x;
    const size_t base = (size_t)m * MM;
    __shared__ float bv[256];
    __shared__ int bi[256];
    float best = -1.0f; int bidx = 0;
    for (int d = threadIdx.x; d < DN; d += 256) {
        float val = fabsf(__half2float(P[base + (size_t)d * DN + d]));
        if (val > best) { best = val; bidx = d; }
    }
    bv[threadIdx.x] = best; bi[threadIdx.x] = bidx;
    __syncthreads();
    for (int off = 128; off > 0; off >>= 1) {
        if (threadIdx.x < off && bv[threadIdx.x + off] > bv[threadIdx.x]) {
            bv[threadIdx.x] = bv[threadIdx.x + off];
            bi[threadIdx.x] = bi[threadIdx.x + off];
        }
        __syncthreads();
    }
    const int j = bi[0];
    for (int i = threadIdx.x; i < DN; i += 256)
        v[m * DN + i] = __half2float(P[base + (size_t)j * DN + i]);
}

__global__ void __launch_bounds__(256) k_matvec(const float* __restrict__ G,
                                                const float* __restrict__ v,
                                                float* __restrict__ gv)
{
    const int m = blockIdx.y, r = blockIdx.x;
    const float* row = G + (size_t)m * MM + (size_t)r * DN;
    const float* vm = v + m * DN;
    float4 a = *(const float4*)&row[threadIdx.x * 4];
    float4 b = *(const float4*)&vm[threadIdx.x * 4];
    float sum = a.x * b.x + a.y * b.y + a.z * b.z + a.w * b.w;
    __shared__ float red[256];
    red[threadIdx.x] = sum; __syncthreads();
    for (int off = 128; off > 0; off >>= 1) {
        if (threadIdx.x < off) red[threadIdx.x] += red[threadIdx.x + off];
        __syncthreads();
    }
    if (threadIdx.x == 0) gv[m * DN + r] = red[0];
}

__global__ void __launch_bounds__(256) k_sigma(const float* __restrict__ v,
                                               const float* __restrict__ gv,
                                               float* __restrict__ is_)
{
    const int m = blockIdx.x;
    float num = 0.0f, den = 0.0f;
    for (int d = threadIdx.x; d < DN; d += 256) {
        float vv = v[m * DN + d];
        num += vv * gv[m * DN + d];
        den += vv * vv;
    }
    __shared__ float rn[256], rd[256];
    rn[threadIdx.x] = num; rd[threadIdx.x] = den; __syncthreads();
    for (int off = 128; off > 0; off >>= 1) {
        if (threadIdx.x < off) { rn[threadIdx.x] += rn[threadIdx.x + off]; rd[threadIdx.x] += rd[threadIdx.x + off]; }
        __syncthreads();
    }
    if (threadIdx.x == 0) is_[m] = sqrtf(rd[0] / rn[0]);
}

// ---------------------------------------------------------------------------
extern "C" void kernel_launch(void* const* d_in, const int* in_sizes, int n_in,
                              void* d_out, int out_size)
{
    const float* x  = (const float*)d_in[0];
    const float* w1 = (const float*)d_in[1];
    const float* b1 = (const float*)d_in[2];
    const float* w2 = (const float*)d_in[3];
    const float* b2 = (const float*)d_in[4];
    float* out = (float*)d_out;

    fp16 *x16, *w16h, *w16l, *h16;
    bf16 *wth, *wtl, *P0h, *P0l, *P1h, *P1l;
    float *G, *tr, *v, *gv, *is_;
    cudaGetSymbolAddress((void**)&x16, g_x16);
    cudaGetSymbolAddress((void**)&wth, g_wth); cudaGetSymbolAddress((void**)&wtl, g_wtl);
    cudaGetSymbolAddress((void**)&w16h, g_w16h); cudaGetSymbolAddress((void**)&w16l, g_w16l);
    cudaGetSymbolAddress((void**)&G, g_G);
    cudaGetSymbolAddress((void**)&P0h, g_P0h); cudaGetSymbolAddress((void**)&P0l, g_P0l);
    cudaGetSymbolAddress((void**)&P1h, g_P1h); cudaGetSymbolAddress((void**)&P1l, g_P1l);
    cudaGetSymbolAddress((void**)&h16, g_h16);
    cudaGetSymbolAddress((void**)&tr, g_tr);   cudaGetSymbolAddress((void**)&v, g_v);
    cudaGetSymbolAddress((void**)&gv, g_gv);   cudaGetSymbolAddress((void**)&is_, g_is);

    cudaFuncSetAttribute(gemm_k<0>, cudaFuncAttributeMaxDynamicSharedMemorySize, SMEM_BYTES);
    cudaFuncSetAttribute(gemm_k<1>, cudaFuncAttributeMaxDynamicSharedMemorySize, SMEM_BYTES);
    cudaFuncSetAttribute(gemm_k<4>, cudaFuncAttributeMaxDynamicSharedMemorySize, SMEM_BYTES);
    cudaFuncSetAttribute(gemm2h_k<0>, cudaFuncAttributeMaxDynamicSharedMemorySize, SMEM2H);
    cudaFuncSetAttribute(gemm2h_k<1>, cudaFuncAttributeMaxDynamicSharedMemorySize, SMEM2H);
    cudaFuncSetAttribute(gemm1h_k,  cudaFuncAttributeMaxDynamicSharedMemorySize, SMEM1);

    conv_x16<<<(unsigned)((size_t)BATCH * RS / 4 / 256), 256>>>(x, x16);
    conv_wT<<<dim3(32, 32, NB), 256>>>(w1, wth, wtl, w16h, w16l);
    conv_wT<<<dim3(32, 32, NB), 256>>>(w2, wth + (size_t)NB * MM, wtl + (size_t)NB * MM,
                                       w16h + (size_t)NB * MM, w16l + (size_t)NB * MM);

    // Gram: G (fp32) + P0 hi/lo, triangular grid; trace from fp32 G
    gemm_k<0><<<dim3(36, 1, NMAT), 512, SMEM_BYTES>>>(
        wth, wtl, wth, wtl, G, P0h, P0l, nullptr);
    k_trace_f<<<NMAT, 256>>>(G, tr);

    // Steps 1..3: hi/lo bf16 squarings (small-gap regime)
    bf16 *pih = P0h, *pil = P0l, *poh = P1h, *pol = P1l;
    int step = 0;
    for (int s = 0; s < NSQ_HL - 1; s++, step++) {
        gemm_k<1><<<dim3(36, 1, NMAT), 512, SMEM_BYTES>>>(
            pih, pil, pih, pil, nullptr, poh, pol, tr + step * NMAT);
        k_trace_hl<<<NMAT, 256>>>(poh, pol, tr + (step + 1) * NMAT);
        bf16* t1 = pih; pih = poh; poh = t1;
        bf16* t2 = pil; pil = pol; pol = t2;
    }
    // Step 4: hi/lo -> fp16 single output at trace TRTGT
    fp16* q0 = reinterpret_cast<fp16*>(poh == P0h ? P0h : P1h);
    {
        gemm_k<4><<<dim3(36, 1, NMAT), 512, SMEM_BYTES>>>(
            pih, pil, pih, pil, nullptr, (bf16*)q0, nullptr, tr + step * NMAT);
        step++;
        k_trace_h16<<<NMAT, 256>>>(q0, tr + step * NMAT);
    }
    // Steps 5..10: single-term fp16 squarings at trace TRTGT
    fp16* pi16 = q0;
    fp16* po16 = reinterpret_cast<fp16*>((void*)q0 == (void*)P0h ? P1h : P0h);
    for (int s = 0; s < NSQ_F16; s++, step++) {
        gemm1h_k<<<dim3(36, 1, NMAT), 256, SMEM1>>>(pi16, po16, tr + step * NMAT);
        k_trace_h16<<<NMAT, 256>>>(po16, tr + (step + 1) * NMAT);
        fp16* t1 = pi16; pi16 = po16; po16 = t1;
    }

    // Rayleigh quotient on fp32 G with v = argmax-diag column of P_final
    k_pickcol16<<<NMAT, 256>>>(pi16, v);
    k_matvec<<<dim3(DN, NMAT), 256>>>(G, v, gv);
    k_sigma<<<NMAT, 256>>>(v, gv, is_);

    // MLP: 2-term fp16
    gemm2h_k<0><<<dim3(8, 32, NB), 512, SMEM2H>>>(
        x16, RS, w16h, w16l, nullptr, h16, b1, is_);
    gemm2h_k<1><<<dim3(8, 32, NB), 512, SMEM2H>>>(
        h16, RS, w16h + (size_t)NB * MM, w16l + (size_t)NB * MM,
        out, nullptr, b2, is_ + NB);
}

// round 15
// speedup vs baseline: 1.8412x; 1.0434x over previous
#include <cuda_runtime.h>
#include <cuda_bf16.h>
#include <cuda_fp16.h>
#include <cstdint>
#include <math.h>

#define NB 25
#define BATCH 4096
#define DN 1024
#define RS (NB * DN)
#define NMAT (2 * NB)
#define MM ((size_t)DN * DN)
#define NSQ 10
#define BK 64
#define NKS (DN / BK)            // 16 k-stages
#define RSEB 144                 // smem row stride bytes (128B data + 16B pad)
#define MATB (128 * RSEB)        // 18432 B per matrix tile
#define STG4 (4 * MATB)          // 73728 B per stage (4 mats)
#define SMEM_BYTES (3 * STG4)    // 221184, 3-stage pipeline (4-mat kernels)
#define STG3 (3 * MATB)          // 55296 B per stage (3 mats)
#define SMEM3M (3 * STG3)        // 165888 (3-mat kernels, 3 stages)
#define STG2 (2 * MATB)          // 36864 B per stage (2 mats)
#define SMEM1 (2 * STG2)         // 73728 (1-term kernel, 2 stages)
#define TRTGT 256.0f             // fp16-chain trace target

typedef __nv_bfloat16 bf16;
typedef __half fp16;

// ----------------------------- scratch -------------------------------------
__device__ fp16  g_x16[(size_t)BATCH * RS];
__device__ bf16  g_wth[NMAT * MM];
__device__ bf16  g_wtl[NMAT * MM];
__device__ fp16  g_w16h[NMAT * MM];
__device__ fp16  g_w16l[NMAT * MM];
__device__ float g_G  [NMAT * MM];
__device__ bf16  g_P0h[NMAT * MM];
__device__ bf16  g_P0l[NMAT * MM];
__device__ bf16  g_P1h[NMAT * MM];
__device__ bf16  g_P1l[NMAT * MM];
__device__ fp16  g_h16[(size_t)BATCH * RS];
__device__ float g_tr [(NSQ + 1) * NMAT];
__device__ float g_v  [NMAT * DN];
__device__ float g_gv [NMAT * DN];
__device__ float g_is [NMAT];

// ----------------------------- PTX helpers ---------------------------------
__device__ __forceinline__ uint32_t smem_u32(const void* p) {
    uint32_t a;
    asm("{ .reg .u64 t; cvta.to.shared.u64 t, %1; cvt.u32.u64 %0, t; }" : "=r"(a) : "l"(p));
    return a;
}
__device__ __forceinline__ void cp16(uint32_t s, const void* g) {
    asm volatile("cp.async.cg.shared.global [%0], [%1], 16;" :: "r"(s), "l"(g));
}
#define CP_COMMIT() asm volatile("cp.async.commit_group;" ::: "memory")
#define CP_WAIT(N)  asm volatile("cp.async.wait_group %0;" :: "n"(N) : "memory")

#define LDSM4(r0, r1, r2, r3, addr) \
    asm volatile("ldmatrix.sync.aligned.m8n8.x4.shared.b16 {%0,%1,%2,%3}, [%4];" \
        : "=r"(r0), "=r"(r1), "=r"(r2), "=r"(r3) : "r"(addr))

#define MMA16816(c, a, b) \
    asm volatile("mma.sync.aligned.m16n8k16.row.col.f32.bf16.bf16.f32 " \
        "{%0,%1,%2,%3}, {%4,%5,%6,%7}, {%8,%9}, {%0,%1,%2,%3};" \
        : "+f"((c)[0]), "+f"((c)[1]), "+f"((c)[2]), "+f"((c)[3]) \
        : "r"((a)[0]), "r"((a)[1]), "r"((a)[2]), "r"((a)[3]), "r"((b)[0]), "r"((b)[1]))

#define MMAH16816(c, a, b) \
    asm volatile("mma.sync.aligned.m16n8k16.row.col.f32.f16.f16.f32 " \
        "{%0,%1,%2,%3}, {%4,%5,%6,%7}, {%8,%9}, {%0,%1,%2,%3};" \
        : "+f"((c)[0]), "+f"((c)[1]), "+f"((c)[2]), "+f"((c)[3]) \
        : "r"((a)[0]), "r"((a)[1]), "r"((a)[2]), "r"((a)[3]), "r"((b)[0]), "r"((b)[1]))

// ----------------------------- conversions ---------------------------------
__global__ void __launch_bounds__(256) conv_x16(const float* __restrict__ in,
                                                fp16* __restrict__ out)
{
    size_t i = ((size_t)blockIdx.x * 256 + threadIdx.x) * 4;
    float4 v = *(const float4*)(in + i);
    *(__half2*)(out + i)     = __floats2half2_rn(v.x, v.y);
    *(__half2*)(out + i + 2) = __floats2half2_rn(v.z, v.w);
}

__global__ void __launch_bounds__(256) conv_wT(const float* __restrict__ w,
                                               bf16* __restrict__ bhi, bf16* __restrict__ blo,
                                               fp16* __restrict__ hhi, fp16* __restrict__ hlo)
{
    const int m = blockIdx.z;
    const float* W = w + (size_t)m * MM;
    bf16* Bh = bhi + (size_t)m * MM;
    bf16* Bl = blo + (size_t)m * MM;
    fp16* Hh = hhi + (size_t)m * MM;
    fp16* Hl = hlo + (size_t)m * MM;
    __shared__ float t[32][33];
    const int r0 = blockIdx.y * 32, c0 = blockIdx.x * 32;
    const int tr = threadIdx.x >> 5, tc = threadIdx.x & 31;
#pragma unroll
    for (int i = 0; i < 4; i++)
        t[tr + 8 * i][tc] = W[(size_t)(r0 + tr + 8 * i) * DN + c0 + tc];
    __syncthreads();
#pragma unroll
    for (int i = 0; i < 4; i++) {
        int rr = tr + 8 * i;
        float v = t[tc][rr];
        size_t o = (size_t)(c0 + rr) * DN + r0 + tc;
        bf16 h = __float2bfloat16(v);
        Bh[o] = h;
        Bl[o] = __float2bfloat16(v - __bfloat162float(h));
        fp16 h6 = __float2half_rn(v);
        Hh[o] = h6;
        Hl[o] = __float2half_rn(v - __half2float(h6));
    }
}

// -------- 3-term hi/lo bf16 GEMM, triangular, 512 thr, 3-stage -------------
// MODE 0: Gram   -> Cf (fp32) + Chi/Clo (bf16)
// MODE 1: square -> Chi/Clo (bf16), scl=(1/tr)^2
// MODE 4: square -> fp16 HI/LO out, scl=TRTGT/tr^2 (transition to fp16 chain)
template <int MODE>
__global__ void __launch_bounds__(512, 1) gemm_k(
    const bf16* __restrict__ Ahi, const bf16* __restrict__ Alo,
    const bf16* __restrict__ Bhi, const bf16* __restrict__ Blo,
    float* __restrict__ Cf, bf16* __restrict__ Chi, bf16* __restrict__ Clo,
    const float* __restrict__ trin)
{
    constexpr bool OUT16 = (MODE == 4);
    extern __shared__ char smem[];
    const uint32_t sb = smem_u32(smem);

    const int tid = threadIdx.x;
    const int wid = tid >> 5, lane = tid & 31;
    const int wr = wid >> 2, wc = wid & 3;
    const int z = blockIdx.z;

    int t = blockIdx.x, ti = 0;
    while (t >= 8 - ti) { t -= 8 - ti; ti++; }
    const int row0 = ti * 128, col0 = (ti + t) * 128;

    const bf16* Ah = Ahi + (size_t)z * MM + (size_t)row0 * DN;
    const bf16* Al = Alo + (size_t)z * MM + (size_t)row0 * DN;
    const bf16* Bh = Bhi + (size_t)z * MM + (size_t)col0 * DN;
    const bf16* Bl = Blo + (size_t)z * MM + (size_t)col0 * DN;
    const bf16* gbase[4] = {Ah, Al, Bh, Bl};

    auto load_stage = [&](int st, int k0) {
        const uint32_t base = sb + (uint32_t)st * STG4;
        const int ch = tid & 7;
        const int rlo = tid >> 3;
#pragma unroll
        for (int t2 = 0; t2 < 8; t2++) {
            const int mat = t2 >> 1;
            const int r = ((t2 & 1) << 6) + rlo;
            cp16(base + (uint32_t)mat * MATB + (uint32_t)(r * RSEB + ch * 16),
                 gbase[mat] + (long)r * DN + k0 + ch * 8);
        }
        CP_COMMIT();
    };

    float acc[2][4][4];
#pragma unroll
    for (int mi = 0; mi < 2; mi++)
#pragma unroll
        for (int ni = 0; ni < 4; ni++)
#pragma unroll
            for (int q = 0; q < 4; q++) acc[mi][ni][q] = 0.0f;

    load_stage(0, 0);
    load_stage(1, BK);

    const int arow = (lane & 7) + ((lane >> 3) & 1) * 8;
    const int acol = (lane >> 4) * 16;
    const int brow = (lane & 7) + ((lane >> 4) & 1) * 8;
    const int bcol = ((lane >> 3) & 1) * 16;

    for (int s = 0; s < NKS; s++) {
        if (s < NKS - 1) { CP_WAIT(1); } else { CP_WAIT(0); }
        __syncthreads();
        if (s + 2 < NKS) load_stage((s + 2) % 3, (s + 2) * BK);

        const uint32_t stb = sb + (uint32_t)(s % 3) * STG4;
        const uint32_t aBh = stb + (uint32_t)((wr * 32 + arow) * RSEB) + acol;
        const uint32_t aBl = aBh + MATB;
        const uint32_t bBh = stb + 2u * MATB + (uint32_t)((wc * 32 + brow) * RSEB) + bcol;
        const uint32_t bBl = bBh + MATB;

#pragma unroll
        for (int kk = 0; kk < 4; kk++) {
            const uint32_t ko = (uint32_t)(kk * 32);
            uint32_t ah[2][4], al[2][4], bh[4][2], bl[4][2];
#pragma unroll
            for (int mi = 0; mi < 2; mi++) {
                LDSM4(ah[mi][0], ah[mi][1], ah[mi][2], ah[mi][3], aBh + ko + (uint32_t)(mi * 16 * RSEB));
                LDSM4(al[mi][0], al[mi][1], al[mi][2], al[mi][3], aBl + ko + (uint32_t)(mi * 16 * RSEB));
            }
#pragma unroll
            for (int p = 0; p < 2; p++) {
                LDSM4(bh[2*p][0], bh[2*p][1], bh[2*p+1][0], bh[2*p+1][1], bBh + ko + (uint32_t)(p * 16 * RSEB));
                LDSM4(bl[2*p][0], bl[2*p][1], bl[2*p+1][0], bl[2*p+1][1], bBl + ko + (uint32_t)(p * 16 * RSEB));
            }
#pragma unroll
            for (int mi = 0; mi < 2; mi++)
#pragma unroll
                for (int ni = 0; ni < 4; ni++) MMA16816(acc[mi][ni], ah[mi], bh[ni]);
#pragma unroll
            for (int mi = 0; mi < 2; mi++)
#pragma unroll
                for (int ni = 0; ni < 4; ni++) MMA16816(acc[mi][ni], ah[mi], bl[ni]);
#pragma unroll
            for (int mi = 0; mi < 2; mi++)
#pragma unroll
                for (int ni = 0; ni < 4; ni++) MMA16816(acc[mi][ni], al[mi], bh[ni]);
        }
        __syncthreads();
    }

    float scl = 1.0f;
    if (MODE == 1) { float it = 1.0f / trin[z]; scl = it * it; }
    if (MODE == 4) { float tv = trin[z]; scl = TRTGT / (tv * tv); }
    const int gID = lane >> 2, tg = lane & 3;
    const bool mirror = (row0 != col0);
    float* ts = (float*)smem;
    fp16* H16 = reinterpret_cast<fp16*>(Chi);
    fp16* L16 = reinterpret_cast<fp16*>(Clo);

#pragma unroll
    for (int mi = 0; mi < 2; mi++)
#pragma unroll
        for (int ni = 0; ni < 4; ni++)
#pragma unroll
            for (int hf = 0; hf < 2; hf++) {
                const int rl = wr * 32 + mi * 16 + gID + hf * 8;
                const int cl = wc * 32 + ni * 8 + tg * 2;
                float v0 = acc[mi][ni][hf * 2 + 0] * scl;
                float v1 = acc[mi][ni][hf * 2 + 1] * scl;
                const size_t off = (size_t)z * MM + (size_t)(row0 + rl) * DN + col0 + cl;
                if (MODE == 0) {
                    float2 f2; f2.x = v0; f2.y = v1;
                    *(float2*)(Cf + off) = f2;
                }
                if (!OUT16) {
                    bf16 h0 = __float2bfloat16(v0);
                    bf16 h1 = __float2bfloat16(v1);
                    __nv_bfloat162 hh; hh.x = h0; hh.y = h1;
                    __nv_bfloat162 ll;
                    ll.x = __float2bfloat16(v0 - __bfloat162float(h0));
                    ll.y = __float2bfloat16(v1 - __bfloat162float(h1));
                    *(__nv_bfloat162*)(Chi + off) = hh;
                    *(__nv_bfloat162*)(Clo + off) = ll;
                } else {
                    fp16 h0 = __float2half_rn(v0);
                    fp16 h1 = __float2half_rn(v1);
                    __half2 hh; hh.x = h0; hh.y = h1;
                    __half2 ll;
                    ll.x = __float2half_rn(v0 - __half2float(h0));
                    ll.y = __float2half_rn(v1 - __half2float(h1));
                    *(__half2*)(H16 + off) = hh;
                    *(__half2*)(L16 + off) = ll;
                }
                if (mirror) {
                    ts[rl * 129 + cl] = v0;
                    ts[rl * 129 + cl + 1] = v1;
                }
            }

    if (mirror) {
        __syncthreads();
#pragma unroll 4
        for (int i = 0; i < 16; i++) {
            int lin = i * 1024 + tid * 2;
            int mr = lin >> 7, mc = lin & 127;
            float v0 = ts[mc * 129 + mr];
            float v1 = ts[(mc + 1) * 129 + mr];
            const size_t off = (size_t)z * MM + (size_t)(col0 + mr) * DN + row0 + mc;
            if (MODE == 0) {
                float2 f2; f2.x = v0; f2.y = v1;
                *(float2*)(Cf + off) = f2;
            }
            if (!OUT16) {
                bf16 h0 = __float2bfloat16(v0);
                bf16 h1 = __float2bfloat16(v1);
                __nv_bfloat162 hh; hh.x = h0; hh.y = h1;
                __nv_bfloat162 ll;
                ll.x = __float2bfloat16(v0 - __bfloat162float(h0));
                ll.y = __float2bfloat16(v1 - __bfloat162float(h1));
                *(__nv_bfloat162*)(Chi + off) = hh;
                *(__nv_bfloat162*)(Clo + off) = ll;
            } else {
                fp16 h0 = __float2half_rn(v0);
                fp16 h1 = __float2half_rn(v1);
                __half2 hh; hh.x = h0; hh.y = h1;
                __half2 ll;
                ll.x = __float2half_rn(v0 - __half2float(h0));
                ll.y = __float2half_rn(v1 - __half2float(h1));
                *(__half2*)(H16 + off) = hh;
                *(__half2*)(L16 + off) = ll;
            }
        }
    }
}

// ---- 2-term fp16 squaring: A = P-hi (single), B = P-hi + P-lo (exact) -----
// Triangular + mirror; out fp16 hi/lo at trace TRTGT. 512 thr, 3-stage.
__global__ void __launch_bounds__(512, 1) gemm2hsq_k(
    const fp16* __restrict__ Phi, const fp16* __restrict__ Plo,
    fp16* __restrict__ Poh, fp16* __restrict__ Pol,
    const float* __restrict__ trin)
{
    extern __shared__ char smem[];
    const uint32_t sb = smem_u32(smem);

    const int tid = threadIdx.x;
    const int wid = tid >> 5, lane = tid & 31;
    const int wr = wid >> 2, wc = wid & 3;
    const int z = blockIdx.z;

    int t = blockIdx.x, ti = 0;
    while (t >= 8 - ti) { t -= 8 - ti; ti++; }
    const int row0 = ti * 128, col0 = (ti + t) * 128;

    const fp16* Aa = Phi + (size_t)z * MM + (size_t)row0 * DN;
    const fp16* Bh = Phi + (size_t)z * MM + (size_t)col0 * DN;
    const fp16* Bl = Plo + (size_t)z * MM + (size_t)col0 * DN;
    const fp16* gbase[3] = {Aa, Bh, Bl};

    auto load_stage = [&](int st, int k0) {
        const uint32_t base = sb + (uint32_t)st * STG3;
        const int ch = tid & 7;
        const int rlo = tid >> 3;
#pragma unroll
        for (int t2 = 0; t2 < 6; t2++) {
            const int mat = t2 >> 1;
            const int r = ((t2 & 1) << 6) + rlo;
            cp16(base + (uint32_t)mat * MATB + (uint32_t)(r * RSEB + ch * 16),
                 gbase[mat] + (long)r * DN + k0 + ch * 8);
        }
        CP_COMMIT();
    };

    float acc[2][4][4];
#pragma unroll
    for (int mi = 0; mi < 2; mi++)
#pragma unroll
        for (int ni = 0; ni < 4; ni++)
#pragma unroll
            for (int q = 0; q < 4; q++) acc[mi][ni][q] = 0.0f;

    load_stage(0, 0);
    load_stage(1, BK);

    const int arow = (lane & 7) + ((lane >> 3) & 1) * 8;
    const int acol = (lane >> 4) * 16;
    const int brow = (lane & 7) + ((lane >> 4) & 1) * 8;
    const int bcol = ((lane >> 3) & 1) * 16;

    for (int s = 0; s < NKS; s++) {
        if (s < NKS - 1) { CP_WAIT(1); } else { CP_WAIT(0); }
        __syncthreads();
        if (s + 2 < NKS) load_stage((s + 2) % 3, (s + 2) * BK);

        const uint32_t stb = sb + (uint32_t)(s % 3) * STG3;
        const uint32_t aB  = stb + (uint32_t)((wr * 32 + arow) * RSEB) + acol;
        const uint32_t bBh = stb + MATB + (uint32_t)((wc * 32 + brow) * RSEB) + bcol;
        const uint32_t bBl = bBh + MATB;

#pragma unroll
        for (int kk = 0; kk < 4; kk++) {
            const uint32_t ko = (uint32_t)(kk * 32);
            uint32_t ah[2][4], bh[4][2], bl[4][2];
#pragma unroll
            for (int mi = 0; mi < 2; mi++)
                LDSM4(ah[mi][0], ah[mi][1], ah[mi][2], ah[mi][3], aB + ko + (uint32_t)(mi * 16 * RSEB));
#pragma unroll
            for (int p = 0; p < 2; p++) {
                LDSM4(bh[2*p][0], bh[2*p][1], bh[2*p+1][0], bh[2*p+1][1], bBh + ko + (uint32_t)(p * 16 * RSEB));
                LDSM4(bl[2*p][0], bl[2*p][1], bl[2*p+1][0], bl[2*p+1][1], bBl + ko + (uint32_t)(p * 16 * RSEB));
            }
#pragma unroll
            for (int mi = 0; mi < 2; mi++)
#pragma unroll
                for (int ni = 0; ni < 4; ni++) MMAH16816(acc[mi][ni], ah[mi], bh[ni]);
#pragma unroll
            for (int mi = 0; mi < 2; mi++)
#pragma unroll
                for (int ni = 0; ni < 4; ni++) MMAH16816(acc[mi][ni], ah[mi], bl[ni]);
        }
        __syncthreads();
    }

    const float tv = trin[z];
    const float scl = TRTGT / (tv * tv);
    const int gID = lane >> 2, tg = lane & 3;
    const bool mirror = (row0 != col0);
    float* ts = (float*)smem;

#pragma unroll
    for (int mi = 0; mi < 2; mi++)
#pragma unroll
        for (int ni = 0; ni < 4; ni++)
#pragma unroll
            for (int hf = 0; hf < 2; hf++) {
                const int rl = wr * 32 + mi * 16 + gID + hf * 8;
                const int cl = wc * 32 + ni * 8 + tg * 2;
                float v0 = acc[mi][ni][hf * 2 + 0] * scl;
                float v1 = acc[mi][ni][hf * 2 + 1] * scl;
                const size_t off = (size_t)z * MM + (size_t)(row0 + rl) * DN + col0 + cl;
                fp16 h0 = __float2half_rn(v0);
                fp16 h1 = __float2half_rn(v1);
                __half2 hh; hh.x = h0; hh.y = h1;
                __half2 ll;
                ll.x = __float2half_rn(v0 - __half2float(h0));
                ll.y = __float2half_rn(v1 - __half2float(h1));
                *(__half2*)(Poh + off) = hh;
                *(__half2*)(Pol + off) = ll;
                if (mirror) {
                    ts[rl * 129 + cl] = v0;
                    ts[rl * 129 + cl + 1] = v1;
                }
            }

    if (mirror) {
        __syncthreads();
#pragma unroll 4
        for (int i = 0; i < 16; i++) {
            int lin = i * 1024 + tid * 2;
            int mr = lin >> 7, mc = lin & 127;
            float v0 = ts[mc * 129 + mr];
            float v1 = ts[(mc + 1) * 129 + mr];
            const size_t off = (size_t)z * MM + (size_t)(col0 + mr) * DN + row0 + mc;
            fp16 h0 = __float2half_rn(v0);
            fp16 h1 = __float2half_rn(v1);
            __half2 hh; hh.x = h0; hh.y = h1;
            __half2 ll;
            ll.x = __float2half_rn(v0 - __half2float(h0));
            ll.y = __float2half_rn(v1 - __half2float(h1));
            *(__half2*)(Poh + off) = hh;
            *(__half2*)(Pol + off) = ll;
        }
    }
}

// -------- 2-term fp16 MLP GEMM: A single fp16, B fp16 hi/lo, 3-stage -------
template <int MODE>
__global__ void __launch_bounds__(512, 1) gemm2h_k(
    const fp16* __restrict__ A, long lda,
    const fp16* __restrict__ Bhi, const fp16* __restrict__ Blo,
    float* __restrict__ Cf, fp16* __restrict__ C16,
    const float* __restrict__ bias, const float* __restrict__ sc)
{
    extern __shared__ char smem[];
    const uint32_t sb = smem_u32(smem);

    const int tid = threadIdx.x;
    const int wid = tid >> 5, lane = tid & 31;
    const int wr = wid >> 2, wc = wid & 3;
    const int z = blockIdx.z;
    const int row0 = blockIdx.y * 128, col0 = blockIdx.x * 128;

    const fp16* Aa = A + (size_t)z * DN + (size_t)row0 * lda;
    const fp16* Bh = Bhi + (size_t)z * MM + (size_t)col0 * DN;
    const fp16* Bl = Blo + (size_t)z * MM + (size_t)col0 * DN;
    const fp16* gbase[3] = {Aa, Bh, Bl};
    const long  gstr [3] = {lda, DN, DN};

    auto load_stage = [&](int st, int k0) {
        const uint32_t base = sb + (uint32_t)st * STG3;
        const int ch = tid & 7;
        const int rlo = tid >> 3;
#pragma unroll
        for (int t = 0; t < 6; t++) {
            const int mat = t >> 1;
            const int r = ((t & 1) << 6) + rlo;
            cp16(base + (uint32_t)mat * MATB + (uint32_t)(r * RSEB + ch * 16),
                 gbase[mat] + (long)r * gstr[mat] + k0 + ch * 8);
        }
        CP_COMMIT();
    };

    float acc[2][4][4];
#pragma unroll
    for (int mi = 0; mi < 2; mi++)
#pragma unroll
        for (int ni = 0; ni < 4; ni++)
#pragma unroll
            for (int q = 0; q < 4; q++) acc[mi][ni][q] = 0.0f;

    load_stage(0, 0);
    load_stage(1, BK);

    const int arow = (lane & 7) + ((lane >> 3) & 1) * 8;
    const int acol = (lane >> 4) * 16;
    const int brow = (lane & 7) + ((lane >> 4) & 1) * 8;
    const int bcol = ((lane >> 3) & 1) * 16;

    for (int s = 0; s < NKS; s++) {
        if (s < NKS - 1) { CP_WAIT(1); } else { CP_WAIT(0); }
        __syncthreads();
        if (s + 2 < NKS) load_stage((s + 2) % 3, (s + 2) * BK);

        const uint32_t stb = sb + (uint32_t)(s % 3) * STG3;
        const uint32_t aB  = stb + (uint32_t)((wr * 32 + arow) * RSEB) + acol;
        const uint32_t bBh = stb + MATB + (uint32_t)((wc * 32 + brow) * RSEB) + bcol;
        const uint32_t bBl = bBh + MATB;

#pragma unroll
        for (int kk = 0; kk < 4; kk++) {
            const uint32_t ko = (uint32_t)(kk * 32);
            uint32_t ah[2][4], bh[4][2], bl[4][2];
#pragma unroll
            for (int mi = 0; mi < 2; mi++)
                LDSM4(ah[mi][0], ah[mi][1], ah[mi][2], ah[mi][3], aB + ko + (uint32_t)(mi * 16 * RSEB));
#pragma unroll
            for (int p = 0; p < 2; p++) {
                LDSM4(bh[2*p][0], bh[2*p][1], bh[2*p+1][0], bh[2*p+1][1], bBh + ko + (uint32_t)(p * 16 * RSEB));
                LDSM4(bl[2*p][0], bl[2*p][1], bl[2*p+1][0], bl[2*p+1][1], bBl + ko + (uint32_t)(p * 16 * RSEB));
            }
#pragma unroll
            for (int mi = 0; mi < 2; mi++)
#pragma unroll
                for (int ni = 0; ni < 4; ni++) MMAH16816(acc[mi][ni], ah[mi], bh[ni]);
#pragma unroll
            for (int mi = 0; mi < 2; mi++)
#pragma unroll
                for (int ni = 0; ni < 4; ni++) MMAH16816(acc[mi][ni], ah[mi], bl[ni]);
        }
        __syncthreads();
    }

    const float scl = sc[z];
    const int gID = lane >> 2, tg = lane & 3;

#pragma unroll
    for (int mi = 0; mi < 2; mi++)
#pragma unroll
        for (int ni = 0; ni < 4; ni++)
#pragma unroll
            for (int hf = 0; hf < 2; hf++) {
                const int rl = wr * 32 + mi * 16 + gID + hf * 8;
                const int cl = wc * 32 + ni * 8 + tg * 2;
                float v0 = acc[mi][ni][hf * 2 + 0] * scl + bias[z * DN + col0 + cl];
                float v1 = acc[mi][ni][hf * 2 + 1] * scl + bias[z * DN + col0 + cl + 1];
                if (MODE == 0) {
                    v0 = 0.5f * v0 * (1.0f + erff(v0 * 0.70710678118654752f));
                    v1 = 0.5f * v1 * (1.0f + erff(v1 * 0.70710678118654752f));
                }
                const size_t off = (size_t)z * DN + (size_t)(row0 + rl) * RS + col0 + cl;
                if (MODE == 0) {
                    *(__half2*)(C16 + off) = __floats2half2_rn(v0, v1);
                } else {
                    float2 f2; f2.x = v0; f2.y = v1;
                    *(float2*)(Cf + off) = f2;
                }
            }
}

// ------------- 1-term fp16 squaring GEMM, 2-stage, 2 CTAs/SM ----------------
__global__ void __launch_bounds__(256, 2) gemm1h_k(
    const fp16* __restrict__ Ph, fp16* __restrict__ Po,
    const float* __restrict__ trin)
{
    extern __shared__ char smem[];
    const uint32_t sb = smem_u32(smem);

    const int tid = threadIdx.x;
    const int wid = tid >> 5, lane = tid & 31;
    const int wr = wid >> 1, wc = wid & 1;
    const int z = blockIdx.z;

    int t = blockIdx.x, ti = 0;
    while (t >= 8 - ti) { t -= 8 - ti; ti++; }
    const int row0 = ti * 128, col0 = (ti + t) * 128;

    const fp16* Ah = Ph + (size_t)z * MM + (size_t)row0 * DN;
    const fp16* Bh = Ph + (size_t)z * MM + (size_t)col0 * DN;

    auto load_stage = [&](int st, int k0) {
        const uint32_t base = sb + (uint32_t)st * STG2;
        const int ch = tid & 7;
        const int rlo = tid >> 3;
#pragma unroll
        for (int t2 = 0; t2 < 8; t2++) {
            const int mat = t2 >> 2;
            const int r = ((t2 & 3) << 5) + rlo;
            const fp16* src = mat ? Bh : Ah;
            cp16(base + (uint32_t)mat * MATB + (uint32_t)(r * RSEB + ch * 16),
                 src + (long)r * DN + k0 + ch * 8);
        }
        CP_COMMIT();
    };

    float acc[2][8][4];
#pragma unroll
    for (int mi = 0; mi < 2; mi++)
#pragma unroll
        for (int ni = 0; ni < 8; ni++)
#pragma unroll
            for (int q = 0; q < 4; q++) acc[mi][ni][q] = 0.0f;

    load_stage(0, 0);

    const int arow = (lane & 7) + ((lane >> 3) & 1) * 8;
    const int acol = (lane >> 4) * 16;
    const int brow = (lane & 7) + ((lane >> 4) & 1) * 8;
    const int bcol = ((lane >> 3) & 1) * 16;

    for (int s = 0; s < NKS; s++) {
        CP_WAIT(0);
        __syncthreads();
        if (s + 1 < NKS) load_stage((s + 1) & 1, (s + 1) * BK);

        const uint32_t stb = sb + (uint32_t)(s & 1) * STG2;
        const uint32_t aB = stb + (uint32_t)((wr * 32 + arow) * RSEB) + acol;
        const uint32_t bB = stb + MATB + (uint32_t)((wc * 64 + brow) * RSEB) + bcol;

#pragma unroll
        for (int kk = 0; kk < 4; kk++) {
            const uint32_t ko = (uint32_t)(kk * 32);
            uint32_t ah[2][4], bh[8][2];
#pragma unroll
            for (int mi = 0; mi < 2; mi++)
                LDSM4(ah[mi][0], ah[mi][1], ah[mi][2], ah[mi][3], aB + ko + (uint32_t)(mi * 16 * RSEB));
#pragma unroll
            for (int p = 0; p < 4; p++)
                LDSM4(bh[2*p][0], bh[2*p][1], bh[2*p+1][0], bh[2*p+1][1], bB + ko + (uint32_t)(p * 16 * RSEB));
#pragma unroll
            for (int mi = 0; mi < 2; mi++)
#pragma unroll
                for (int ni = 0; ni < 8; ni++) MMAH16816(acc[mi][ni], ah[mi], bh[ni]);
        }
        __syncthreads();
    }

    const float tv = trin[z];
    const float scl = TRTGT / (tv * tv);
    const int gID = lane >> 2, tg = lane & 3;
    const bool mirror = (row0 != col0);
    float* ts = (float*)smem;

#pragma unroll
    for (int mi = 0; mi < 2; mi++)
#pragma unroll
        for (int ni = 0; ni < 8; ni++)
#pragma unroll
            for (int hf = 0; hf < 2; hf++) {
                const int rl = wr * 32 + mi * 16 + gID + hf * 8;
                const int cl = wc * 64 + ni * 8 + tg * 2;
                float v0 = acc[mi][ni][hf * 2 + 0] * scl;
                float v1 = acc[mi][ni][hf * 2 + 1] * scl;
                const size_t off = (size_t)z * MM + (size_t)(row0 + rl) * DN + col0 + cl;
                *(__half2*)(Po + off) = __floats2half2_rn(v0, v1);
                if (mirror) {
                    ts[rl * 129 + cl] = v0;
                    ts[rl * 129 + cl + 1] = v1;
                }
            }

    if (mirror) {
        __syncthreads();
#pragma unroll 4
        for (int i = 0; i < 32; i++) {
            int lin = i * 512 + tid * 2;
            int mr = lin >> 7, mc = lin & 127;
            float v0 = ts[mc * 129 + mr];
            float v1 = ts[(mc + 1) * 129 + mr];
            const size_t off = (size_t)z * MM + (size_t)(col0 + mr) * DN + row0 + mc;
            *(__half2*)(Po + off) = __floats2half2_rn(v0, v1);
        }
    }
}

// --------------------------- small kernels ----------------------------------
__global__ void __launch_bounds__(256) k_trace_f(const float* __restrict__ G,
                                                 float* __restrict__ out)
{
    const int m = blockIdx.x;
    float sum = 0.0f;
    for (int d = threadIdx.x; d < DN; d += 256)
        sum += G[(size_t)m * MM + (size_t)d * DN + d];
    __shared__ float red[256];
    red[threadIdx.x] = sum; __syncthreads();
    for (int off = 128; off > 0; off >>= 1) {
        if (threadIdx.x < off) red[threadIdx.x] += red[threadIdx.x + off];
        __syncthreads();
    }
    if (threadIdx.x == 0) out[m] = red[0];
}

__global__ void __launch_bounds__(256) k_trace_hl(const bf16* __restrict__ Ph,
                                                  const bf16* __restrict__ Pl,
                                                  float* __restrict__ out)
{
    const int m = blockIdx.x;
    float sum = 0.0f;
    for (int d = threadIdx.x; d < DN; d += 256) {
        size_t o = (size_t)m * MM + (size_t)d * DN + d;
        sum += __bfloat162float(Ph[o]) + __bfloat162float(Pl[o]);
    }
    __shared__ float red[256];
    red[threadIdx.x] = sum; __syncthreads();
    for (int off = 128; off > 0; off >>= 1) {
        if (threadIdx.x < off) red[threadIdx.x] += red[threadIdx.x + off];
        __syncthreads();
    }
    if (threadIdx.x == 0) out[m] = red[0];
}

// trace of fp16 P (+ optional lo part)
__global__ void __launch_bounds__(256) k_trace_h16(const fp16* __restrict__ P,
                                                   const fp16* __restrict__ Pl,
                                                   float* __restrict__ out)
{
    const int m = blockIdx.x;
    float sum = 0.0f;
    for (int d = threadIdx.x; d < DN; d += 256) {
        size_t o = (size_t)m * MM + (size_t)d * DN + d;
        sum += __half2float(P[o]);
        if (Pl) sum += __half2float(Pl[o]);
    }
    __shared__ float red[256];
    red[threadIdx.x] = sum; __syncthreads();
    for (int off = 128; off > 0; off >>= 1) {
        if (threadIdx.x < off) red[threadIdx.x] += red[threadIdx.x + off];
        __syncthreads();
    }
    if (threadIdx.x == 0) out[m] = red[0];
}

__global__ void __launch_bounds__(256) k_pickcol16(const fp16* __restrict__ P,
                                                   float* __restrict__ v)
{
    const int m = blockIdx.x;
    const size_t base = (size_t)m * MM;
    __shared__ float bv[256];
    __shared__ int bi[256];
    float best = -1.0f; int bidx = 0;
    for (int d = threadIdx.x; d < DN; d += 256) {
        float val = fabsf(__half2float(P[base + (size_t)d * DN + d]));
        if (val > best) { best = val; bidx = d; }
    }
    bv[threadIdx.x] = best; bi[threadIdx.x] = bidx;
    __syncthreads();
    for (int off = 128; off > 0; off >>= 1) {
        if (threadIdx.x < off && bv[threadIdx.x + off] > bv[threadIdx.x]) {
            bv[threadIdx.x] = bv[threadIdx.x + off];
            bi[threadIdx.x] = bi[threadIdx.x + off];
        }
        __syncthreads();
    }
    const int j = bi[0];
    for (int i = threadIdx.x; i < DN; i += 256)
        v[m * DN + i] = __half2float(P[base + (size_t)j * DN + i]);
}

__global__ void __launch_bounds__(256) k_matvec(const float* __restrict__ G,
                                                const float* __restrict__ v,
                                                float* __restrict__ gv)
{
    const int m = blockIdx.y, r = blockIdx.x;
    const float* row = G + (size_t)m * MM + (size_t)r * DN;
    const float* vm = v + m * DN;
    float4 a = *(const float4*)&row[threadIdx.x * 4];
    float4 b = *(const float4*)&vm[threadIdx.x * 4];
    float sum = a.x * b.x + a.y * b.y + a.z * b.z + a.w * b.w;
    __shared__ float red[256];
    red[threadIdx.x] = sum; __syncthreads();
    for (int off = 128; off > 0; off >>= 1) {
        if (threadIdx.x < off) red[threadIdx.x] += red[threadIdx.x + off];
        __syncthreads();
    }
    if (threadIdx.x == 0) gv[m * DN + r] = red[0];
}

__global__ void __launch_bounds__(256) k_sigma(const float* __restrict__ v,
                                               const float* __restrict__ gv,
                                               float* __restrict__ is_)
{
    const int m = blockIdx.x;
    float num = 0.0f, den = 0.0f;
    for (int d = threadIdx.x; d < DN; d += 256) {
        float vv = v[m * DN + d];
        num += vv * gv[m * DN + d];
        den += vv * vv;
    }
    __shared__ float rn[256], rd[256];
    rn[threadIdx.x] = num; rd[threadIdx.x] = den; __syncthreads();
    for (int off = 128; off > 0; off >>= 1) {
        if (threadIdx.x < off) { rn[threadIdx.x] += rn[threadIdx.x + off]; rd[threadIdx.x] += rd[threadIdx.x + off]; }
        __syncthreads();
    }
    if (threadIdx.x == 0) is_[m] = sqrtf(rd[0] / rn[0]);
}

// ---------------------------------------------------------------------------
extern "C" void kernel_launch(void* const* d_in, const int* in_sizes, int n_in,
                              void* d_out, int out_size)
{
    const float* x  = (const float*)d_in[0];
    const float* w1 = (const float*)d_in[1];
    const float* b1 = (const float*)d_in[2];
    const float* w2 = (const float*)d_in[3];
    const float* b2 = (const float*)d_in[4];
    float* out = (float*)d_out;

    fp16 *x16, *w16h, *w16l, *h16;
    bf16 *wth, *wtl, *P0h, *P0l, *P1h, *P1l;
    float *G, *tr, *v, *gv, *is_;
    cudaGetSymbolAddress((void**)&x16, g_x16);
    cudaGetSymbolAddress((void**)&wth, g_wth); cudaGetSymbolAddress((void**)&wtl, g_wtl);
    cudaGetSymbolAddress((void**)&w16h, g_w16h); cudaGetSymbolAddress((void**)&w16l, g_w16l);
    cudaGetSymbolAddress((void**)&G, g_G);
    cudaGetSymbolAddress((void**)&P0h, g_P0h); cudaGetSymbolAddress((void**)&P0l, g_P0l);
    cudaGetSymbolAddress((void**)&P1h, g_P1h); cudaGetSymbolAddress((void**)&P1l, g_P1l);
    cudaGetSymbolAddress((void**)&h16, g_h16);
    cudaGetSymbolAddress((void**)&tr, g_tr);   cudaGetSymbolAddress((void**)&v, g_v);
    cudaGetSymbolAddress((void**)&gv, g_gv);   cudaGetSymbolAddress((void**)&is_, g_is);

    cudaFuncSetAttribute(gemm_k<0>, cudaFuncAttributeMaxDynamicSharedMemorySize, SMEM_BYTES);
    cudaFuncSetAttribute(gemm_k<1>, cudaFuncAttributeMaxDynamicSharedMemorySize, SMEM_BYTES);
    cudaFuncSetAttribute(gemm_k<4>, cudaFuncAttributeMaxDynamicSharedMemorySize, SMEM_BYTES);
    cudaFuncSetAttribute(gemm2hsq_k, cudaFuncAttributeMaxDynamicSharedMemorySize, SMEM3M);
    cudaFuncSetAttribute(gemm2h_k<0>, cudaFuncAttributeMaxDynamicSharedMemorySize, SMEM3M);
    cudaFuncSetAttribute(gemm2h_k<1>, cudaFuncAttributeMaxDynamicSharedMemorySize, SMEM3M);
    cudaFuncSetAttribute(gemm1h_k,  cudaFuncAttributeMaxDynamicSharedMemorySize, SMEM1);

    conv_x16<<<(unsigned)((size_t)BATCH * RS / 4 / 256), 256>>>(x, x16);
    conv_wT<<<dim3(32, 32, NB), 256>>>(w1, wth, wtl, w16h, w16l);
    conv_wT<<<dim3(32, 32, NB), 256>>>(w2, wth + (size_t)NB * MM, wtl + (size_t)NB * MM,
                                       w16h + (size_t)NB * MM, w16l + (size_t)NB * MM);

    // Gram: G (fp32) + P0 (bf16 hi/lo); trace from fp32 G
    gemm_k<0><<<dim3(36, 1, NMAT), 512, SMEM_BYTES>>>(
        wth, wtl, wth, wtl, G, P0h, P0l, nullptr);
    k_trace_f<<<NMAT, 256>>>(G, tr);

    int step = 0;
    // Step 1: 3-term bf16 hi/lo squaring  P0 -> P1 (bf16)
    gemm_k<1><<<dim3(36, 1, NMAT), 512, SMEM_BYTES>>>(
        P0h, P0l, P0h, P0l, nullptr, P1h, P1l, tr + step * NMAT);
    step++;
    k_trace_hl<<<NMAT, 256>>>(P1h, P1l, tr + step * NMAT);

    // Step 2: 3-term bf16 compute, fp16 hi/lo out at trace TRTGT  P1 -> Q0(P0)
    fp16* Q0h = reinterpret_cast<fp16*>(P0h);
    fp16* Q0l = reinterpret_cast<fp16*>(P0l);
    fp16* Q1h = reinterpret_cast<fp16*>(P1h);
    fp16* Q1l = reinterpret_cast<fp16*>(P1l);
    gemm_k<4><<<dim3(36, 1, NMAT), 512, SMEM_BYTES>>>(
        P1h, P1l, P1h, P1l, nullptr, (bf16*)Q0h, (bf16*)Q0l, tr + step * NMAT);
    step++;
    k_trace_h16<<<NMAT, 256>>>(Q0h, Q0l, tr + step * NMAT);

    // Steps 3-4: 2-term fp16 squarings (hi/lo out)  Q0 -> Q1 -> Q0
    gemm2hsq_k<<<dim3(36, 1, NMAT), 512, SMEM3M>>>(Q0h, Q0l, Q1h, Q1l, tr + step * NMAT);
    step++;
    k_trace_h16<<<NMAT, 256>>>(Q1h, Q1l, tr + step * NMAT);
    gemm2hsq_k<<<dim3(36, 1, NMAT), 512, SMEM3M>>>(Q1h, Q1l, Q0h, Q0l, tr + step * NMAT);
    step++;
    k_trace_h16<<<NMAT, 256>>>(Q0h, Q0l, tr + step * NMAT);

    // Steps 5-10: 1-term fp16 squarings (hi buffers only)
    fp16* pi16 = Q0h;
    fp16* po16 = Q1h;
    for (int s = 0; s < 6; s++, step++) {
        gemm1h_k<<<dim3(36, 1, NMAT), 256, SMEM1>>>(pi16, po16, tr + step * NMAT);
        k_trace_h16<<<NMAT, 256>>>(po16, nullptr, tr + (step + 1) * NMAT);
        fp16* t1 = pi16; pi16 = po16; po16 = t1;
    }

    // Rayleigh quotient on fp32 G with v = argmax-diag column of P_final
    k_pickcol16<<<NMAT, 256>>>(pi16, v);
    k_matvec<<<dim3(DN, NMAT), 256>>>(G, v, gv);
    k_sigma<<<NMAT, 256>>>(v, gv, is_);

    // MLP: 2-term fp16
    gemm2h_k<0><<<dim3(8, 32, NB), 512, SMEM3M>>>(
        x16, RS, w16h, w16l, nullptr, h16, b1, is_);
    gemm2h_k<1><<<dim3(8, 32, NB), 512, SMEM3M>>>(
        h16, RS, w16h + (size_t)NB * MM, w16l + (size_t)NB * MM,
        out, nullptr, b2, is_ + NB);
}

// round 16
// speedup vs baseline: 2.4818x; 1.3479x over previous
#include <cuda_runtime.h>
#include <cuda_bf16.h>
#include <cuda_fp16.h>
#include <cstdint>
#include <math.h>

#define NB 25
#define BATCH 4096
#define DN 1024
#define RS (NB * DN)
#define NMAT (2 * NB)
#define MM ((size_t)DN * DN)
#define NSQ 10
#define BK 64
#define NKS (DN / BK)            // 16 k-stages
#define RSEB 144                 // smem row stride bytes (128B data + 16B pad)
#define MATB (128 * RSEB)        // 18432 B per matrix tile
#define STG4 (4 * MATB)          // 73728 B per stage (4 mats)
#define SMEM_BYTES (3 * STG4)    // 221184, 3-stage pipeline (4-mat kernels)
#define STG3 (3 * MATB)          // 55296 B per stage (3 mats)
#define SMEM3M (3 * STG3)        // 165888 (3-mat kernels, 3 stages)
#define STG2 (2 * MATB)          // 36864 B per stage (2 mats)
#define SMEM1 (2 * STG2)         // 73728 (2-mat kernels, 2 stages)
#define TRTGT 256.0f             // fp16-chain trace target

typedef __nv_bfloat16 bf16;
typedef __half fp16;

// ----------------------------- scratch -------------------------------------
__device__ fp16  g_x16[(size_t)BATCH * RS];
__device__ bf16  g_wth[NMAT * MM];
__device__ bf16  g_wtl[NMAT * MM];
__device__ fp16  g_w16h[NMAT * MM];
__device__ float g_G  [NMAT * MM];
__device__ bf16  g_P0h[NMAT * MM];
__device__ bf16  g_P0l[NMAT * MM];
__device__ bf16  g_P1h[NMAT * MM];
__device__ bf16  g_P1l[NMAT * MM];
__device__ fp16  g_h16[(size_t)BATCH * RS];
__device__ float g_tr [(NSQ + 1) * NMAT];
__device__ float g_v  [NMAT * DN];
__device__ float g_gv [NMAT * DN];
__device__ float g_is [NMAT];

// ----------------------------- PTX helpers ---------------------------------
__device__ __forceinline__ uint32_t smem_u32(const void* p) {
    uint32_t a;
    asm("{ .reg .u64 t; cvta.to.shared.u64 t, %1; cvt.u32.u64 %0, t; }" : "=r"(a) : "l"(p));
    return a;
}
__device__ __forceinline__ void cp16(uint32_t s, const void* g) {
    asm volatile("cp.async.cg.shared.global [%0], [%1], 16;" :: "r"(s), "l"(g));
}
#define CP_COMMIT() asm volatile("cp.async.commit_group;" ::: "memory")
#define CP_WAIT(N)  asm volatile("cp.async.wait_group %0;" :: "n"(N) : "memory")

#define LDSM4(r0, r1, r2, r3, addr) \
    asm volatile("ldmatrix.sync.aligned.m8n8.x4.shared.b16 {%0,%1,%2,%3}, [%4];" \
        : "=r"(r0), "=r"(r1), "=r"(r2), "=r"(r3) : "r"(addr))

#define MMA16816(c, a, b) \
    asm volatile("mma.sync.aligned.m16n8k16.row.col.f32.bf16.bf16.f32 " \
        "{%0,%1,%2,%3}, {%4,%5,%6,%7}, {%8,%9}, {%0,%1,%2,%3};" \
        : "+f"((c)[0]), "+f"((c)[1]), "+f"((c)[2]), "+f"((c)[3]) \
        : "r"((a)[0]), "r"((a)[1]), "r"((a)[2]), "r"((a)[3]), "r"((b)[0]), "r"((b)[1]))

#define MMAH16816(c, a, b) \
    asm volatile("mma.sync.aligned.m16n8k16.row.col.f32.f16.f16.f32 " \
        "{%0,%1,%2,%3}, {%4,%5,%6,%7}, {%8,%9}, {%0,%1,%2,%3};" \
        : "+f"((c)[0]), "+f"((c)[1]), "+f"((c)[2]), "+f"((c)[3]) \
        : "r"((a)[0]), "r"((a)[1]), "r"((a)[2]), "r"((a)[3]), "r"((b)[0]), "r"((b)[1]))

// ----------------------------- conversions ---------------------------------
__global__ void __launch_bounds__(256) conv_x16(const float* __restrict__ in,
                                                fp16* __restrict__ out)
{
    size_t i = ((size_t)blockIdx.x * 256 + threadIdx.x) * 4;
    float4 v = *(const float4*)(in + i);
    *(__half2*)(out + i)     = __floats2half2_rn(v.x, v.y);
    *(__half2*)(out + i + 2) = __floats2half2_rn(v.z, v.w);
}

__global__ void __launch_bounds__(256) conv_wT(const float* __restrict__ w,
                                               bf16* __restrict__ bhi, bf16* __restrict__ blo,
                                               fp16* __restrict__ hhi)
{
    const int m = blockIdx.z;
    const float* W = w + (size_t)m * MM;
    bf16* Bh = bhi + (size_t)m * MM;
    bf16* Bl = blo + (size_t)m * MM;
    fp16* Hh = hhi + (size_t)m * MM;
    __shared__ float t[32][33];
    const int r0 = blockIdx.y * 32, c0 = blockIdx.x * 32;
    const int tr = threadIdx.x >> 5, tc = threadIdx.x & 31;
#pragma unroll
    for (int i = 0; i < 4; i++)
        t[tr + 8 * i][tc] = W[(size_t)(r0 + tr + 8 * i) * DN + c0 + tc];
    __syncthreads();
#pragma unroll
    for (int i = 0; i < 4; i++) {
        int rr = tr + 8 * i;
        float v = t[tc][rr];
        size_t o = (size_t)(c0 + rr) * DN + r0 + tc;
        bf16 h = __float2bfloat16(v);
        Bh[o] = h;
        Bl[o] = __float2bfloat16(v - __bfloat162float(h));
        Hh[o] = __float2half_rn(v);
    }
}

// -------- 3-term hi/lo bf16 GEMM, triangular, 512 thr, 3-stage -------------
// MODE 0: Gram   -> Cf (fp32) + Chi/Clo (bf16)
// MODE 4: square -> fp16 HI/LO out, scl=TRTGT/tr^2 (transition to fp16 chain)
template <int MODE>
__global__ void __launch_bounds__(512, 1) gemm_k(
    const bf16* __restrict__ Ahi, const bf16* __restrict__ Alo,
    const bf16* __restrict__ Bhi, const bf16* __restrict__ Blo,
    float* __restrict__ Cf, bf16* __restrict__ Chi, bf16* __restrict__ Clo,
    const float* __restrict__ trin)
{
    constexpr bool OUT16 = (MODE == 4);
    extern __shared__ char smem[];
    const uint32_t sb = smem_u32(smem);

    const int tid = threadIdx.x;
    const int wid = tid >> 5, lane = tid & 31;
    const int wr = wid >> 2, wc = wid & 3;
    const int z = blockIdx.z;

    int t = blockIdx.x, ti = 0;
    while (t >= 8 - ti) { t -= 8 - ti; ti++; }
    const int row0 = ti * 128, col0 = (ti + t) * 128;

    const bf16* Ah = Ahi + (size_t)z * MM + (size_t)row0 * DN;
    const bf16* Al = Alo + (size_t)z * MM + (size_t)row0 * DN;
    const bf16* Bh = Bhi + (size_t)z * MM + (size_t)col0 * DN;
    const bf16* Bl = Blo + (size_t)z * MM + (size_t)col0 * DN;
    const bf16* gbase[4] = {Ah, Al, Bh, Bl};

    auto load_stage = [&](int st, int k0) {
        const uint32_t base = sb + (uint32_t)st * STG4;
        const int ch = tid & 7;
        const int rlo = tid >> 3;
#pragma unroll
        for (int t2 = 0; t2 < 8; t2++) {
            const int mat = t2 >> 1;
            const int r = ((t2 & 1) << 6) + rlo;
            cp16(base + (uint32_t)mat * MATB + (uint32_t)(r * RSEB + ch * 16),
                 gbase[mat] + (long)r * DN + k0 + ch * 8);
        }
        CP_COMMIT();
    };

    float acc[2][4][4];
#pragma unroll
    for (int mi = 0; mi < 2; mi++)
#pragma unroll
        for (int ni = 0; ni < 4; ni++)
#pragma unroll
            for (int q = 0; q < 4; q++) acc[mi][ni][q] = 0.0f;

    load_stage(0, 0);
    load_stage(1, BK);

    const int arow = (lane & 7) + ((lane >> 3) & 1) * 8;
    const int acol = (lane >> 4) * 16;
    const int brow = (lane & 7) + ((lane >> 4) & 1) * 8;
    const int bcol = ((lane >> 3) & 1) * 16;

    for (int s = 0; s < NKS; s++) {
        if (s < NKS - 1) { CP_WAIT(1); } else { CP_WAIT(0); }
        __syncthreads();
        if (s + 2 < NKS) load_stage((s + 2) % 3, (s + 2) * BK);

        const uint32_t stb = sb + (uint32_t)(s % 3) * STG4;
        const uint32_t aBh = stb + (uint32_t)((wr * 32 + arow) * RSEB) + acol;
        const uint32_t aBl = aBh + MATB;
        const uint32_t bBh = stb + 2u * MATB + (uint32_t)((wc * 32 + brow) * RSEB) + bcol;
        const uint32_t bBl = bBh + MATB;

#pragma unroll
        for (int kk = 0; kk < 4; kk++) {
            const uint32_t ko = (uint32_t)(kk * 32);
            uint32_t ah[2][4], al[2][4], bh[4][2], bl[4][2];
#pragma unroll
            for (int mi = 0; mi < 2; mi++) {
                LDSM4(ah[mi][0], ah[mi][1], ah[mi][2], ah[mi][3], aBh + ko + (uint32_t)(mi * 16 * RSEB));
                LDSM4(al[mi][0], al[mi][1], al[mi][2], al[mi][3], aBl + ko + (uint32_t)(mi * 16 * RSEB));
            }
#pragma unroll
            for (int p = 0; p < 2; p++) {
                LDSM4(bh[2*p][0], bh[2*p][1], bh[2*p+1][0], bh[2*p+1][1], bBh + ko + (uint32_t)(p * 16 * RSEB));
                LDSM4(bl[2*p][0], bl[2*p][1], bl[2*p+1][0], bl[2*p+1][1], bBl + ko + (uint32_t)(p * 16 * RSEB));
            }
#pragma unroll
            for (int mi = 0; mi < 2; mi++)
#pragma unroll
                for (int ni = 0; ni < 4; ni++) MMA16816(acc[mi][ni], ah[mi], bh[ni]);
#pragma unroll
            for (int mi = 0; mi < 2; mi++)
#pragma unroll
                for (int ni = 0; ni < 4; ni++) MMA16816(acc[mi][ni], ah[mi], bl[ni]);
#pragma unroll
            for (int mi = 0; mi < 2; mi++)
#pragma unroll
                for (int ni = 0; ni < 4; ni++) MMA16816(acc[mi][ni], al[mi], bh[ni]);
        }
        __syncthreads();
    }

    float scl = 1.0f;
    if (MODE == 4) { float tv = trin[z]; scl = TRTGT / (tv * tv); }
    const int gID = lane >> 2, tg = lane & 3;
    const bool mirror = (row0 != col0);
    float* ts = (float*)smem;
    fp16* H16 = reinterpret_cast<fp16*>(Chi);
    fp16* L16 = reinterpret_cast<fp16*>(Clo);

#pragma unroll
    for (int mi = 0; mi < 2; mi++)
#pragma unroll
        for (int ni = 0; ni < 4; ni++)
#pragma unroll
            for (int hf = 0; hf < 2; hf++) {
                const int rl = wr * 32 + mi * 16 + gID + hf * 8;
                const int cl = wc * 32 + ni * 8 + tg * 2;
                float v0 = acc[mi][ni][hf * 2 + 0] * scl;
                float v1 = acc[mi][ni][hf * 2 + 1] * scl;
                const size_t off = (size_t)z * MM + (size_t)(row0 + rl) * DN + col0 + cl;
                if (MODE == 0) {
                    float2 f2; f2.x = v0; f2.y = v1;
                    *(float2*)(Cf + off) = f2;
                }
                if (!OUT16) {
                    bf16 h0 = __float2bfloat16(v0);
                    bf16 h1 = __float2bfloat16(v1);
                    __nv_bfloat162 hh; hh.x = h0; hh.y = h1;
                    __nv_bfloat162 ll;
                    ll.x = __float2bfloat16(v0 - __bfloat162float(h0));
                    ll.y = __float2bfloat16(v1 - __bfloat162float(h1));
                    *(__nv_bfloat162*)(Chi + off) = hh;
                    *(__nv_bfloat162*)(Clo + off) = ll;
                } else {
                    fp16 h0 = __float2half_rn(v0);
                    fp16 h1 = __float2half_rn(v1);
                    __half2 hh; hh.x = h0; hh.y = h1;
                    __half2 ll;
                    ll.x = __float2half_rn(v0 - __half2float(h0));
                    ll.y = __float2half_rn(v1 - __half2float(h1));
                    *(__half2*)(H16 + off) = hh;
                    *(__half2*)(L16 + off) = ll;
                }
                if (mirror) {
                    ts[rl * 129 + cl] = v0;
                    ts[rl * 129 + cl + 1] = v1;
                }
            }

    if (mirror) {
        __syncthreads();
#pragma unroll 4
        for (int i = 0; i < 16; i++) {
            int lin = i * 1024 + tid * 2;
            int mr = lin >> 7, mc = lin & 127;
            float v0 = ts[mc * 129 + mr];
            float v1 = ts[(mc + 1) * 129 + mr];
            const size_t off = (size_t)z * MM + (size_t)(col0 + mr) * DN + row0 + mc;
            if (MODE == 0) {
                float2 f2; f2.x = v0; f2.y = v1;
                *(float2*)(Cf + off) = f2;
            }
            if (!OUT16) {
                bf16 h0 = __float2bfloat16(v0);
                bf16 h1 = __float2bfloat16(v1);
                __nv_bfloat162 hh; hh.x = h0; hh.y = h1;
                __nv_bfloat162 ll;
                ll.x = __float2bfloat16(v0 - __bfloat162float(h0));
                ll.y = __float2bfloat16(v1 - __bfloat162float(h1));
                *(__nv_bfloat162*)(Chi + off) = hh;
                *(__nv_bfloat162*)(Clo + off) = ll;
            } else {
                fp16 h0 = __float2half_rn(v0);
                fp16 h1 = __float2half_rn(v1);
                __half2 hh; hh.x = h0; hh.y = h1;
                __half2 ll;
                ll.x = __float2half_rn(v0 - __half2float(h0));
                ll.y = __float2half_rn(v1 - __half2float(h1));
                *(__half2*)(H16 + off) = hh;
                *(__half2*)(L16 + off) = ll;
            }
        }
    }
}

// ---- 2-term fp16 squaring: A = P-hi (single), B = P-hi + P-lo (exact) -----
__global__ void __launch_bounds__(512, 1) gemm2hsq_k(
    const fp16* __restrict__ Phi, const fp16* __restrict__ Plo,
    fp16* __restrict__ Poh, fp16* __restrict__ Pol,
    const float* __restrict__ trin)
{
    extern __shared__ char smem[];
    const uint32_t sb = smem_u32(smem);

    const int tid = threadIdx.x;
    const int wid = tid >> 5, lane = tid & 31;
    const int wr = wid >> 2, wc = wid & 3;
    const int z = blockIdx.z;

    int t = blockIdx.x, ti = 0;
    while (t >= 8 - ti) { t -= 8 - ti; ti++; }
    const int row0 = ti * 128, col0 = (ti + t) * 128;

    const fp16* Aa = Phi + (size_t)z * MM + (size_t)row0 * DN;
    const fp16* Bh = Phi + (size_t)z * MM + (size_t)col0 * DN;
    const fp16* Bl = Plo + (size_t)z * MM + (size_t)col0 * DN;
    const fp16* gbase[3] = {Aa, Bh, Bl};

    auto load_stage = [&](int st, int k0) {
        const uint32_t base = sb + (uint32_t)st * STG3;
        const int ch = tid & 7;
        const int rlo = tid >> 3;
#pragma unroll
        for (int t2 = 0; t2 < 6; t2++) {
            const int mat = t2 >> 1;
            const int r = ((t2 & 1) << 6) + rlo;
            cp16(base + (uint32_t)mat * MATB + (uint32_t)(r * RSEB + ch * 16),
                 gbase[mat] + (long)r * DN + k0 + ch * 8);
        }
        CP_COMMIT();
    };

    float acc[2][4][4];
#pragma unroll
    for (int mi = 0; mi < 2; mi++)
#pragma unroll
        for (int ni = 0; ni < 4; ni++)
#pragma unroll
            for (int q = 0; q < 4; q++) acc[mi][ni][q] = 0.0f;

    load_stage(0, 0);
    load_stage(1, BK);

    const int arow = (lane & 7) + ((lane >> 3) & 1) * 8;
    const int acol = (lane >> 4) * 16;
    const int brow = (lane & 7) + ((lane >> 4) & 1) * 8;
    const int bcol = ((lane >> 3) & 1) * 16;

    for (int s = 0; s < NKS; s++) {
        if (s < NKS - 1) { CP_WAIT(1); } else { CP_WAIT(0); }
        __syncthreads();
        if (s + 2 < NKS) load_stage((s + 2) % 3, (s + 2) * BK);

        const uint32_t stb = sb + (uint32_t)(s % 3) * STG3;
        const uint32_t aB  = stb + (uint32_t)((wr * 32 + arow) * RSEB) + acol;
        const uint32_t bBh = stb + MATB + (uint32_t)((wc * 32 + brow) * RSEB) + bcol;
        const uint32_t bBl = bBh + MATB;

#pragma unroll
        for (int kk = 0; kk < 4; kk++) {
            const uint32_t ko = (uint32_t)(kk * 32);
            uint32_t ah[2][4], bh[4][2], bl[4][2];
#pragma unroll
            for (int mi = 0; mi < 2; mi++)
                LDSM4(ah[mi][0], ah[mi][1], ah[mi][2], ah[mi][3], aB + ko + (uint32_t)(mi * 16 * RSEB));
#pragma unroll
            for (int p = 0; p < 2; p++) {
                LDSM4(bh[2*p][0], bh[2*p][1], bh[2*p+1][0], bh[2*p+1][1], bBh + ko + (uint32_t)(p * 16 * RSEB));
                LDSM4(bl[2*p][0], bl[2*p][1], bl[2*p+1][0], bl[2*p+1][1], bBl + ko + (uint32_t)(p * 16 * RSEB));
            }
#pragma unroll
            for (int mi = 0; mi < 2; mi++)
#pragma unroll
                for (int ni = 0; ni < 4; ni++) MMAH16816(acc[mi][ni], ah[mi], bh[ni]);
#pragma unroll
            for (int mi = 0; mi < 2; mi++)
#pragma unroll
                for (int ni = 0; ni < 4; ni++) MMAH16816(acc[mi][ni], ah[mi], bl[ni]);
        }
        __syncthreads();
    }

    const float tv = trin[z];
    const float scl = TRTGT / (tv * tv);
    const int gID = lane >> 2, tg = lane & 3;
    const bool mirror = (row0 != col0);
    float* ts = (float*)smem;

#pragma unroll
    for (int mi = 0; mi < 2; mi++)
#pragma unroll
        for (int ni = 0; ni < 4; ni++)
#pragma unroll
            for (int hf = 0; hf < 2; hf++) {
                const int rl = wr * 32 + mi * 16 + gID + hf * 8;
                const int cl = wc * 32 + ni * 8 + tg * 2;
                float v0 = acc[mi][ni][hf * 2 + 0] * scl;
                float v1 = acc[mi][ni][hf * 2 + 1] * scl;
                const size_t off = (size_t)z * MM + (size_t)(row0 + rl) * DN + col0 + cl;
                fp16 h0 = __float2half_rn(v0);
                fp16 h1 = __float2half_rn(v1);
                __half2 hh; hh.x = h0; hh.y = h1;
                __half2 ll;
                ll.x = __float2half_rn(v0 - __half2float(h0));
                ll.y = __float2half_rn(v1 - __half2float(h1));
                *(__half2*)(Poh + off) = hh;
                *(__half2*)(Pol + off) = ll;
                if (mirror) {
                    ts[rl * 129 + cl] = v0;
                    ts[rl * 129 + cl + 1] = v1;
                }
            }

    if (mirror) {
        __syncthreads();
#pragma unroll 4
        for (int i = 0; i < 16; i++) {
            int lin = i * 1024 + tid * 2;
            int mr = lin >> 7, mc = lin & 127;
            float v0 = ts[mc * 129 + mr];
            float v1 = ts[(mc + 1) * 129 + mr];
            const size_t off = (size_t)z * MM + (size_t)(col0 + mr) * DN + row0 + mc;
            fp16 h0 = __float2half_rn(v0);
            fp16 h1 = __float2half_rn(v1);
            __half2 hh; hh.x = h0; hh.y = h1;
            __half2 ll;
            ll.x = __float2half_rn(v0 - __half2float(h0));
            ll.y = __float2half_rn(v1 - __half2float(h1));
            *(__half2*)(Poh + off) = hh;
            *(__half2*)(Pol + off) = ll;
        }
    }
}

// ------ 1-term fp16 MLP GEMM: A single, B = W-hi single, 2-stage, 2/SM -----
// MODE 0: h = gelu((X W1)*is + b1) -> fp16
// MODE 1: out = (h W2)*is + b2     -> fp32
template <int MODE>
__global__ void __launch_bounds__(256, 2) gemm1hm_k(
    const fp16* __restrict__ A, long lda,
    const fp16* __restrict__ B,
    float* __restrict__ Cf, fp16* __restrict__ C16,
    const float* __restrict__ bias, const float* __restrict__ sc)
{
    extern __shared__ char smem[];
    const uint32_t sb = smem_u32(smem);

    const int tid = threadIdx.x;
    const int wid = tid >> 5, lane = tid & 31;
    const int wr = wid >> 1, wc = wid & 1;       // 4x2 warps, 32x64 warp tiles
    const int z = blockIdx.z;
    const int row0 = blockIdx.y * 128, col0 = blockIdx.x * 128;

    const fp16* Aa = A + (size_t)z * DN + (size_t)row0 * lda;
    const fp16* Bb = B + (size_t)z * MM + (size_t)col0 * DN;

    auto load_stage = [&](int st, int k0) {
        const uint32_t base = sb + (uint32_t)st * STG2;
        const int ch = tid & 7;
        const int rlo = tid >> 3;
#pragma unroll
        for (int t2 = 0; t2 < 8; t2++) {
            const int mat = t2 >> 2;
            const int r = ((t2 & 3) << 5) + rlo;
            const fp16* src = mat ? Bb : Aa;
            const long stride = mat ? (long)DN : lda;
            cp16(base + (uint32_t)mat * MATB + (uint32_t)(r * RSEB + ch * 16),
                 src + (long)r * stride + k0 + ch * 8);
        }
        CP_COMMIT();
    };

    float acc[2][8][4];
#pragma unroll
    for (int mi = 0; mi < 2; mi++)
#pragma unroll
        for (int ni = 0; ni < 8; ni++)
#pragma unroll
            for (int q = 0; q < 4; q++) acc[mi][ni][q] = 0.0f;

    load_stage(0, 0);

    const int arow = (lane & 7) + ((lane >> 3) & 1) * 8;
    const int acol = (lane >> 4) * 16;
    const int brow = (lane & 7) + ((lane >> 4) & 1) * 8;
    const int bcol = ((lane >> 3) & 1) * 16;

    for (int s = 0; s < NKS; s++) {
        CP_WAIT(0);
        __syncthreads();
        if (s + 1 < NKS) load_stage((s + 1) & 1, (s + 1) * BK);

        const uint32_t stb = sb + (uint32_t)(s & 1) * STG2;
        const uint32_t aB = stb + (uint32_t)((wr * 32 + arow) * RSEB) + acol;
        const uint32_t bB = stb + MATB + (uint32_t)((wc * 64 + brow) * RSEB) + bcol;

#pragma unroll
        for (int kk = 0; kk < 4; kk++) {
            const uint32_t ko = (uint32_t)(kk * 32);
            uint32_t ah[2][4], bh[8][2];
#pragma unroll
            for (int mi = 0; mi < 2; mi++)
                LDSM4(ah[mi][0], ah[mi][1], ah[mi][2], ah[mi][3], aB + ko + (uint32_t)(mi * 16 * RSEB));
#pragma unroll
            for (int p = 0; p < 4; p++)
                LDSM4(bh[2*p][0], bh[2*p][1], bh[2*p+1][0], bh[2*p+1][1], bB + ko + (uint32_t)(p * 16 * RSEB));
#pragma unroll
            for (int mi = 0; mi < 2; mi++)
#pragma unroll
                for (int ni = 0; ni < 8; ni++) MMAH16816(acc[mi][ni], ah[mi], bh[ni]);
        }
        __syncthreads();
    }

    const float scl = sc[z];
    const int gID = lane >> 2, tg = lane & 3;

#pragma unroll
    for (int mi = 0; mi < 2; mi++)
#pragma unroll
        for (int ni = 0; ni < 8; ni++)
#pragma unroll
            for (int hf = 0; hf < 2; hf++) {
                const int rl = wr * 32 + mi * 16 + gID + hf * 8;
                const int cl = wc * 64 + ni * 8 + tg * 2;
                float v0 = acc[mi][ni][hf * 2 + 0] * scl + bias[z * DN + col0 + cl];
                float v1 = acc[mi][ni][hf * 2 + 1] * scl + bias[z * DN + col0 + cl + 1];
                if (MODE == 0) {
                    v0 = 0.5f * v0 * (1.0f + erff(v0 * 0.70710678118654752f));
                    v1 = 0.5f * v1 * (1.0f + erff(v1 * 0.70710678118654752f));
                }
                const size_t off = (size_t)z * DN + (size_t)(row0 + rl) * RS + col0 + cl;
                if (MODE == 0) {
                    *(__half2*)(C16 + off) = __floats2half2_rn(v0, v1);
                } else {
                    float2 f2; f2.x = v0; f2.y = v1;
                    *(float2*)(Cf + off) = f2;
                }
            }
}

// ------------- 1-term fp16 squaring GEMM, 2-stage, 2 CTAs/SM ----------------
__global__ void __launch_bounds__(256, 2) gemm1h_k(
    const fp16* __restrict__ Ph, fp16* __restrict__ Po,
    const float* __restrict__ trin)
{
    extern __shared__ char smem[];
    const uint32_t sb = smem_u32(smem);

    const int tid = threadIdx.x;
    const int wid = tid >> 5, lane = tid & 31;
    const int wr = wid >> 1, wc = wid & 1;
    const int z = blockIdx.z;

    int t = blockIdx.x, ti = 0;
    while (t >= 8 - ti) { t -= 8 - ti; ti++; }
    const int row0 = ti * 128, col0 = (ti + t) * 128;

    const fp16* Ah = Ph + (size_t)z * MM + (size_t)row0 * DN;
    const fp16* Bh = Ph + (size_t)z * MM + (size_t)col0 * DN;

    auto load_stage = [&](int st, int k0) {
        const uint32_t base = sb + (uint32_t)st * STG2;
        const int ch = tid & 7;
        const int rlo = tid >> 3;
#pragma unroll
        for (int t2 = 0; t2 < 8; t2++) {
            const int mat = t2 >> 2;
            const int r = ((t2 & 3) << 5) + rlo;
            const fp16* src = mat ? Bh : Ah;
            cp16(base + (uint32_t)mat * MATB + (uint32_t)(r * RSEB + ch * 16),
                 src + (long)r * DN + k0 + ch * 8);
        }
        CP_COMMIT();
    };

    float acc[2][8][4];
#pragma unroll
    for (int mi = 0; mi < 2; mi++)
#pragma unroll
        for (int ni = 0; ni < 8; ni++)
#pragma unroll
            for (int q = 0; q < 4; q++) acc[mi][ni][q] = 0.0f;

    load_stage(0, 0);

    const int arow = (lane & 7) + ((lane >> 3) & 1) * 8;
    const int acol = (lane >> 4) * 16;
    const int brow = (lane & 7) + ((lane >> 4) & 1) * 8;
    const int bcol = ((lane >> 3) & 1) * 16;

    for (int s = 0; s < NKS; s++) {
        CP_WAIT(0);
        __syncthreads();
        if (s + 1 < NKS) load_stage((s + 1) & 1, (s + 1) * BK);

        const uint32_t stb = sb + (uint32_t)(s & 1) * STG2;
        const uint32_t aB = stb + (uint32_t)((wr * 32 + arow) * RSEB) + acol;
        const uint32_t bB = stb + MATB + (uint32_t)((wc * 64 + brow) * RSEB) + bcol;

#pragma unroll
        for (int kk = 0; kk < 4; kk++) {
            const uint32_t ko = (uint32_t)(kk * 32);
            uint32_t ah[2][4], bh[8][2];
#pragma unroll
            for (int mi = 0; mi < 2; mi++)
                LDSM4(ah[mi][0], ah[mi][1], ah[mi][2], ah[mi][3], aB + ko + (uint32_t)(mi * 16 * RSEB));
#pragma unroll
            for (int p = 0; p < 4; p++)
                LDSM4(bh[2*p][0], bh[2*p][1], bh[2*p+1][0], bh[2*p+1][1], bB + ko + (uint32_t)(p * 16 * RSEB));
#pragma unroll
            for (int mi = 0; mi < 2; mi++)
#pragma unroll
                for (int ni = 0; ni < 8; ni++) MMAH16816(acc[mi][ni], ah[mi], bh[ni]);
        }
        __syncthreads();
    }

    const float tv = trin[z];
    const float scl = TRTGT / (tv * tv);
    const int gID = lane >> 2, tg = lane & 3;
    const bool mirror = (row0 != col0);
    float* ts = (float*)smem;

#pragma unroll
    for (int mi = 0; mi < 2; mi++)
#pragma unroll
        for (int ni = 0; ni < 8; ni++)
#pragma unroll
            for (int hf = 0; hf < 2; hf++) {
                const int rl = wr * 32 + mi * 16 + gID + hf * 8;
                const int cl = wc * 64 + ni * 8 + tg * 2;
                float v0 = acc[mi][ni][hf * 2 + 0] * scl;
                float v1 = acc[mi][ni][hf * 2 + 1] * scl;
                const size_t off = (size_t)z * MM + (size_t)(row0 + rl) * DN + col0 + cl;
                *(__half2*)(Po + off) = __floats2half2_rn(v0, v1);
                if (mirror) {
                    ts[rl * 129 + cl] = v0;
                    ts[rl * 129 + cl + 1] = v1;
                }
            }

    if (mirror) {
        __syncthreads();
#pragma unroll 4
        for (int i = 0; i < 32; i++) {
            int lin = i * 512 + tid * 2;
            int mr = lin >> 7, mc = lin & 127;
            float v0 = ts[mc * 129 + mr];
            float v1 = ts[(mc + 1) * 129 + mr];
            const size_t off = (size_t)z * MM + (size_t)(col0 + mr) * DN + row0 + mc;
            *(__half2*)(Po + off) = __floats2half2_rn(v0, v1);
        }
    }
}

// --------------------------- small kernels ----------------------------------
__global__ void __launch_bounds__(256) k_trace_f(const float* __restrict__ G,
                                                 float* __restrict__ out)
{
    const int m = blockIdx.x;
    float sum = 0.0f;
    for (int d = threadIdx.x; d < DN; d += 256)
        sum += G[(size_t)m * MM + (size_t)d * DN + d];
    __shared__ float red[256];
    red[threadIdx.x] = sum; __syncthreads();
    for (int off = 128; off > 0; off >>= 1) {
        if (threadIdx.x < off) red[threadIdx.x] += red[threadIdx.x + off];
        __syncthreads();
    }
    if (threadIdx.x == 0) out[m] = red[0];
}

__global__ void __launch_bounds__(256) k_trace_h16(const fp16* __restrict__ P,
                                                   const fp16* __restrict__ Pl,
                                                   float* __restrict__ out)
{
    const int m = blockIdx.x;
    float sum = 0.0f;
    for (int d = threadIdx.x; d < DN; d += 256) {
        size_t o = (size_t)m * MM + (size_t)d * DN + d;
        sum += __half2float(P[o]);
        if (Pl) sum += __half2float(Pl[o]);
    }
    __shared__ float red[256];
    red[threadIdx.x] = sum; __syncthreads();
    for (int off = 128; off > 0; off >>= 1) {
        if (threadIdx.x < off) red[threadIdx.x] += red[threadIdx.x + off];
        __syncthreads();
    }
    if (threadIdx.x == 0) out[m] = red[0];
}

__global__ void __launch_bounds__(256) k_pickcol16(const fp16* __restrict__ P,
                                                   float* __restrict__ v)
{
    const int m = blockIdx.x;
    const size_t base = (size_t)m * MM;
    __shared__ float bv[256];
    __shared__ int bi[256];
    float best = -1.0f; int bidx = 0;
    for (int d = threadIdx.x; d < DN; d += 256) {
        float val = fabsf(__half2float(P[base + (size_t)d * DN + d]));
        if (val > best) { best = val; bidx = d; }
    }
    bv[threadIdx.x] = best; bi[threadIdx.x] = bidx;
    __syncthreads();
    for (int off = 128; off > 0; off >>= 1) {
        if (threadIdx.x < off && bv[threadIdx.x + off] > bv[threadIdx.x]) {
            bv[threadIdx.x] = bv[threadIdx.x + off];
            bi[threadIdx.x] = bi[threadIdx.x + off];
        }
        __syncthreads();
    }
    const int j = bi[0];
    for (int i = threadIdx.x; i < DN; i += 256)
        v[m * DN + i] = __half2float(P[base + (size_t)j * DN + i]);
}

__global__ void __launch_bounds__(256) k_matvec(const float* __restrict__ G,
                                                const float* __restrict__ v,
                                                float* __restrict__ gv)
{
    const int m = blockIdx.y, r = blockIdx.x;
    const float* row = G + (size_t)m * MM + (size_t)r * DN;
    const float* vm = v + m * DN;
    float4 a = *(const float4*)&row[threadIdx.x * 4];
    float4 b = *(const float4*)&vm[threadIdx.x * 4];
    float sum = a.x * b.x + a.y * b.y + a.z * b.z + a.w * b.w;
    __shared__ float red[256];
    red[threadIdx.x] = sum; __syncthreads();
    for (int off = 128; off > 0; off >>= 1) {
        if (threadIdx.x < off) red[threadIdx.x] += red[threadIdx.x + off];
        __syncthreads();
    }
    if (threadIdx.x == 0) gv[m * DN + r] = red[0];
}

__global__ void __launch_bounds__(256) k_sigma(const float* __restrict__ v,
                                               const float* __restrict__ gv,
                                               float* __restrict__ is_)
{
    const int m = blockIdx.x;
    float num = 0.0f, den = 0.0f;
    for (int d = threadIdx.x; d < DN; d += 256) {
        float vv = v[m * DN + d];
        num += vv * gv[m * DN + d];
        den += vv * vv;
    }
    __shared__ float rn[256], rd[256];
    rn[threadIdx.x] = num; rd[threadIdx.x] = den; __syncthreads();
    for (int off = 128; off > 0; off >>= 1) {
        if (threadIdx.x < off) { rn[threadIdx.x] += rn[threadIdx.x + off]; rd[threadIdx.x] += rd[threadIdx.x + off]; }
        __syncthreads();
    }
    if (threadIdx.x == 0) is_[m] = sqrtf(rd[0] / rn[0]);
}

// ---------------------------------------------------------------------------
extern "C" void kernel_launch(void* const* d_in, const int* in_sizes, int n_in,
                              void* d_out, int out_size)
{
    const float* x  = (const float*)d_in[0];
    const float* w1 = (const float*)d_in[1];
    const float* b1 = (const float*)d_in[2];
    const float* w2 = (const float*)d_in[3];
    const float* b2 = (const float*)d_in[4];
    float* out = (float*)d_out;

    fp16 *x16, *w16h, *h16;
    bf16 *wth, *wtl, *P0h, *P0l, *P1h, *P1l;
    float *G, *tr, *v, *gv, *is_;
    cudaGetSymbolAddress((void**)&x16, g_x16);
    cudaGetSymbolAddress((void**)&wth, g_wth); cudaGetSymbolAddress((void**)&wtl, g_wtl);
    cudaGetSymbolAddress((void**)&w16h, g_w16h);
    cudaGetSymbolAddress((void**)&G, g_G);
    cudaGetSymbolAddress((void**)&P0h, g_P0h); cudaGetSymbolAddress((void**)&P0l, g_P0l);
    cudaGetSymbolAddress((void**)&P1h, g_P1h); cudaGetSymbolAddress((void**)&P1l, g_P1l);
    cudaGetSymbolAddress((void**)&h16, g_h16);
    cudaGetSymbolAddress((void**)&tr, g_tr);   cudaGetSymbolAddress((void**)&v, g_v);
    cudaGetSymbolAddress((void**)&gv, g_gv);   cudaGetSymbolAddress((void**)&is_, g_is);

    cudaFuncSetAttribute(gemm_k<0>, cudaFuncAttributeMaxDynamicSharedMemorySize, SMEM_BYTES);
    cudaFuncSetAttribute(gemm_k<4>, cudaFuncAttributeMaxDynamicSharedMemorySize, SMEM_BYTES);
    cudaFuncSetAttribute(gemm2hsq_k, cudaFuncAttributeMaxDynamicSharedMemorySize, SMEM3M);
    cudaFuncSetAttribute(gemm1hm_k<0>, cudaFuncAttributeMaxDynamicSharedMemorySize, SMEM1);
    cudaFuncSetAttribute(gemm1hm_k<1>, cudaFuncAttributeMaxDynamicSharedMemorySize, SMEM1);
    cudaFuncSetAttribute(gemm1h_k,  cudaFuncAttributeMaxDynamicSharedMemorySize, SMEM1);

    conv_x16<<<(unsigned)((size_t)BATCH * RS / 4 / 256), 256>>>(x, x16);
    conv_wT<<<dim3(32, 32, NB), 256>>>(w1, wth, wtl, w16h);
    conv_wT<<<dim3(32, 32, NB), 256>>>(w2, wth + (size_t)NB * MM, wtl + (size_t)NB * MM,
                                       w16h + (size_t)NB * MM);

    // Gram: G (fp32) + P0 (bf16 hi/lo); trace from fp32 G
    gemm_k<0><<<dim3(36, 1, NMAT), 512, SMEM_BYTES>>>(
        wth, wtl, wth, wtl, G, P0h, P0l, nullptr);
    k_trace_f<<<NMAT, 256>>>(G, tr);

    int step = 0;
    fp16* Q0h = reinterpret_cast<fp16*>(P0h);
    fp16* Q0l = reinterpret_cast<fp16*>(P0l);
    fp16* Q1h = reinterpret_cast<fp16*>(P1h);
    fp16* Q1l = reinterpret_cast<fp16*>(P1l);

    // Step 1: 3-term bf16 compute, fp16 hi/lo out at trace TRTGT  P0 -> Q1
    gemm_k<4><<<dim3(36, 1, NMAT), 512, SMEM_BYTES>>>(
        P0h, P0l, P0h, P0l, nullptr, (bf16*)Q1h, (bf16*)Q1l, tr + step * NMAT);
    step++;
    k_trace_h16<<<NMAT, 256>>>(Q1h, Q1l, tr + step * NMAT);

    // Steps 2-3: 2-term fp16 squarings (hi/lo out)  Q1 -> Q0 -> Q1
    gemm2hsq_k<<<dim3(36, 1, NMAT), 512, SMEM3M>>>(Q1h, Q1l, Q0h, Q0l, tr + step * NMAT);
    step++;
    k_trace_h16<<<NMAT, 256>>>(Q0h, Q0l, tr + step * NMAT);
    gemm2hsq_k<<<dim3(36, 1, NMAT), 512, SMEM3M>>>(Q0h, Q0l, Q1h, Q1l, tr + step * NMAT);
    step++;
    k_trace_h16<<<NMAT, 256>>>(Q1h, Q1l, tr + step * NMAT);

    // Steps 4-10: 1-term fp16 squarings (hi buffers only)
    fp16* pi16 = Q1h;
    fp16* po16 = Q0h;
    for (int s = 0; s < 7; s++, step++) {
        gemm1h_k<<<dim3(36, 1, NMAT), 256, SMEM1>>>(pi16, po16, tr + step * NMAT);
        k_trace_h16<<<NMAT, 256>>>(po16, nullptr, tr + (step + 1) * NMAT);
        fp16* t1 = pi16; pi16 = po16; po16 = t1;
    }

    // Rayleigh quotient on fp32 G with v = argmax-diag column of P_final
    k_pickcol16<<<NMAT, 256>>>(pi16, v);
    k_matvec<<<dim3(DN, NMAT), 256>>>(G, v, gv);
    k_sigma<<<NMAT, 256>>>(v, gv, is_);

    // MLP: 1-term fp16 (A single, B = W-hi single)
    gemm1hm_k<0><<<dim3(8, 32, NB), 256, SMEM1>>>(
        x16, RS, w16h, nullptr, h16, b1, is_);
    gemm1hm_k<1><<<dim3(8, 32, NB), 256, SMEM1>>>(
        h16, RS, w16h + (size_t)NB * MM, out, nullptr, b2, is_ + NB);
}

// round 17
// speedup vs baseline: 2.6613x; 1.0723x over previous
#include <cuda_runtime.h>
#include <cuda_fp16.h>
#include <cstdint>
#include <math.h>

#define NB 25
#define BATCH 4096
#define DN 1024
#define RS (NB * DN)
#define NMAT (2 * NB)
#define MM ((size_t)DN * DN)
#define NSQ 10
#define BK 64
#define NKS (DN / BK)            // 16 k-stages
#define RSEB 144                 // smem row stride bytes (128B data + 16B pad)
#define MATB (128 * RSEB)        // 18432 B per matrix tile
#define STG3 (3 * MATB)          // 55296 B per stage (3 mats)
#define SMEM3M (3 * STG3)        // 165888 (2-term kernels, 3 stages)
#define STG2 (2 * MATB)          // 36864 B per stage (2 mats)
#define SMEM1 (2 * STG2)         // 73728 (1-term kernels, 2 stages)
#define TRTGT 256.0f             // fp16-chain trace target
#define SC0 (TRTGT / 420.0f)     // Gram->P0 seed scale (trace(G)~||W||_F^2~420)

typedef __half fp16;

// ----------------------------- scratch -------------------------------------
__device__ fp16  g_x16[(size_t)BATCH * RS];
__device__ fp16  g_w16h[NMAT * MM];
__device__ fp16  g_w16l[NMAT * MM];
__device__ float g_G  [NMAT * MM];
__device__ fp16  g_Q0h[NMAT * MM];
__device__ fp16  g_Q0l[NMAT * MM];
__device__ fp16  g_Q1h[NMAT * MM];
__device__ fp16  g_Q1l[NMAT * MM];
__device__ fp16  g_h16[(size_t)BATCH * RS];
__device__ float g_tr [(NSQ + 1) * NMAT];
__device__ float g_v  [NMAT * DN];
__device__ float g_gv [NMAT * DN];
__device__ float g_is [NMAT];

// ----------------------------- PTX helpers ---------------------------------
__device__ __forceinline__ uint32_t smem_u32(const void* p) {
    uint32_t a;
    asm("{ .reg .u64 t; cvta.to.shared.u64 t, %1; cvt.u32.u64 %0, t; }" : "=r"(a) : "l"(p));
    return a;
}
__device__ __forceinline__ void cp16(uint32_t s, const void* g) {
    asm volatile("cp.async.cg.shared.global [%0], [%1], 16;" :: "r"(s), "l"(g));
}
#define CP_COMMIT() asm volatile("cp.async.commit_group;" ::: "memory")
#define CP_WAIT(N)  asm volatile("cp.async.wait_group %0;" :: "n"(N) : "memory")

#define LDSM4(r0, r1, r2, r3, addr) \
    asm volatile("ldmatrix.sync.aligned.m8n8.x4.shared.b16 {%0,%1,%2,%3}, [%4];" \
        : "=r"(r0), "=r"(r1), "=r"(r2), "=r"(r3) : "r"(addr))

#define MMAH16816(c, a, b) \
    asm volatile("mma.sync.aligned.m16n8k16.row.col.f32.f16.f16.f32 " \
        "{%0,%1,%2,%3}, {%4,%5,%6,%7}, {%8,%9}, {%0,%1,%2,%3};" \
        : "+f"((c)[0]), "+f"((c)[1]), "+f"((c)[2]), "+f"((c)[3]) \
        : "r"((a)[0]), "r"((a)[1]), "r"((a)[2]), "r"((a)[3]), "r"((b)[0]), "r"((b)[1]))

// ----------------------------- conversions ---------------------------------
__global__ void __launch_bounds__(256) conv_x16(const float* __restrict__ in,
                                                fp16* __restrict__ out)
{
    size_t i = ((size_t)blockIdx.x * 256 + threadIdx.x) * 4;
    float4 v = *(const float4*)(in + i);
    *(__half2*)(out + i)     = __floats2half2_rn(v.x, v.y);
    *(__half2*)(out + i + 2) = __floats2half2_rn(v.z, v.w);
}

// W transpose + fp16 hi/lo split
__global__ void __launch_bounds__(256) conv_wT16(const float* __restrict__ w,
                                                 fp16* __restrict__ hhi,
                                                 fp16* __restrict__ hlo)
{
    const int m = blockIdx.z;
    const float* W = w + (size_t)m * MM;
    fp16* Hh = hhi + (size_t)m * MM;
    fp16* Hl = hlo + (size_t)m * MM;
    __shared__ float t[32][33];
    const int r0 = blockIdx.y * 32, c0 = blockIdx.x * 32;
    const int tr = threadIdx.x >> 5, tc = threadIdx.x & 31;
#pragma unroll
    for (int i = 0; i < 4; i++)
        t[tr + 8 * i][tc] = W[(size_t)(r0 + tr + 8 * i) * DN + c0 + tc];
    __syncthreads();
#pragma unroll
    for (int i = 0; i < 4; i++) {
        int rr = tr + 8 * i;
        float v = t[tc][rr];
        size_t o = (size_t)(c0 + rr) * DN + r0 + tc;
        fp16 h6 = __float2half_rn(v);
        Hh[o] = h6;
        Hl[o] = __float2half_rn(v - __half2float(h6));
    }
}

// ------ 2-term fp16 GEMM (A = hi single, B = hi+lo), triangular, 3-stage ---
// MODE 0: Gram    -> Cf (fp32 G) + fp16 hi/lo out at fixed SC0
// MODE 1: square  -> fp16 hi/lo out, scl = TRTGT/tr^2
template <int MODE>
__global__ void __launch_bounds__(512, 1) gemm2h_k(
    const fp16* __restrict__ Ahi,
    const fp16* __restrict__ Bhi, const fp16* __restrict__ Blo,
    float* __restrict__ Cf, fp16* __restrict__ Poh, fp16* __restrict__ Pol,
    const float* __restrict__ trin)
{
    extern __shared__ char smem[];
    const uint32_t sb = smem_u32(smem);

    const int tid = threadIdx.x;
    const int wid = tid >> 5, lane = tid & 31;
    const int wr = wid >> 2, wc = wid & 3;
    const int z = blockIdx.z;

    int t = blockIdx.x, ti = 0;
    while (t >= 8 - ti) { t -= 8 - ti; ti++; }
    const int row0 = ti * 128, col0 = (ti + t) * 128;

    const fp16* Aa = Ahi + (size_t)z * MM + (size_t)row0 * DN;
    const fp16* Bh = Bhi + (size_t)z * MM + (size_t)col0 * DN;
    const fp16* Bl = Blo + (size_t)z * MM + (size_t)col0 * DN;
    const fp16* gbase[3] = {Aa, Bh, Bl};

    auto load_stage = [&](int st, int k0) {
        const uint32_t base = sb + (uint32_t)st * STG3;
        const int ch = tid & 7;
        const int rlo = tid >> 3;
#pragma unroll
        for (int t2 = 0; t2 < 6; t2++) {
            const int mat = t2 >> 1;
            const int r = ((t2 & 1) << 6) + rlo;
            cp16(base + (uint32_t)mat * MATB + (uint32_t)(r * RSEB + ch * 16),
                 gbase[mat] + (long)r * DN + k0 + ch * 8);
        }
        CP_COMMIT();
    };

    float acc[2][4][4];
#pragma unroll
    for (int mi = 0; mi < 2; mi++)
#pragma unroll
        for (int ni = 0; ni < 4; ni++)
#pragma unroll
            for (int q = 0; q < 4; q++) acc[mi][ni][q] = 0.0f;

    load_stage(0, 0);
    load_stage(1, BK);

    const int arow = (lane & 7) + ((lane >> 3) & 1) * 8;
    const int acol = (lane >> 4) * 16;
    const int brow = (lane & 7) + ((lane >> 4) & 1) * 8;
    const int bcol = ((lane >> 3) & 1) * 16;

    for (int s = 0; s < NKS; s++) {
        if (s < NKS - 1) { CP_WAIT(1); } else { CP_WAIT(0); }
        __syncthreads();
        if (s + 2 < NKS) load_stage((s + 2) % 3, (s + 2) * BK);

        const uint32_t stb = sb + (uint32_t)(s % 3) * STG3;
        const uint32_t aB  = stb + (uint32_t)((wr * 32 + arow) * RSEB) + acol;
        const uint32_t bBh = stb + MATB + (uint32_t)((wc * 32 + brow) * RSEB) + bcol;
        const uint32_t bBl = bBh + MATB;

#pragma unroll
        for (int kk = 0; kk < 4; kk++) {
            const uint32_t ko = (uint32_t)(kk * 32);
            uint32_t ah[2][4], bh[4][2], bl[4][2];
#pragma unroll
            for (int mi = 0; mi < 2; mi++)
                LDSM4(ah[mi][0], ah[mi][1], ah[mi][2], ah[mi][3], aB + ko + (uint32_t)(mi * 16 * RSEB));
#pragma unroll
            for (int p = 0; p < 2; p++) {
                LDSM4(bh[2*p][0], bh[2*p][1], bh[2*p+1][0], bh[2*p+1][1], bBh + ko + (uint32_t)(p * 16 * RSEB));
                LDSM4(bl[2*p][0], bl[2*p][1], bl[2*p+1][0], bl[2*p+1][1], bBl + ko + (uint32_t)(p * 16 * RSEB));
            }
#pragma unroll
            for (int mi = 0; mi < 2; mi++)
#pragma unroll
                for (int ni = 0; ni < 4; ni++) MMAH16816(acc[mi][ni], ah[mi], bh[ni]);
#pragma unroll
            for (int mi = 0; mi < 2; mi++)
#pragma unroll
                for (int ni = 0; ni < 4; ni++) MMAH16816(acc[mi][ni], ah[mi], bl[ni]);
        }
        __syncthreads();
    }

    float scl;
    if (MODE == 0) {
        scl = SC0;
    } else {
        const float tv = trin[z];
        scl = TRTGT / (tv * tv);
    }
    const int gID = lane >> 2, tg = lane & 3;
    const bool mirror = (row0 != col0);
    float* ts = (float*)smem;

#pragma unroll
    for (int mi = 0; mi < 2; mi++)
#pragma unroll
        for (int ni = 0; ni < 4; ni++)
#pragma unroll
            for (int hf = 0; hf < 2; hf++) {
                const int rl = wr * 32 + mi * 16 + gID + hf * 8;
                const int cl = wc * 32 + ni * 8 + tg * 2;
                float r0v = acc[mi][ni][hf * 2 + 0];
                float r1v = acc[mi][ni][hf * 2 + 1];
                float v0 = r0v * scl;
                float v1 = r1v * scl;
                const size_t off = (size_t)z * MM + (size_t)(row0 + rl) * DN + col0 + cl;
                if (MODE == 0) {
                    float2 f2; f2.x = r0v; f2.y = r1v;   // G at true scale
                    *(float2*)(Cf + off) = f2;
                }
                fp16 h0 = __float2half_rn(v0);
                fp16 h1 = __float2half_rn(v1);
                __half2 hh; hh.x = h0; hh.y = h1;
                __half2 ll;
                ll.x = __float2half_rn(v0 - __half2float(h0));
                ll.y = __float2half_rn(v1 - __half2float(h1));
                *(__half2*)(Poh + off) = hh;
                *(__half2*)(Pol + off) = ll;
                if (mirror) {
                    ts[rl * 129 + cl] = v0;
                    ts[rl * 129 + cl + 1] = v1;
                }
            }

    if (mirror) {
        __syncthreads();
#pragma unroll 4
        for (int i = 0; i < 16; i++) {
            int lin = i * 1024 + tid * 2;
            int mr = lin >> 7, mc = lin & 127;
            float v0 = ts[mc * 129 + mr];
            float v1 = ts[(mc + 1) * 129 + mr];
            const size_t off = (size_t)z * MM + (size_t)(col0 + mr) * DN + row0 + mc;
            if (MODE == 0) {
                float2 f2; f2.x = v0 / SC0; f2.y = v1 / SC0;
                *(float2*)(Cf + off) = f2;
            }
            fp16 h0 = __float2half_rn(v0);
            fp16 h1 = __float2half_rn(v1);
            __half2 hh; hh.x = h0; hh.y = h1;
            __half2 ll;
            ll.x = __float2half_rn(v0 - __half2float(h0));
            ll.y = __float2half_rn(v1 - __half2float(h1));
            *(__half2*)(Poh + off) = hh;
            *(__half2*)(Pol + off) = ll;
        }
    }
}

// ------ 1-term fp16 MLP GEMM: A single, B = W-hi single, 2-stage, 2/SM -----
// MODE 0: h = gelu((X W1)*is + b1) -> fp16
// MODE 1: out = (h W2)*is + b2     -> fp32
template <int MODE>
__global__ void __launch_bounds__(256, 2) gemm1hm_k(
    const fp16* __restrict__ A, long lda,
    const fp16* __restrict__ B,
    float* __restrict__ Cf, fp16* __restrict__ C16,
    const float* __restrict__ bias, const float* __restrict__ sc)
{
    extern __shared__ char smem[];
    const uint32_t sb = smem_u32(smem);

    const int tid = threadIdx.x;
    const int wid = tid >> 5, lane = tid & 31;
    const int wr = wid >> 1, wc = wid & 1;
    const int z = blockIdx.z;
    const int row0 = blockIdx.y * 128, col0 = blockIdx.x * 128;

    const fp16* Aa = A + (size_t)z * DN + (size_t)row0 * lda;
    const fp16* Bb = B + (size_t)z * MM + (size_t)col0 * DN;

    auto load_stage = [&](int st, int k0) {
        const uint32_t base = sb + (uint32_t)st * STG2;
        const int ch = tid & 7;
        const int rlo = tid >> 3;
#pragma unroll
        for (int t2 = 0; t2 < 8; t2++) {
            const int mat = t2 >> 2;
            const int r = ((t2 & 3) << 5) + rlo;
            const fp16* src = mat ? Bb : Aa;
            const long stride = mat ? (long)DN : lda;
            cp16(base + (uint32_t)mat * MATB + (uint32_t)(r * RSEB + ch * 16),
                 src + (long)r * stride + k0 + ch * 8);
        }
        CP_COMMIT();
    };

    float acc[2][8][4];
#pragma unroll
    for (int mi = 0; mi < 2; mi++)
#pragma unroll
        for (int ni = 0; ni < 8; ni++)
#pragma unroll
            for (int q = 0; q < 4; q++) acc[mi][ni][q] = 0.0f;

    load_stage(0, 0);

    const int arow = (lane & 7) + ((lane >> 3) & 1) * 8;
    const int acol = (lane >> 4) * 16;
    const int brow = (lane & 7) + ((lane >> 4) & 1) * 8;
    const int bcol = ((lane >> 3) & 1) * 16;

    for (int s = 0; s < NKS; s++) {
        CP_WAIT(0);
        __syncthreads();
        if (s + 1 < NKS) load_stage((s + 1) & 1, (s + 1) * BK);

        const uint32_t stb = sb + (uint32_t)(s & 1) * STG2;
        const uint32_t aB = stb + (uint32_t)((wr * 32 + arow) * RSEB) + acol;
        const uint32_t bB = stb + MATB + (uint32_t)((wc * 64 + brow) * RSEB) + bcol;

#pragma unroll
        for (int kk = 0; kk < 4; kk++) {
            const uint32_t ko = (uint32_t)(kk * 32);
            uint32_t ah[2][4], bh[8][2];
#pragma unroll
            for (int mi = 0; mi < 2; mi++)
                LDSM4(ah[mi][0], ah[mi][1], ah[mi][2], ah[mi][3], aB + ko + (uint32_t)(mi * 16 * RSEB));
#pragma unroll
            for (int p = 0; p < 4; p++)
                LDSM4(bh[2*p][0], bh[2*p][1], bh[2*p+1][0], bh[2*p+1][1], bB + ko + (uint32_t)(p * 16 * RSEB));
#pragma unroll
            for (int mi = 0; mi < 2; mi++)
#pragma unroll
                for (int ni = 0; ni < 8; ni++) MMAH16816(acc[mi][ni], ah[mi], bh[ni]);
        }
        __syncthreads();
    }

    const float scl = sc[z];
    const int gID = lane >> 2, tg = lane & 3;

#pragma unroll
    for (int mi = 0; mi < 2; mi++)
#pragma unroll
        for (int ni = 0; ni < 8; ni++)
#pragma unroll
            for (int hf = 0; hf < 2; hf++) {
                const int rl = wr * 32 + mi * 16 + gID + hf * 8;
                const int cl = wc * 64 + ni * 8 + tg * 2;
                float v0 = acc[mi][ni][hf * 2 + 0] * scl + bias[z * DN + col0 + cl];
                float v1 = acc[mi][ni][hf * 2 + 1] * scl + bias[z * DN + col0 + cl + 1];
                if (MODE == 0) {
                    v0 = 0.5f * v0 * (1.0f + erff(v0 * 0.70710678118654752f));
                    v1 = 0.5f * v1 * (1.0f + erff(v1 * 0.70710678118654752f));
                }
                const size_t off = (size_t)z * DN + (size_t)(row0 + rl) * RS + col0 + cl;
                if (MODE == 0) {
                    *(__half2*)(C16 + off) = __floats2half2_rn(v0, v1);
                } else {
                    float2 f2; f2.x = v0; f2.y = v1;
                    *(float2*)(Cf + off) = f2;
                }
            }
}

// ------------- 1-term fp16 squaring GEMM, 2-stage, 2 CTAs/SM ----------------
__global__ void __launch_bounds__(256, 2) gemm1h_k(
    const fp16* __restrict__ Ph, fp16* __restrict__ Po,
    const float* __restrict__ trin)
{
    extern __shared__ char smem[];
    const uint32_t sb = smem_u32(smem);

    const int tid = threadIdx.x;
    const int wid = tid >> 5, lane = tid & 31;
    const int wr = wid >> 1, wc = wid & 1;
    const int z = blockIdx.z;

    int t = blockIdx.x, ti = 0;
    while (t >= 8 - ti) { t -= 8 - ti; ti++; }
    const int row0 = ti * 128, col0 = (ti + t) * 128;

    const fp16* Ah = Ph + (size_t)z * MM + (size_t)row0 * DN;
    const fp16* Bh = Ph + (size_t)z * MM + (size_t)col0 * DN;

    auto load_stage = [&](int st, int k0) {
        const uint32_t base = sb + (uint32_t)st * STG2;
        const int ch = tid & 7;
        const int rlo = tid >> 3;
#pragma unroll
        for (int t2 = 0; t2 < 8; t2++) {
            const int mat = t2 >> 2;
            const int r = ((t2 & 3) << 5) + rlo;
            const fp16* src = mat ? Bh : Ah;
            cp16(base + (uint32_t)mat * MATB + (uint32_t)(r * RSEB + ch * 16),
                 src + (long)r * DN + k0 + ch * 8);
        }
        CP_COMMIT();
    };

    float acc[2][8][4];
#pragma unroll
    for (int mi = 0; mi < 2; mi++)
#pragma unroll
        for (int ni = 0; ni < 8; ni++)
#pragma unroll
            for (int q = 0; q < 4; q++) acc[mi][ni][q] = 0.0f;

    load_stage(0, 0);

    const int arow = (lane & 7) + ((lane >> 3) & 1) * 8;
    const int acol = (lane >> 4) * 16;
    const int brow = (lane & 7) + ((lane >> 4) & 1) * 8;
    const int bcol = ((lane >> 3) & 1) * 16;

    for (int s = 0; s < NKS; s++) {
        CP_WAIT(0);
        __syncthreads();
        if (s + 1 < NKS) load_stage((s + 1) & 1, (s + 1) * BK);

        const uint32_t stb = sb + (uint32_t)(s & 1) * STG2;
        const uint32_t aB = stb + (uint32_t)((wr * 32 + arow) * RSEB) + acol;
        const uint32_t bB = stb + MATB + (uint32_t)((wc * 64 + brow) * RSEB) + bcol;

#pragma unroll
        for (int kk = 0; kk < 4; kk++) {
            const uint32_t ko = (uint32_t)(kk * 32);
            uint32_t ah[2][4], bh[8][2];
#pragma unroll
            for (int mi = 0; mi < 2; mi++)
                LDSM4(ah[mi][0], ah[mi][1], ah[mi][2], ah[mi][3], aB + ko + (uint32_t)(mi * 16 * RSEB));
#pragma unroll
            for (int p = 0; p < 4; p++)
                LDSM4(bh[2*p][0], bh[2*p][1], bh[2*p+1][0], bh[2*p+1][1], bB + ko + (uint32_t)(p * 16 * RSEB));
#pragma unroll
            for (int mi = 0; mi < 2; mi++)
#pragma unroll
                for (int ni = 0; ni < 8; ni++) MMAH16816(acc[mi][ni], ah[mi], bh[ni]);
        }
        __syncthreads();
    }

    const float tv = trin[z];
    const float scl = TRTGT / (tv * tv);
    const int gID = lane >> 2, tg = lane & 3;
    const bool mirror = (row0 != col0);
    float* ts = (float*)smem;

#pragma unroll
    for (int mi = 0; mi < 2; mi++)
#pragma unroll
        for (int ni = 0; ni < 8; ni++)
#pragma unroll
            for (int hf = 0; hf < 2; hf++) {
                const int rl = wr * 32 + mi * 16 + gID + hf * 8;
                const int cl = wc * 64 + ni * 8 + tg * 2;
                float v0 = acc[mi][ni][hf * 2 + 0] * scl;
                float v1 = acc[mi][ni][hf * 2 + 1] * scl;
                const size_t off = (size_t)z * MM + (size_t)(row0 + rl) * DN + col0 + cl;
                *(__half2*)(Po + off) = __floats2half2_rn(v0, v1);
                if (mirror) {
                    ts[rl * 129 + cl] = v0;
                    ts[rl * 129 + cl + 1] = v1;
                }
            }

    if (mirror) {
        __syncthreads();
#pragma unroll 4
        for (int i = 0; i < 32; i++) {
            int lin = i * 512 + tid * 2;
            int mr = lin >> 7, mc = lin & 127;
            float v0 = ts[mc * 129 + mr];
            float v1 = ts[(mc + 1) * 129 + mr];
            const size_t off = (size_t)z * MM + (size_t)(col0 + mr) * DN + row0 + mc;
            *(__half2*)(Po + off) = __floats2half2_rn(v0, v1);
        }
    }
}

// --------------------------- small kernels ----------------------------------
__global__ void __launch_bounds__(256) k_trace_h16(const fp16* __restrict__ P,
                                                   const fp16* __restrict__ Pl,
                                                   float* __restrict__ out)
{
    const int m = blockIdx.x;
    float sum = 0.0f;
    for (int d = threadIdx.x; d < DN; d += 256) {
        size_t o = (size_t)m * MM + (size_t)d * DN + d;
        sum += __half2float(P[o]);
        if (Pl) sum += __half2float(Pl[o]);
    }
    __shared__ float red[256];
    red[threadIdx.x] = sum; __syncthreads();
    for (int off = 128; off > 0; off >>= 1) {
        if (threadIdx.x < off) red[threadIdx.x] += red[threadIdx.x + off];
        __syncthreads();
    }
    if (threadIdx.x == 0) out[m] = red[0];
}

__global__ void __launch_bounds__(256) k_pickcol16(const fp16* __restrict__ P,
                                                   float* __restrict__ v)
{
    const int m = blockIdx.x;
    const size_t base = (size_t)m * MM;
    __shared__ float bv[256];
    __shared__ int bi[256];
    float best = -1.0f; int bidx = 0;
    for (int d = threadIdx.x; d < DN; d += 256) {
        float val = fabsf(__half2float(P[base + (size_t)d * DN + d]));
        if (val > best) { best = val; bidx = d; }
    }
    bv[threadIdx.x] = best; bi[threadIdx.x] = bidx;
    __syncthreads();
    for (int off = 128; off > 0; off >>= 1) {
        if (threadIdx.x < off && bv[threadIdx.x + off] > bv[threadIdx.x]) {
            bv[threadIdx.x] = bv[threadIdx.x + off];
            bi[threadIdx.x] = bi[threadIdx.x + off];
        }
        __syncthreads();
    }
    const int j = bi[0];
    for (int i = threadIdx.x; i < DN; i += 256)
        v[m * DN + i] = __half2float(P[base + (size_t)j * DN + i]);
}

__global__ void __launch_bounds__(256) k_matvec(const float* __restrict__ G,
                                                const float* __restrict__ v,
                                                float* __restrict__ gv)
{
    const int m = blockIdx.y, r = blockIdx.x;
    const float* row = G + (size_t)m * MM + (size_t)r * DN;
    const float* vm = v + m * DN;
    float4 a = *(const float4*)&row[threadIdx.x * 4];
    float4 b = *(const float4*)&vm[threadIdx.x * 4];
    float sum = a.x * b.x + a.y * b.y + a.z * b.z + a.w * b.w;
    __shared__ float red[256];
    red[threadIdx.x] = sum; __syncthreads();
    for (int off = 128; off > 0; off >>= 1) {
        if (threadIdx.x < off) red[threadIdx.x] += red[threadIdx.x + off];
        __syncthreads();
    }
    if (threadIdx.x == 0) gv[m * DN + r] = red[0];
}

__global__ void __launch_bounds__(256) k_sigma(const float* __restrict__ v,
                                               const float* __restrict__ gv,
                                               float* __restrict__ is_)
{
    const int m = blockIdx.x;
    float num = 0.0f, den = 0.0f;
    for (int d = threadIdx.x; d < DN; d += 256) {
        float vv = v[m * DN + d];
        num += vv * gv[m * DN + d];
        den += vv * vv;
    }
    __shared__ float rn[256], rd[256];
    rn[threadIdx.x] = num; rd[threadIdx.x] = den; __syncthreads();
    for (int off = 128; off > 0; off >>= 1) {
        if (threadIdx.x < off) { rn[threadIdx.x] += rn[threadIdx.x + off]; rd[threadIdx.x] += rd[threadIdx.x + off]; }
        __syncthreads();
    }
    if (threadIdx.x == 0) is_[m] = sqrtf(rd[0] / rn[0]);
}

// ---------------------------------------------------------------------------
extern "C" void kernel_launch(void* const* d_in, const int* in_sizes, int n_in,
                              void* d_out, int out_size)
{
    const float* x  = (const float*)d_in[0];
    const float* w1 = (const float*)d_in[1];
    const float* b1 = (const float*)d_in[2];
    const float* w2 = (const float*)d_in[3];
    const float* b2 = (const float*)d_in[4];
    float* out = (float*)d_out;

    fp16 *x16, *w16h, *w16l, *h16, *Q0h, *Q0l, *Q1h, *Q1l;
    float *G, *tr, *v, *gv, *is_;
    cudaGetSymbolAddress((void**)&x16, g_x16);
    cudaGetSymbolAddress((void**)&w16h, g_w16h);
    cudaGetSymbolAddress((void**)&w16l, g_w16l);
    cudaGetSymbolAddress((void**)&G, g_G);
    cudaGetSymbolAddress((void**)&Q0h, g_Q0h); cudaGetSymbolAddress((void**)&Q0l, g_Q0l);
    cudaGetSymbolAddress((void**)&Q1h, g_Q1h); cudaGetSymbolAddress((void**)&Q1l, g_Q1l);
    cudaGetSymbolAddress((void**)&h16, g_h16);
    cudaGetSymbolAddress((void**)&tr, g_tr);   cudaGetSymbolAddress((void**)&v, g_v);
    cudaGetSymbolAddress((void**)&gv, g_gv);   cudaGetSymbolAddress((void**)&is_, g_is);

    cudaFuncSetAttribute(gemm2h_k<0>, cudaFuncAttributeMaxDynamicSharedMemorySize, SMEM3M);
    cudaFuncSetAttribute(gemm2h_k<1>, cudaFuncAttributeMaxDynamicSharedMemorySize, SMEM3M);
    cudaFuncSetAttribute(gemm1hm_k<0>, cudaFuncAttributeMaxDynamicSharedMemorySize, SMEM1);
    cudaFuncSetAttribute(gemm1hm_k<1>, cudaFuncAttributeMaxDynamicSharedMemorySize, SMEM1);
    cudaFuncSetAttribute(gemm1h_k,  cudaFuncAttributeMaxDynamicSharedMemorySize, SMEM1);

    conv_x16<<<(unsigned)((size_t)BATCH * RS / 4 / 256), 256>>>(x, x16);
    conv_wT16<<<dim3(32, 32, NB), 256>>>(w1, w16h, w16l);
    conv_wT16<<<dim3(32, 32, NB), 256>>>(w2, w16h + (size_t)NB * MM, w16l + (size_t)NB * MM);

    // Gram (2-term fp16): G fp32 + Q1 = G*SC0 (fp16 hi/lo)
    gemm2h_k<0><<<dim3(36, 1, NMAT), 512, SMEM3M>>>(
        w16h, w16h, w16l, G, Q1h, Q1l, nullptr);
    int step = 0;
    k_trace_h16<<<NMAT, 256>>>(Q1h, Q1l, tr + step * NMAT);

    // Steps 1-3: 2-term fp16 squarings (hi/lo out)  Q1 -> Q0 -> Q1 -> Q0
    gemm2h_k<1><<<dim3(36, 1, NMAT), 512, SMEM3M>>>(
        Q1h, Q1h, Q1l, nullptr, Q0h, Q0l, tr + step * NMAT);
    step++;
    k_trace_h16<<<NMAT, 256>>>(Q0h, Q0l, tr + step * NMAT);
    gemm2h_k<1><<<dim3(36, 1, NMAT), 512, SMEM3M>>>(
        Q0h, Q0h, Q0l, nullptr, Q1h, Q1l, tr + step * NMAT);
    step++;
    k_trace_h16<<<NMAT, 256>>>(Q1h, Q1l, tr + step * NMAT);
    gemm2h_k<1><<<dim3(36, 1, NMAT), 512, SMEM3M>>>(
        Q1h, Q1h, Q1l, nullptr, Q0h, Q0l, tr + step * NMAT);
    step++;
    k_trace_h16<<<NMAT, 256>>>(Q0h, Q0l, tr + step * NMAT);

    // Steps 4-10: 1-term fp16 squarings (hi buffers only)
    fp16* pi16 = Q0h;
    fp16* po16 = Q1h;
    for (int s = 0; s < 7; s++, step++) {
        gemm1h_k<<<dim3(36, 1, NMAT), 256, SMEM1>>>(pi16, po16, tr + step * NMAT);
        k_trace_h16<<<NMAT, 256>>>(po16, nullptr, tr + (step + 1) * NMAT);
        fp16* t1 = pi16; pi16 = po16; po16 = t1;
    }

    // Rayleigh quotient on fp32 G with v = argmax-diag column of P_final
    k_pickcol16<<<NMAT, 256>>>(pi16, v);
    k_matvec<<<dim3(DN, NMAT), 256>>>(G, v, gv);
    k_sigma<<<NMAT, 256>>>(v, gv, is_);

    // MLP: 1-term fp16 (A single, B = W-hi single)
    gemm1hm_k<0><<<dim3(8, 32, NB), 256, SMEM1>>>(
        x16, RS, w16h, nullptr, h16, b1, is_);
    gemm1hm_k<1><<<dim3(8, 32, NB), 256, SMEM1>>>(
        h16, RS, w16h + (size_t)NB * MM, out, nullptr, b2, is_ + NB);
}